// round 1
// baseline (speedup 1.0000x reference)
#include <cuda_runtime.h>

// ---------------------------------------------------------------------------
// RT1 transformer forward, fp32 baseline.
//   B=32, S=584 (prefix 518 + action 66), D=512, H=8 (dh=64), L=4, FF=2048,
//   V=256, A=66. Output logits (B, A, V) fp32.
// ---------------------------------------------------------------------------

namespace {
constexpr int Bz   = 32;
constexpr int KK   = 32;     // lang tokens
constexpr int VIS  = 486;    // vision tokens
constexpr int SS   = 584;    // total sequence
constexpr int DD   = 512;
constexpr int HH   = 8;
constexpr int DHH  = 64;
constexpr int LL   = 4;
constexpr int VV   = 256;
constexpr int AA   = 66;
constexpr int PP   = 518;    // prefix length
constexpr int FF   = 2048;
constexpr int NTOK = Bz * SS;    // 18688
constexpr int NACT = Bz * AA;    // 2112
constexpr float ATT_SCALE = 0.125f;   // 1/sqrt(64)
constexpr float NEGBIG    = -1e9f;
}

// Scratch (static device allocations; no cudaMalloc allowed)
__device__ float g_x  [NTOK * DD];               //  38 MB activations
__device__ float g_qkv[NTOK * 3 * DD];           // 115 MB qkv
__device__ float g_o  [NTOK * DD];               //  38 MB attn out / ffn2 out
__device__ float g_h  [NTOK * FF];               // 153 MB ffn hidden / oproj out
__device__ float g_scores[(size_t)Bz * HH * SS * SS];  // 349 MB attention scores
__device__ float g_xa [NACT * DD];               //   4 MB gathered action rows

// ---------------------------------------------------------------------------
// Embedding / concat: x[b, s, :] from lang | vision | action_embed[idx]
// ---------------------------------------------------------------------------
__global__ __launch_bounds__(128) void embed_kernel(
    const float* __restrict__ lang, const float* __restrict__ vis,
    const int* __restrict__ aidx, const float* __restrict__ aemb)
{
    int n = blockIdx.x;           // token index
    int b = n / SS, s = n % SS;
    const float* src;
    if (s < KK) {
        src = lang + ((size_t)b * KK + s) * DD;
    } else if (s < PP) {
        src = vis + ((size_t)b * VIS + (s - KK)) * DD;
    } else {
        int tok = aidx[b * AA + (s - PP)];
        src = aemb + (size_t)tok * DD;
    }
    const float4* s4 = (const float4*)src;
    float4* d4 = (float4*)(g_x + (size_t)n * DD);
    d4[threadIdx.x] = s4[threadIdx.x];            // 128 thr * 4 = 512
}

// ---------------------------------------------------------------------------
// Gather action-position rows of x into a packed (NACT, D) matrix for the head
// ---------------------------------------------------------------------------
__global__ __launch_bounds__(128) void gather_act_kernel()
{
    int n = blockIdx.x;           // 0..NACT-1
    int b = n / AA, a = n % AA;
    const float4* src = (const float4*)(g_x + ((size_t)(b * SS + PP + a)) * DD);
    float4* dst = (float4*)(g_xa + (size_t)n * DD);
    dst[threadIdx.x] = src[threadIdx.x];
}

// ---------------------------------------------------------------------------
// SGEMM: C[M,N] = A[M,K] @ W[N,K]^T + bias[N]  (optionally ReLU)
// 128x128 tile, BK=8, 256 threads, 8x8 per thread, double-buffered smem.
// Requires K % 8 == 0, N % 4 == 0; M guarded.
// ---------------------------------------------------------------------------
template<bool RELU>
__global__ __launch_bounds__(256) void sgemm_nt(
    const float* __restrict__ A, const float* __restrict__ W,
    const float* __restrict__ bias, float* __restrict__ C,
    int M, int N, int K)
{
    constexpr int BM = 128, BN = 128, BK = 8;
    __shared__ float As[2][BK][BM + 4];
    __shared__ float Bs[2][BK][BN + 4];

    const int tid  = threadIdx.x;
    const int bm   = blockIdx.x * BM;
    const int bn   = blockIdx.y * BN;
    const int lrow = tid >> 1;            // 0..127
    const int lcol = (tid & 1) << 2;      // 0 or 4
    const int tr   = (tid >> 4) << 3;     // row of 8x8 sub-tile
    const int tc   = (tid & 15) << 3;     // col of 8x8 sub-tile

    const bool aok = (bm + lrow) < M;
    const bool wok = (bn + lrow) < N;
    const float* Aptr = A + (size_t)(bm + lrow) * K + lcol;
    const float* Wptr = W + (size_t)(bn + lrow) * K + lcol;

    float acc[8][8];
    #pragma unroll
    for (int i = 0; i < 8; ++i)
        #pragma unroll
        for (int j = 0; j < 8; ++j) acc[i][j] = 0.f;

    float4 pa = aok ? *(const float4*)Aptr : make_float4(0, 0, 0, 0);
    float4 pw = wok ? *(const float4*)Wptr : make_float4(0, 0, 0, 0);
    As[0][lcol + 0][lrow] = pa.x; As[0][lcol + 1][lrow] = pa.y;
    As[0][lcol + 2][lrow] = pa.z; As[0][lcol + 3][lrow] = pa.w;
    Bs[0][lcol + 0][lrow] = pw.x; Bs[0][lcol + 1][lrow] = pw.y;
    Bs[0][lcol + 2][lrow] = pw.z; Bs[0][lcol + 3][lrow] = pw.w;
    __syncthreads();

    const int kTiles = K / BK;
    for (int t = 0; t < kTiles; ++t) {
        const int cur = t & 1;
        if (t + 1 < kTiles) {
            const float* ap = Aptr + (size_t)(t + 1) * BK;
            const float* wp = Wptr + (size_t)(t + 1) * BK;
            pa = aok ? *(const float4*)ap : make_float4(0, 0, 0, 0);
            pw = wok ? *(const float4*)wp : make_float4(0, 0, 0, 0);
        }
        #pragma unroll
        for (int k = 0; k < BK; ++k) {
            float af[8], bf[8];
            *(float4*)&af[0] = *(const float4*)&As[cur][k][tr];
            *(float4*)&af[4] = *(const float4*)&As[cur][k][tr + 4];
            *(float4*)&bf[0] = *(const float4*)&Bs[cur][k][tc];
            *(float4*)&bf[4] = *(const float4*)&Bs[cur][k][tc + 4];
            #pragma unroll
            for (int i = 0; i < 8; ++i)
                #pragma unroll
                for (int j = 0; j < 8; ++j)
                    acc[i][j] += af[i] * bf[j];
        }
        if (t + 1 < kTiles) {
            const int nxt = cur ^ 1;
            As[nxt][lcol + 0][lrow] = pa.x; As[nxt][lcol + 1][lrow] = pa.y;
            As[nxt][lcol + 2][lrow] = pa.z; As[nxt][lcol + 3][lrow] = pa.w;
            Bs[nxt][lcol + 0][lrow] = pw.x; Bs[nxt][lcol + 1][lrow] = pw.y;
            Bs[nxt][lcol + 2][lrow] = pw.z; Bs[nxt][lcol + 3][lrow] = pw.w;
        }
        __syncthreads();
    }

    float bv[8];
    #pragma unroll
    for (int j = 0; j < 8; ++j) bv[j] = bias[bn + tc + j];

    #pragma unroll
    for (int i = 0; i < 8; ++i) {
        int gr = bm + tr + i;
        if (gr < M) {
            #pragma unroll
            for (int jj = 0; jj < 8; jj += 4) {
                float4 v;
                v.x = acc[i][jj + 0] + bv[jj + 0];
                v.y = acc[i][jj + 1] + bv[jj + 1];
                v.z = acc[i][jj + 2] + bv[jj + 2];
                v.w = acc[i][jj + 3] + bv[jj + 3];
                if (RELU) {
                    v.x = fmaxf(v.x, 0.f); v.y = fmaxf(v.y, 0.f);
                    v.z = fmaxf(v.z, 0.f); v.w = fmaxf(v.w, 0.f);
                }
                *(float4*)&C[(size_t)gr * N + bn + tc + jj] = v;
            }
        }
    }
}

// ---------------------------------------------------------------------------
// Attention scores: scores[bh, i, j] = (q_i . k_j) * scale + mask(i, j)
// 64x64 tile per block, 4x4 per thread, BK=16 over dh=64.
// ---------------------------------------------------------------------------
__global__ __launch_bounds__(256) void scores_kernel(
    const float* __restrict__ qkv, float* __restrict__ scores)
{
    constexpr int BT = 64, BK = 16;
    __shared__ float Qs[BK][BT + 4];
    __shared__ float Ks[BK][BT + 4];

    const int it = blockIdx.x, jt = blockIdx.y, bh = blockIdx.z;
    const int b = bh >> 3, h = bh & 7;
    const float* qbase = qkv + (size_t)b * SS * (3 * DD) + h * DHH;
    const float* kbase = qbase + DD;

    const int tid = threadIdx.x;
    const int lr = tid >> 2;            // 0..63 (row within tile)
    const int lc = (tid & 3) << 2;      // 0,4,8,12 (k offset)
    const int ty = tid >> 4, tx = tid & 15;

    const int qi = it * BT + lr;
    const int kj = jt * BT + lr;
    float acc[4][4];
    #pragma unroll
    for (int i = 0; i < 4; ++i)
        #pragma unroll
        for (int j = 0; j < 4; ++j) acc[i][j] = 0.f;

    #pragma unroll
    for (int kt = 0; kt < DHH / BK; ++kt) {
        float4 q4 = (qi < SS)
            ? *(const float4*)&qbase[(size_t)qi * (3 * DD) + kt * BK + lc]
            : make_float4(0, 0, 0, 0);
        float4 k4 = (kj < SS)
            ? *(const float4*)&kbase[(size_t)kj * (3 * DD) + kt * BK + lc]
            : make_float4(0, 0, 0, 0);
        Qs[lc + 0][lr] = q4.x; Qs[lc + 1][lr] = q4.y;
        Qs[lc + 2][lr] = q4.z; Qs[lc + 3][lr] = q4.w;
        Ks[lc + 0][lr] = k4.x; Ks[lc + 1][lr] = k4.y;
        Ks[lc + 2][lr] = k4.z; Ks[lc + 3][lr] = k4.w;
        __syncthreads();
        #pragma unroll
        for (int k = 0; k < BK; ++k) {
            float qf[4], kf[4];
            *(float4*)qf = *(const float4*)&Qs[k][ty * 4];
            *(float4*)kf = *(const float4*)&Ks[k][tx * 4];
            #pragma unroll
            for (int i = 0; i < 4; ++i)
                #pragma unroll
                for (int j = 0; j < 4; ++j)
                    acc[i][j] += qf[i] * kf[j];
        }
        __syncthreads();
    }

    #pragma unroll
    for (int i = 0; i < 4; ++i) {
        int gi = it * BT + ty * 4 + i;
        if (gi < SS) {
            #pragma unroll
            for (int j = 0; j < 4; ++j) {
                int gj = jt * BT + tx * 4 + j;
                if (gj < SS) {
                    float m = (gj < PP || gj <= gi) ? 0.f : NEGBIG;
                    scores[((size_t)bh * SS + gi) * SS + gj] =
                        acc[i][j] * ATT_SCALE + m;
                }
            }
        }
    }
}

// ---------------------------------------------------------------------------
// Row softmax over S=584 (one block / row, 128 threads, 5 elems each)
// ---------------------------------------------------------------------------
__global__ __launch_bounds__(128) void softmax_kernel(float* __restrict__ scores)
{
    __shared__ float sm[4];
    const size_t row = blockIdx.x;
    float* p = scores + row * SS;
    const int tid = threadIdx.x;

    float v[5];
    float mx = -3.4e38f;
    #pragma unroll
    for (int i = 0; i < 5; ++i) {
        int c = tid + i * 128;
        v[i] = (c < SS) ? p[c] : -3.4e38f;
        mx = fmaxf(mx, v[i]);
    }
    #pragma unroll
    for (int o = 16; o > 0; o >>= 1) mx = fmaxf(mx, __shfl_xor_sync(0xffffffffu, mx, o));
    if ((tid & 31) == 0) sm[tid >> 5] = mx;
    __syncthreads();
    mx = fmaxf(fmaxf(sm[0], sm[1]), fmaxf(sm[2], sm[3]));
    __syncthreads();

    float s = 0.f;
    #pragma unroll
    for (int i = 0; i < 5; ++i) {
        int c = tid + i * 128;
        v[i] = (c < SS) ? __expf(v[i] - mx) : 0.f;
        s += v[i];
    }
    #pragma unroll
    for (int o = 16; o > 0; o >>= 1) s += __shfl_xor_sync(0xffffffffu, s, o);
    if ((tid & 31) == 0) sm[tid >> 5] = s;
    __syncthreads();
    s = sm[0] + sm[1] + sm[2] + sm[3];
    float inv = 1.f / s;

    #pragma unroll
    for (int i = 0; i < 5; ++i) {
        int c = tid + i * 128;
        if (c < SS) p[c] = v[i] * inv;
    }
}

// ---------------------------------------------------------------------------
// attn @ V: o[b, i, h*64 + c] = sum_j P[bh, i, j] * V[b, j, h*64 + c]
// 64 (rows) x 64 (dh) tile per block, BK=16 over j, 4x4 per thread.
// ---------------------------------------------------------------------------
__global__ __launch_bounds__(256) void av_kernel(
    const float* __restrict__ scores, const float* __restrict__ qkv,
    float* __restrict__ o)
{
    constexpr int BT = 64, BK = 16;
    __shared__ float Ps[BK][BT + 4];
    __shared__ float Vs[BK][BT + 4];

    const int it = blockIdx.x, bh = blockIdx.y;
    const int b = bh >> 3, h = bh & 7;
    const float* vbase = qkv + (size_t)b * SS * (3 * DD) + 2 * DD + h * DHH;
    const float* prow  = scores + (size_t)bh * SS * SS;

    const int tid = threadIdx.x;
    const int lr = tid >> 2;            // P rows (0..63)
    const int lc = (tid & 3) << 2;      // P cols within k-tile
    const int vr = tid >> 4;            // V row within k-tile (0..15)
    const int vc = (tid & 15) << 2;     // V col (0..60)
    const int ty = tid >> 4, tx = tid & 15;

    const int gi = it * BT + lr;
    float acc[4][4];
    #pragma unroll
    for (int i = 0; i < 4; ++i)
        #pragma unroll
        for (int j = 0; j < 4; ++j) acc[i][j] = 0.f;

    for (int kt = 0; kt < (SS + BK - 1) / BK; ++kt) {
        int j0 = kt * BK;
        int jc = j0 + lc;
        float4 p4 = (gi < SS && jc < SS)  // SS % 4 == 0 so float4 never straddles
            ? *(const float4*)&prow[(size_t)gi * SS + jc]
            : make_float4(0, 0, 0, 0);
        int jv = j0 + vr;
        float4 v4 = (jv < SS)
            ? *(const float4*)&vbase[(size_t)jv * (3 * DD) + vc]
            : make_float4(0, 0, 0, 0);
        Ps[lc + 0][lr] = p4.x; Ps[lc + 1][lr] = p4.y;
        Ps[lc + 2][lr] = p4.z; Ps[lc + 3][lr] = p4.w;
        *(float4*)&Vs[vr][vc] = v4;
        __syncthreads();
        #pragma unroll
        for (int k = 0; k < BK; ++k) {
            float pf[4], vf[4];
            *(float4*)pf = *(const float4*)&Ps[k][ty * 4];
            *(float4*)vf = *(const float4*)&Vs[k][tx * 4];
            #pragma unroll
            for (int i = 0; i < 4; ++i)
                #pragma unroll
                for (int j = 0; j < 4; ++j)
                    acc[i][j] += pf[i] * vf[j];
        }
        __syncthreads();
    }

    #pragma unroll
    for (int i = 0; i < 4; ++i) {
        int gr = it * BT + ty * 4 + i;
        if (gr < SS) {
            float4 v;
            v.x = acc[i][0]; v.y = acc[i][1]; v.z = acc[i][2]; v.w = acc[i][3];
            *(float4*)&o[(size_t)(b * SS + gr) * DD + h * DHH + tx * 4] = v;
        }
    }
}

// ---------------------------------------------------------------------------
// x = LayerNorm(x + r) * g + b   (one block per token, 128 threads)
// ---------------------------------------------------------------------------
__global__ __launch_bounds__(128) void add_ln_kernel(
    float* __restrict__ x, const float* __restrict__ r,
    const float* __restrict__ g, const float* __restrict__ bta)
{
    __shared__ float sm[4];
    const size_t n = blockIdx.x;
    const int tid = threadIdx.x;

    float4 v  = *(const float4*)&x[n * DD + tid * 4];
    float4 rv = *(const float4*)&r[n * DD + tid * 4];
    v.x += rv.x; v.y += rv.y; v.z += rv.z; v.w += rv.w;

    float s = v.x + v.y + v.z + v.w;
    #pragma unroll
    for (int o = 16; o > 0; o >>= 1) s += __shfl_xor_sync(0xffffffffu, s, o);
    if ((tid & 31) == 0) sm[tid >> 5] = s;
    __syncthreads();
    float mu = (sm[0] + sm[1] + sm[2] + sm[3]) * (1.f / DD);
    __syncthreads();

    float dx = v.x - mu, dy = v.y - mu, dz = v.z - mu, dw = v.w - mu;
    float sq = dx * dx + dy * dy + dz * dz + dw * dw;
    #pragma unroll
    for (int o = 16; o > 0; o >>= 1) sq += __shfl_xor_sync(0xffffffffu, sq, o);
    if ((tid & 31) == 0) sm[tid >> 5] = sq;
    __syncthreads();
    float var = (sm[0] + sm[1] + sm[2] + sm[3]) * (1.f / DD);
    float rinv = rsqrtf(var + 1e-5f);

    float4 gg = *(const float4*)&g[tid * 4];
    float4 bb = *(const float4*)&bta[tid * 4];
    float4 out;
    out.x = dx * rinv * gg.x + bb.x;
    out.y = dy * rinv * gg.y + bb.y;
    out.z = dz * rinv * gg.z + bb.z;
    out.w = dw * rinv * gg.w + bb.w;
    *(float4*)&x[n * DD + tid * 4] = out;
}

// ---------------------------------------------------------------------------
// Launch
// ---------------------------------------------------------------------------
extern "C" void kernel_launch(void* const* d_in, const int* in_sizes, int n_in,
                              void* d_out, int out_size)
{
    const float* lang = (const float*)d_in[0];
    const float* vis  = (const float*)d_in[1];
    const int*   aidx = (const int*)  d_in[2];
    const float* aemb = (const float*)d_in[3];
    const float* Wqkv = (const float*)d_in[4];
    const float* bqkv = (const float*)d_in[5];
    const float* Wo   = (const float*)d_in[6];
    const float* bo   = (const float*)d_in[7];
    const float* W1   = (const float*)d_in[8];
    const float* b1   = (const float*)d_in[9];
    const float* W2   = (const float*)d_in[10];
    const float* b2   = (const float*)d_in[11];
    const float* ln1g = (const float*)d_in[12];
    const float* ln1b = (const float*)d_in[13];
    const float* ln2g = (const float*)d_in[14];
    const float* ln2b = (const float*)d_in[15];
    const float* hW   = (const float*)d_in[16];
    const float* hb   = (const float*)d_in[17];
    float* out = (float*)d_out;

    float *px, *pqkv, *po, *ph, *psc, *pxa;
    cudaGetSymbolAddress((void**)&px,   g_x);
    cudaGetSymbolAddress((void**)&pqkv, g_qkv);
    cudaGetSymbolAddress((void**)&po,   g_o);
    cudaGetSymbolAddress((void**)&ph,   g_h);
    cudaGetSymbolAddress((void**)&psc,  g_scores);
    cudaGetSymbolAddress((void**)&pxa,  g_xa);

    embed_kernel<<<NTOK, 128>>>(lang, vis, aidx, aemb);

    for (int l = 0; l < LL; ++l) {
        // qkv = x @ Wqkv^T + bqkv          (18688, 1536, 512)
        sgemm_nt<false><<<dim3(NTOK / 128, (3 * DD) / 128), 256>>>(
            px, Wqkv + (size_t)l * 3 * DD * DD, bqkv + l * 3 * DD, pqkv,
            NTOK, 3 * DD, DD);
        // scores + mask
        scores_kernel<<<dim3(10, 10, Bz * HH), 256>>>(pqkv, psc);
        // softmax rows
        softmax_kernel<<<Bz * HH * SS, 128>>>(psc);
        // o = attn @ V
        av_kernel<<<dim3(10, Bz * HH), 256>>>(psc, pqkv, po);
        // o proj -> ph                      (18688, 512, 512)
        sgemm_nt<false><<<dim3(NTOK / 128, DD / 128), 256>>>(
            po, Wo + (size_t)l * DD * DD, bo + l * DD, ph, NTOK, DD, DD);
        // x = LN(x + oproj)
        add_ln_kernel<<<NTOK, 128>>>(px, ph, ln1g + l * DD, ln1b + l * DD);
        // ffn1 (ReLU) -> ph                 (18688, 2048, 512)
        sgemm_nt<true><<<dim3(NTOK / 128, FF / 128), 256>>>(
            px, W1 + (size_t)l * FF * DD, b1 + l * FF, ph, NTOK, FF, DD);
        // ffn2 -> po                        (18688, 512, 2048)
        sgemm_nt<false><<<dim3(NTOK / 128, DD / 128), 256>>>(
            ph, W2 + (size_t)l * DD * FF, b2 + l * DD, po, NTOK, DD, FF);
        // x = LN(x + ffn2)
        add_ln_kernel<<<NTOK, 128>>>(px, po, ln2g + l * DD, ln2b + l * DD);
    }

    // head on the 66 action positions
    gather_act_kernel<<<NACT, 128>>>();
    sgemm_nt<false><<<dim3((NACT + 127) / 128, VV / 128), 256>>>(
        pxa, hW, hb, out, NACT, VV, DD);
}

// round 2
// speedup vs baseline: 2.8065x; 2.8065x over previous
#include <cuda_runtime.h>
#include <cstdint>

// ---------------------------------------------------------------------------
// RT1 transformer forward — tf32 tensor-core (mma.sync.m16n8k8) version.
//   B=32, S=584 (prefix 518 + action 66), D=512, H=8 (dh=64), L=4, FF=2048,
//   V=256, A=66. Output logits (B, A, V) fp32.
// ---------------------------------------------------------------------------

namespace {
constexpr int Bz   = 32;
constexpr int KK   = 32;     // lang tokens
constexpr int VIS  = 486;    // vision tokens
constexpr int SS   = 584;    // total sequence
constexpr int DD   = 512;
constexpr int HH   = 8;
constexpr int LL   = 4;
constexpr int VV   = 256;
constexpr int AA   = 66;
constexpr int PP   = 518;    // prefix length
constexpr int FF   = 2048;
constexpr int NTOK = Bz * SS;    // 18688 = 73 * 256
constexpr int NACT = Bz * AA;    // 2112
constexpr float ATT_SCALE = 0.125f;
constexpr float NEGBIG    = -1e9f;
}

// Scratch (static device arrays; cudaMalloc is forbidden)
__device__ float g_x  [NTOK * DD];
__device__ float g_qkv[NTOK * 3 * DD];
__device__ float g_o  [NTOK * DD];
__device__ float g_h  [NTOK * FF];
__device__ float g_scores[(size_t)Bz * HH * SS * SS];
__device__ float g_xa [NACT * DD];

// ---------------------------------------------------------------------------
// PTX helpers
// ---------------------------------------------------------------------------
__device__ __forceinline__ uint32_t f2tf(float x) {
    uint32_t u;
    asm("cvt.rna.tf32.f32 %0, %1;" : "=r"(u) : "f"(x));
    return u;
}

__device__ __forceinline__ void mma_tf32(float* c, const uint32_t* a, const uint32_t* b) {
    asm volatile(
        "mma.sync.aligned.m16n8k8.row.col.f32.tf32.tf32.f32 "
        "{%0,%1,%2,%3}, {%4,%5,%6,%7}, {%8,%9}, {%0,%1,%2,%3};\n"
        : "+f"(c[0]), "+f"(c[1]), "+f"(c[2]), "+f"(c[3])
        : "r"(a[0]), "r"(a[1]), "r"(a[2]), "r"(a[3]), "r"(b[0]), "r"(b[1]));
}

__device__ __forceinline__ void cpa16(uint32_t dst, const void* src) {
    asm volatile("cp.async.cg.shared.global [%0], [%1], 16;" :: "r"(dst), "l"(src));
}
#define CP_COMMIT asm volatile("cp.async.commit_group;\n" ::: "memory")
#define CP_WAIT0  asm volatile("cp.async.wait_group 0;\n" ::: "memory")
#define CP_WAIT1  asm volatile("cp.async.wait_group 1;\n" ::: "memory")

// ---------------------------------------------------------------------------
// Embedding / concat
// ---------------------------------------------------------------------------
__global__ __launch_bounds__(128) void embed_kernel(
    const float* __restrict__ lang, const float* __restrict__ vis,
    const int* __restrict__ aidx, const float* __restrict__ aemb)
{
    int n = blockIdx.x;
    int b = n / SS, s = n % SS;
    const float* src;
    if (s < KK)       src = lang + ((size_t)b * KK + s) * DD;
    else if (s < PP)  src = vis + ((size_t)b * VIS + (s - KK)) * DD;
    else {
        int tok = aidx[b * AA + (s - PP)];
        src = aemb + (size_t)tok * DD;
    }
    ((float4*)(g_x + (size_t)n * DD))[threadIdx.x] = ((const float4*)src)[threadIdx.x];
}

__global__ __launch_bounds__(128) void gather_act_kernel()
{
    int n = blockIdx.x;
    int b = n / AA, a = n % AA;
    ((float4*)(g_xa + (size_t)n * DD))[threadIdx.x] =
        ((const float4*)(g_x + ((size_t)(b * SS + PP + a)) * DD))[threadIdx.x];
}

// ---------------------------------------------------------------------------
// Dense tf32 GEMM: C[M,N] = A[M,K] @ W[N,K]^T + bias[N]  (optional ReLU)
// BM=256, BN=128, BK=32, 256 threads, 8 warps each 64x64.
// Requires M % 256 == 0, N % 128 == 0, K % 32 == 0 (true for all uses).
// Dynamic smem = (2*256*36 + 2*128*36)*4 = 110592 bytes, double-buffered.
// ---------------------------------------------------------------------------
namespace dg {
constexpr int BM = 256, BN = 128, BK = 32;
constexpr int LDA = 36, LDB = 36;           // stride ≡ 4 (mod 32): conflict-free frags
constexpr int A_BUF = BM * LDA;             // 9216 floats
constexpr int B_BUF = BN * LDB;             // 4608 floats
constexpr int SMEM_BYTES = (2 * A_BUF + 2 * B_BUF) * 4;   // 110592
}

template<bool RELU>
__global__ __launch_bounds__(256) void gemm_tf32(
    const float* __restrict__ A, const float* __restrict__ W,
    const float* __restrict__ bias, float* __restrict__ C,
    int N, int K)
{
    using namespace dg;
    extern __shared__ float smem[];
    float* As = smem;                 // [2][BM][LDA]
    float* Bs = smem + 2 * A_BUF;     // [2][BN][LDB]

    const int tid  = threadIdx.x;
    const int bm   = blockIdx.x * BM;
    const int bn   = blockIdx.y * BN;
    const int w    = tid >> 5, lane = tid & 31;
    const int gid  = lane >> 2, t4 = lane & 3;
    const int wm   = (w >> 1) * 64;
    const int wn   = (w & 1) * 64;

    const uint32_t sA = (uint32_t)__cvta_generic_to_shared(As);
    const uint32_t sB = (uint32_t)__cvta_generic_to_shared(Bs);

    float acc[4][8][4];
    #pragma unroll
    for (int i = 0; i < 4; ++i)
        #pragma unroll
        for (int j = 0; j < 8; ++j)
            #pragma unroll
            for (int v = 0; v < 4; ++v) acc[i][j][v] = 0.f;

    const float* Abase = A + (size_t)bm * K;
    const float* Wbase = W + (size_t)bn * K;

    // ---- tile loader (cp.async) ----
    auto load_tile = [&](int t, int buf) {
        const float* Ab = Abase + t * BK;
        const float* Wb = Wbase + t * BK;
        #pragma unroll
        for (int i = 0; i < 8; ++i) {
            int c = tid + i * 256;
            int m = c >> 3, kc = (c & 7) * 4;
            cpa16(sA + (uint32_t)(buf * A_BUF + m * LDA + kc) * 4,
                  Ab + (size_t)m * K + kc);
        }
        #pragma unroll
        for (int i = 0; i < 4; ++i) {
            int c = tid + i * 256;
            int n = c >> 3, kc = (c & 7) * 4;
            cpa16(sB + (uint32_t)(buf * B_BUF + n * LDB + kc) * 4,
                  Wb + (size_t)n * K + kc);
        }
    };

    load_tile(0, 0);
    CP_COMMIT;

    const int T = K / BK;
    for (int t = 0; t < T; ++t) {
        const int cur = t & 1;
        if (t + 1 < T) { load_tile(t + 1, cur ^ 1); CP_COMMIT; CP_WAIT1; }
        else           { CP_WAIT0; }
        __syncthreads();

        const float* Ab = As + cur * A_BUF;
        const float* Bb = Bs + cur * B_BUF;
        #pragma unroll
        for (int kk = 0; kk < 4; ++kk) {
            uint32_t af[4][4], bf[8][2];
            #pragma unroll
            for (int mt = 0; mt < 4; ++mt) {
                const float* p = Ab + (wm + mt * 16 + gid) * LDA + kk * 8 + t4;
                af[mt][0] = f2tf(p[0]);
                af[mt][1] = f2tf(p[8 * LDA]);
                af[mt][2] = f2tf(p[4]);
                af[mt][3] = f2tf(p[8 * LDA + 4]);
            }
            #pragma unroll
            for (int nt = 0; nt < 8; ++nt) {
                const float* p = Bb + (wn + nt * 8 + gid) * LDB + kk * 8 + t4;
                bf[nt][0] = f2tf(p[0]);
                bf[nt][1] = f2tf(p[4]);
            }
            #pragma unroll
            for (int mt = 0; mt < 4; ++mt)
                #pragma unroll
                for (int nt = 0; nt < 8; ++nt)
                    mma_tf32(acc[mt][nt], af[mt], bf[nt]);
        }
        __syncthreads();
    }

    // ---- epilogue ----
    #pragma unroll
    for (int mt = 0; mt < 4; ++mt) {
        int r0 = bm + wm + mt * 16 + gid;
        #pragma unroll
        for (int nt = 0; nt < 8; ++nt) {
            int col = bn + wn + nt * 8 + 2 * t4;
            float b0 = bias[col], b1 = bias[col + 1];
            float2 v0, v1;
            v0.x = acc[mt][nt][0] + b0; v0.y = acc[mt][nt][1] + b1;
            v1.x = acc[mt][nt][2] + b0; v1.y = acc[mt][nt][3] + b1;
            if (RELU) {
                v0.x = fmaxf(v0.x, 0.f); v0.y = fmaxf(v0.y, 0.f);
                v1.x = fmaxf(v1.x, 0.f); v1.y = fmaxf(v1.y, 0.f);
            }
            *(float2*)&C[(size_t)r0 * N + col]       = v0;
            *(float2*)&C[(size_t)(r0 + 8) * N + col] = v1;
        }
    }
}

// ---------------------------------------------------------------------------
// Attention scores (tf32 mma): scores[bh,i,j] = (q_i.k_j)*scale + mask
// Block 128x128 tile, 8 warps each 64x32 (2 m-warps x 4 n-warps).
// K = dh = 64, two BK=32 iterations.
// ---------------------------------------------------------------------------
__global__ __launch_bounds__(256) void scores_mma(
    const float* __restrict__ qkv, float* __restrict__ scores)
{
    constexpr int LD = 36;
    __shared__ float Qs[128 * LD];
    __shared__ float Ks[128 * LD];

    const int it = blockIdx.x, jt = blockIdx.y, bh = blockIdx.z;
    const int b = bh >> 3, h = bh & 7;
    const float* qbase = qkv + (size_t)b * SS * (3 * DD) + h * 64;
    const float* kbase = qbase + DD;

    const int tid = threadIdx.x;
    const int w = tid >> 5, lane = tid & 31;
    const int gid = lane >> 2, t4 = lane & 3;
    const int wm = (w >> 2) * 64;     // 2 m-warps
    const int wn = (w & 3) * 32;      // 4 n-warps

    float acc[4][4][4];
    #pragma unroll
    for (int i = 0; i < 4; ++i)
        #pragma unroll
        for (int j = 0; j < 4; ++j)
            #pragma unroll
            for (int v = 0; v < 4; ++v) acc[i][j][v] = 0.f;

    for (int kt = 0; kt < 2; ++kt) {
        // load Q/K tiles (rows guarded, zero fill)
        #pragma unroll
        for (int i = 0; i < 4; ++i) {
            int c = tid + i * 256;
            int r = c >> 3, kc = (c & 7) * 4;
            int qi = it * 128 + r;
            float4 qv = make_float4(0, 0, 0, 0), kv = make_float4(0, 0, 0, 0);
            if (qi < SS) qv = *(const float4*)(qbase + (size_t)qi * (3 * DD) + kt * 32 + kc);
            int kj = jt * 128 + r;
            if (kj < SS) kv = *(const float4*)(kbase + (size_t)kj * (3 * DD) + kt * 32 + kc);
            *(float4*)&Qs[r * LD + kc] = qv;
            *(float4*)&Ks[r * LD + kc] = kv;
        }
        __syncthreads();

        #pragma unroll
        for (int kk = 0; kk < 4; ++kk) {
            uint32_t af[4][4], bf[4][2];
            #pragma unroll
            for (int mt = 0; mt < 4; ++mt) {
                const float* p = Qs + (wm + mt * 16 + gid) * LD + kk * 8 + t4;
                af[mt][0] = f2tf(p[0]);
                af[mt][1] = f2tf(p[8 * LD]);
                af[mt][2] = f2tf(p[4]);
                af[mt][3] = f2tf(p[8 * LD + 4]);
            }
            #pragma unroll
            for (int nt = 0; nt < 4; ++nt) {
                const float* p = Ks + (wn + nt * 8 + gid) * LD + kk * 8 + t4;
                bf[nt][0] = f2tf(p[0]);
                bf[nt][1] = f2tf(p[4]);
            }
            #pragma unroll
            for (int mt = 0; mt < 4; ++mt)
                #pragma unroll
                for (int nt = 0; nt < 4; ++nt)
                    mma_tf32(acc[mt][nt], af[mt], bf[nt]);
        }
        __syncthreads();
    }

    // epilogue: scale + mask, guarded
    #pragma unroll
    for (int mt = 0; mt < 4; ++mt) {
        #pragma unroll
        for (int rr = 0; rr < 2; ++rr) {
            int gi = it * 128 + wm + mt * 16 + gid + rr * 8;
            if (gi >= SS) continue;
            float* orow = scores + ((size_t)bh * SS + gi) * SS;
            #pragma unroll
            for (int nt = 0; nt < 4; ++nt) {
                int gj = jt * 128 + wn + nt * 8 + 2 * t4;
                if (gj < SS) {
                    float m0 = (gj < PP || gj <= gi) ? 0.f : NEGBIG;
                    orow[gj] = acc[mt][nt][rr * 2 + 0] * ATT_SCALE + m0;
                }
                if (gj + 1 < SS) {
                    float m1 = ((gj + 1) < PP || (gj + 1) <= gi) ? 0.f : NEGBIG;
                    orow[gj + 1] = acc[mt][nt][rr * 2 + 1] * ATT_SCALE + m1;
                }
            }
        }
    }
}

// ---------------------------------------------------------------------------
// Row softmax over S=584
// ---------------------------------------------------------------------------
__global__ __launch_bounds__(128) void softmax_kernel(float* __restrict__ scores)
{
    __shared__ float sm[4];
    const size_t row = blockIdx.x;
    float* p = scores + row * SS;
    const int tid = threadIdx.x;

    float v[5];
    float mx = -3.4e38f;
    #pragma unroll
    for (int i = 0; i < 5; ++i) {
        int c = tid + i * 128;
        v[i] = (c < SS) ? p[c] : -3.4e38f;
        mx = fmaxf(mx, v[i]);
    }
    #pragma unroll
    for (int o = 16; o > 0; o >>= 1) mx = fmaxf(mx, __shfl_xor_sync(0xffffffffu, mx, o));
    if ((tid & 31) == 0) sm[tid >> 5] = mx;
    __syncthreads();
    mx = fmaxf(fmaxf(sm[0], sm[1]), fmaxf(sm[2], sm[3]));
    __syncthreads();

    float s = 0.f;
    #pragma unroll
    for (int i = 0; i < 5; ++i) {
        int c = tid + i * 128;
        v[i] = (c < SS) ? __expf(v[i] - mx) : 0.f;
        s += v[i];
    }
    #pragma unroll
    for (int o = 16; o > 0; o >>= 1) s += __shfl_xor_sync(0xffffffffu, s, o);
    if ((tid & 31) == 0) sm[tid >> 5] = s;
    __syncthreads();
    s = sm[0] + sm[1] + sm[2] + sm[3];
    float inv = 1.f / s;

    #pragma unroll
    for (int i = 0; i < 5; ++i) {
        int c = tid + i * 128;
        if (c < SS) p[c] = v[i] * inv;
    }
}

// ---------------------------------------------------------------------------
// attn @ V (tf32 mma): o[b,i,h*64+c] = sum_j P[bh,i,j] * V[b,j,h*64+c]
// Block: 128 rows x 64 cols; 8 warps each 32x32 (4 m-warps x 2 n-warps).
// K loop over j (584) in BK=32 steps (19 iters, last partially guarded).
// ---------------------------------------------------------------------------
__global__ __launch_bounds__(256) void av_mma(
    const float* __restrict__ scores, const float* __restrict__ qkv,
    float* __restrict__ o)
{
    constexpr int LDP = 36;   // P: m-major [128][36], stride ≡ 4 (mod 32)
    constexpr int LDV = 72;   // V: k-major [32][72],  stride ≡ 8 (mod 32)
    __shared__ float Ps[128 * LDP];
    __shared__ float Vs[32 * LDV];

    const int it = blockIdx.x, bh = blockIdx.y;
    const int b = bh >> 3, h = bh & 7;
    const float* prow  = scores + (size_t)bh * SS * SS;
    const float* vbase = qkv + (size_t)b * SS * (3 * DD) + 2 * DD + h * 64;

    const int tid = threadIdx.x;
    const int w = tid >> 5, lane = tid & 31;
    const int gid = lane >> 2, t4 = lane & 3;
    const int wm = (w >> 1) * 32;     // 4 m-warps
    const int wn = (w & 1) * 32;      // 2 n-warps

    float acc[2][4][4];
    #pragma unroll
    for (int i = 0; i < 2; ++i)
        #pragma unroll
        for (int j = 0; j < 4; ++j)
            #pragma unroll
            for (int v = 0; v < 4; ++v) acc[i][j][v] = 0.f;

    const int T = (SS + 31) / 32;     // 19
    for (int t = 0; t < T; ++t) {
        const int j0 = t * 32;
        // P tile: 128 rows x 32 j
        #pragma unroll
        for (int i = 0; i < 4; ++i) {
            int c = tid + i * 256;
            int r = c >> 3, kc = (c & 7) * 4;
            int gi = it * 128 + r;
            int j = j0 + kc;
            float4 pv = make_float4(0, 0, 0, 0);
            if (gi < SS && j < SS)
                pv = *(const float4*)(prow + (size_t)gi * SS + j);
            *(float4*)&Ps[r * LDP + kc] = pv;
        }
        // V tile: 32 j-rows x 64 cols (k-major: natural row layout)
        #pragma unroll
        for (int i = 0; i < 2; ++i) {
            int c = tid + i * 256;
            int jl = c >> 4, cc = (c & 15) * 4;
            int j = j0 + jl;
            float4 vv = make_float4(0, 0, 0, 0);
            if (j < SS)
                vv = *(const float4*)(vbase + (size_t)j * (3 * DD) + cc);
            *(float4*)&Vs[jl * LDV + cc] = vv;
        }
        __syncthreads();

        #pragma unroll
        for (int kk = 0; kk < 4; ++kk) {
            uint32_t af[2][4], bf[4][2];
            #pragma unroll
            for (int mt = 0; mt < 2; ++mt) {
                const float* p = Ps + (wm + mt * 16 + gid) * LDP + kk * 8 + t4;
                af[mt][0] = f2tf(p[0]);
                af[mt][1] = f2tf(p[8 * LDP]);
                af[mt][2] = f2tf(p[4]);
                af[mt][3] = f2tf(p[8 * LDP + 4]);
            }
            #pragma unroll
            for (int nt = 0; nt < 4; ++nt) {
                const float* p = Vs + (kk * 8 + t4) * LDV + wn + nt * 8 + gid;
                bf[nt][0] = f2tf(p[0]);
                bf[nt][1] = f2tf(p[4 * LDV]);
            }
            #pragma unroll
            for (int mt = 0; mt < 2; ++mt)
                #pragma unroll
                for (int nt = 0; nt < 4; ++nt)
                    mma_tf32(acc[mt][nt], af[mt], bf[nt]);
        }
        __syncthreads();
    }

    #pragma unroll
    for (int mt = 0; mt < 2; ++mt) {
        #pragma unroll
        for (int rr = 0; rr < 2; ++rr) {
            int gi = it * 128 + wm + mt * 16 + gid + rr * 8;
            if (gi >= SS) continue;
            float* orow = o + (size_t)(b * SS + gi) * DD + h * 64;
            #pragma unroll
            for (int nt = 0; nt < 4; ++nt) {
                int col = wn + nt * 8 + 2 * t4;
                float2 v;
                v.x = acc[mt][nt][rr * 2 + 0];
                v.y = acc[mt][nt][rr * 2 + 1];
                *(float2*)&orow[col] = v;
            }
        }
    }
}

// ---------------------------------------------------------------------------
// x = LayerNorm(x + r) * g + b
// ---------------------------------------------------------------------------
__global__ __launch_bounds__(128) void add_ln_kernel(
    float* __restrict__ x, const float* __restrict__ r,
    const float* __restrict__ g, const float* __restrict__ bta)
{
    __shared__ float sm[4];
    const size_t n = blockIdx.x;
    const int tid = threadIdx.x;

    float4 v  = *(const float4*)&x[n * DD + tid * 4];
    float4 rv = *(const float4*)&r[n * DD + tid * 4];
    v.x += rv.x; v.y += rv.y; v.z += rv.z; v.w += rv.w;

    float s = v.x + v.y + v.z + v.w;
    #pragma unroll
    for (int o = 16; o > 0; o >>= 1) s += __shfl_xor_sync(0xffffffffu, s, o);
    if ((tid & 31) == 0) sm[tid >> 5] = s;
    __syncthreads();
    float mu = (sm[0] + sm[1] + sm[2] + sm[3]) * (1.f / DD);
    __syncthreads();

    float dx = v.x - mu, dy = v.y - mu, dz = v.z - mu, dw = v.w - mu;
    float sq = dx * dx + dy * dy + dz * dz + dw * dw;
    #pragma unroll
    for (int o = 16; o > 0; o >>= 1) sq += __shfl_xor_sync(0xffffffffu, sq, o);
    if ((tid & 31) == 0) sm[tid >> 5] = sq;
    __syncthreads();
    float var = (sm[0] + sm[1] + sm[2] + sm[3]) * (1.f / DD);
    float rinv = rsqrtf(var + 1e-5f);

    float4 gg = *(const float4*)&g[tid * 4];
    float4 bb = *(const float4*)&bta[tid * 4];
    float4 out;
    out.x = dx * rinv * gg.x + bb.x;
    out.y = dy * rinv * gg.y + bb.y;
    out.z = dz * rinv * gg.z + bb.z;
    out.w = dw * rinv * gg.w + bb.w;
    *(float4*)&x[n * DD + tid * 4] = out;
}

// ---------------------------------------------------------------------------
// fp32 SGEMM (kept for the tiny head GEMM: M=2112, N=256, K=512)
// ---------------------------------------------------------------------------
__global__ __launch_bounds__(256) void sgemm_head(
    const float* __restrict__ A, const float* __restrict__ W,
    const float* __restrict__ bias, float* __restrict__ C,
    int M, int N, int K)
{
    constexpr int BM = 128, BN = 128, BK = 8;
    __shared__ float As[BK][BM + 4];
    __shared__ float Bs[BK][BN + 4];

    const int tid  = threadIdx.x;
    const int bm   = blockIdx.x * BM;
    const int bn   = blockIdx.y * BN;
    const int lrow = tid >> 1;
    const int lcol = (tid & 1) << 2;
    const int tr   = (tid >> 4) << 3;
    const int tc   = (tid & 15) << 3;

    const bool aok = (bm + lrow) < M;
    const bool wok = (bn + lrow) < N;
    const float* Aptr = A + (size_t)(bm + lrow) * K + lcol;
    const float* Wptr = W + (size_t)(bn + lrow) * K + lcol;

    float acc[8][8];
    #pragma unroll
    for (int i = 0; i < 8; ++i)
        #pragma unroll
        for (int j = 0; j < 8; ++j) acc[i][j] = 0.f;

    for (int t = 0; t < K / BK; ++t) {
        float4 pa = aok ? *(const float4*)(Aptr + (size_t)t * BK) : make_float4(0, 0, 0, 0);
        float4 pw = wok ? *(const float4*)(Wptr + (size_t)t * BK) : make_float4(0, 0, 0, 0);
        As[lcol + 0][lrow] = pa.x; As[lcol + 1][lrow] = pa.y;
        As[lcol + 2][lrow] = pa.z; As[lcol + 3][lrow] = pa.w;
        Bs[lcol + 0][lrow] = pw.x; Bs[lcol + 1][lrow] = pw.y;
        Bs[lcol + 2][lrow] = pw.z; Bs[lcol + 3][lrow] = pw.w;
        __syncthreads();
        #pragma unroll
        for (int k = 0; k < BK; ++k) {
            float af[8], bf[8];
            *(float4*)&af[0] = *(const float4*)&As[k][tr];
            *(float4*)&af[4] = *(const float4*)&As[k][tr + 4];
            *(float4*)&bf[0] = *(const float4*)&Bs[k][tc];
            *(float4*)&bf[4] = *(const float4*)&Bs[k][tc + 4];
            #pragma unroll
            for (int i = 0; i < 8; ++i)
                #pragma unroll
                for (int j = 0; j < 8; ++j)
                    acc[i][j] += af[i] * bf[j];
        }
        __syncthreads();
    }

    #pragma unroll
    for (int i = 0; i < 8; ++i) {
        int gr = bm + tr + i;
        if (gr < M) {
            #pragma unroll
            for (int jj = 0; jj < 8; jj += 4) {
                float4 v;
                v.x = acc[i][jj + 0] + bias[bn + tc + jj + 0];
                v.y = acc[i][jj + 1] + bias[bn + tc + jj + 1];
                v.z = acc[i][jj + 2] + bias[bn + tc + jj + 2];
                v.w = acc[i][jj + 3] + bias[bn + tc + jj + 3];
                *(float4*)&C[(size_t)gr * N + bn + tc + jj] = v;
            }
        }
    }
}

// ---------------------------------------------------------------------------
// Launch
// ---------------------------------------------------------------------------
extern "C" void kernel_launch(void* const* d_in, const int* in_sizes, int n_in,
                              void* d_out, int out_size)
{
    const float* lang = (const float*)d_in[0];
    const float* vis  = (const float*)d_in[1];
    const int*   aidx = (const int*)  d_in[2];
    const float* aemb = (const float*)d_in[3];
    const float* Wqkv = (const float*)d_in[4];
    const float* bqkv = (const float*)d_in[5];
    const float* Wo   = (const float*)d_in[6];
    const float* bo   = (const float*)d_in[7];
    const float* W1   = (const float*)d_in[8];
    const float* b1   = (const float*)d_in[9];
    const float* W2   = (const float*)d_in[10];
    const float* b2   = (const float*)d_in[11];
    const float* ln1g = (const float*)d_in[12];
    const float* ln1b = (const float*)d_in[13];
    const float* ln2g = (const float*)d_in[14];
    const float* ln2b = (const float*)d_in[15];
    const float* hW   = (const float*)d_in[16];
    const float* hb   = (const float*)d_in[17];
    float* out = (float*)d_out;

    float *px, *pqkv, *po, *ph, *psc, *pxa;
    cudaGetSymbolAddress((void**)&px,   g_x);
    cudaGetSymbolAddress((void**)&pqkv, g_qkv);
    cudaGetSymbolAddress((void**)&po,   g_o);
    cudaGetSymbolAddress((void**)&ph,   g_h);
    cudaGetSymbolAddress((void**)&psc,  g_scores);
    cudaGetSymbolAddress((void**)&pxa,  g_xa);

    cudaFuncSetAttribute(gemm_tf32<false>,
        cudaFuncAttributeMaxDynamicSharedMemorySize, dg::SMEM_BYTES);
    cudaFuncSetAttribute(gemm_tf32<true>,
        cudaFuncAttributeMaxDynamicSharedMemorySize, dg::SMEM_BYTES);

    embed_kernel<<<NTOK, 128>>>(lang, vis, aidx, aemb);

    for (int l = 0; l < LL; ++l) {
        // qkv = x @ Wqkv^T + bqkv          (18688, 1536, 512)
        gemm_tf32<false><<<dim3(NTOK / 256, (3 * DD) / 128), 256, dg::SMEM_BYTES>>>(
            px, Wqkv + (size_t)l * 3 * DD * DD, bqkv + l * 3 * DD, pqkv, 3 * DD, DD);
        // scores + mask
        scores_mma<<<dim3(5, 5, Bz * HH), 256>>>(pqkv, psc);
        // softmax rows
        softmax_kernel<<<Bz * HH * SS, 128>>>(psc);
        // o = attn @ V
        av_mma<<<dim3(5, Bz * HH), 256>>>(psc, pqkv, po);
        // o proj -> ph
        gemm_tf32<false><<<dim3(NTOK / 256, DD / 128), 256, dg::SMEM_BYTES>>>(
            po, Wo + (size_t)l * DD * DD, bo + l * DD, ph, DD, DD);
        // x = LN(x + oproj)
        add_ln_kernel<<<NTOK, 128>>>(px, ph, ln1g + l * DD, ln1b + l * DD);
        // ffn1 (ReLU) -> ph
        gemm_tf32<true><<<dim3(NTOK / 256, FF / 128), 256, dg::SMEM_BYTES>>>(
            px, W1 + (size_t)l * FF * DD, b1 + l * FF, ph, FF, DD);
        // ffn2 -> po
        gemm_tf32<false><<<dim3(NTOK / 256, DD / 128), 256, dg::SMEM_BYTES>>>(
            ph, W2 + (size_t)l * DD * FF, b2 + l * DD, po, DD, FF);
        // x = LN(x + ffn2)
        add_ln_kernel<<<NTOK, 128>>>(px, po, ln2g + l * DD, ln2b + l * DD);
    }

    // head on the 66 action positions
    gather_act_kernel<<<NACT, 128>>>();
    sgemm_head<<<dim3((NACT + 127) / 128, VV / 128), 256>>>(
        pxa, hW, hb, out, NACT, VV, DD);
}

// round 3
// speedup vs baseline: 3.2625x; 1.1625x over previous
#include <cuda_runtime.h>
#include <cstdint>

// ---------------------------------------------------------------------------
// RT1 transformer forward — tf32 mma + fused flash attention.
//   B=32, S=584 (prefix 518 + action 66), D=512, H=8 (dh=64), L=4, FF=2048,
//   V=256, A=66. Output logits (B, A, V) fp32.
// ---------------------------------------------------------------------------

namespace {
constexpr int Bz   = 32;
constexpr int KK   = 32;
constexpr int VIS  = 486;
constexpr int SS   = 584;
constexpr int DD   = 512;
constexpr int HH   = 8;
constexpr int LL   = 4;
constexpr int VV   = 256;
constexpr int AA   = 66;
constexpr int PP   = 518;
constexpr int FF   = 2048;
constexpr int NTOK = Bz * SS;    // 18688 = 73 * 256
constexpr int NACT = Bz * AA;    // 2112
constexpr float ATT_SCALE = 0.125f;
constexpr float NEGBIG    = -1e9f;

// pre-rounded weight scratch offsets (floats)
constexpr size_t W_QKV_OFF = 0;
constexpr size_t W_QKV_N   = (size_t)LL * 3 * DD * DD;   // 3,145,728
constexpr size_t W_O_OFF   = W_QKV_OFF + W_QKV_N;
constexpr size_t W_O_N     = (size_t)LL * DD * DD;       // 1,048,576
constexpr size_t W_1_OFF   = W_O_OFF + W_O_N;
constexpr size_t W_1_N     = (size_t)LL * FF * DD;       // 4,194,304
constexpr size_t W_2_OFF   = W_1_OFF + W_1_N;
constexpr size_t W_2_N     = (size_t)LL * DD * FF;       // 4,194,304
constexpr size_t W_TOTAL   = W_2_OFF + W_2_N;            // 12,582,912
}

// Scratch (static device arrays; cudaMalloc is forbidden)
__device__ float g_x  [NTOK * DD];
__device__ float g_qkv[NTOK * 3 * DD];
__device__ float g_o  [NTOK * DD];
__device__ float g_h  [NTOK * FF];
__device__ float g_xa [NACT * DD];
__device__ float g_wr [W_TOTAL];

// ---------------------------------------------------------------------------
// PTX helpers
// ---------------------------------------------------------------------------
__device__ __forceinline__ uint32_t f2tf(float x) {
    uint32_t u;
    asm("cvt.rna.tf32.f32 %0, %1;" : "=r"(u) : "f"(x));
    return u;
}

__device__ __forceinline__ void mma_tf32(float* c, const uint32_t* a, const uint32_t* b) {
    asm volatile(
        "mma.sync.aligned.m16n8k8.row.col.f32.tf32.tf32.f32 "
        "{%0,%1,%2,%3}, {%4,%5,%6,%7}, {%8,%9}, {%0,%1,%2,%3};\n"
        : "+f"(c[0]), "+f"(c[1]), "+f"(c[2]), "+f"(c[3])
        : "r"(a[0]), "r"(a[1]), "r"(a[2]), "r"(a[3]), "r"(b[0]), "r"(b[1]));
}

__device__ __forceinline__ void cpa16(uint32_t dst, const void* src) {
    asm volatile("cp.async.cg.shared.global [%0], [%1], 16;" :: "r"(dst), "l"(src));
}
#define CP_COMMIT asm volatile("cp.async.commit_group;\n" ::: "memory")
#define CP_WAIT0  asm volatile("cp.async.wait_group 0;\n" ::: "memory")
#define CP_WAIT1  asm volatile("cp.async.wait_group 1;\n" ::: "memory")

// ---------------------------------------------------------------------------
// Weight pre-rounding: dst = tf32_rna(src), float4-vectorized
// ---------------------------------------------------------------------------
__global__ __launch_bounds__(256) void round_w_kernel(
    const float* __restrict__ src, float* __restrict__ dst, int n4)
{
    int i = blockIdx.x * 256 + threadIdx.x;
    if (i < n4) {
        float4 v = ((const float4*)src)[i];
        v.x = __uint_as_float(f2tf(v.x));
        v.y = __uint_as_float(f2tf(v.y));
        v.z = __uint_as_float(f2tf(v.z));
        v.w = __uint_as_float(f2tf(v.w));
        ((float4*)dst)[i] = v;
    }
}

// ---------------------------------------------------------------------------
// Embedding / concat
// ---------------------------------------------------------------------------
__global__ __launch_bounds__(128) void embed_kernel(
    const float* __restrict__ lang, const float* __restrict__ vis,
    const int* __restrict__ aidx, const float* __restrict__ aemb)
{
    int n = blockIdx.x;
    int b = n / SS, s = n % SS;
    const float* src;
    if (s < KK)       src = lang + ((size_t)b * KK + s) * DD;
    else if (s < PP)  src = vis + ((size_t)b * VIS + (s - KK)) * DD;
    else {
        int tok = aidx[b * AA + (s - PP)];
        src = aemb + (size_t)tok * DD;
    }
    ((float4*)(g_x + (size_t)n * DD))[threadIdx.x] = ((const float4*)src)[threadIdx.x];
}

__global__ __launch_bounds__(128) void gather_act_kernel()
{
    int n = blockIdx.x;
    int b = n / AA, a = n % AA;
    ((float4*)(g_xa + (size_t)n * DD))[threadIdx.x] =
        ((const float4*)(g_x + ((size_t)(b * SS + PP + a)) * DD))[threadIdx.x];
}

// ---------------------------------------------------------------------------
// Dense tf32 GEMM: C[M,N] = A[M,K] @ W[N,K]^T + bias[N]  (optional ReLU)
// BM=256, BN=128, BK=32, 256 threads, 8 warps each 64x64.
// W is pre-rounded to tf32 — B fragments skip cvt.
// ---------------------------------------------------------------------------
namespace dg {
constexpr int BM = 256, BN = 128, BK = 32;
constexpr int LDA = 36, LDB = 36;
constexpr int A_BUF = BM * LDA;
constexpr int B_BUF = BN * LDB;
constexpr int SMEM_BYTES = (2 * A_BUF + 2 * B_BUF) * 4;   // 110592
}

template<bool RELU>
__global__ __launch_bounds__(256) void gemm_tf32(
    const float* __restrict__ A, const float* __restrict__ W,
    const float* __restrict__ bias, float* __restrict__ C,
    int N, int K)
{
    using namespace dg;
    extern __shared__ float smem[];
    float* As = smem;
    float* Bs = smem + 2 * A_BUF;

    const int tid  = threadIdx.x;
    const int bm   = blockIdx.x * BM;
    const int bn   = blockIdx.y * BN;
    const int w    = tid >> 5, lane = tid & 31;
    const int gid  = lane >> 2, t4 = lane & 3;
    const int wm   = (w >> 1) * 64;
    const int wn   = (w & 1) * 64;

    const uint32_t sA = (uint32_t)__cvta_generic_to_shared(As);
    const uint32_t sB = (uint32_t)__cvta_generic_to_shared(Bs);

    float acc[4][8][4];
    #pragma unroll
    for (int i = 0; i < 4; ++i)
        #pragma unroll
        for (int j = 0; j < 8; ++j)
            #pragma unroll
            for (int v = 0; v < 4; ++v) acc[i][j][v] = 0.f;

    const float* Abase = A + (size_t)bm * K;
    const float* Wbase = W + (size_t)bn * K;

    auto load_tile = [&](int t, int buf) {
        const float* Ab = Abase + t * BK;
        const float* Wb = Wbase + t * BK;
        #pragma unroll
        for (int i = 0; i < 8; ++i) {
            int c = tid + i * 256;
            int m = c >> 3, kc = (c & 7) * 4;
            cpa16(sA + (uint32_t)(buf * A_BUF + m * LDA + kc) * 4,
                  Ab + (size_t)m * K + kc);
        }
        #pragma unroll
        for (int i = 0; i < 4; ++i) {
            int c = tid + i * 256;
            int n = c >> 3, kc = (c & 7) * 4;
            cpa16(sB + (uint32_t)(buf * B_BUF + n * LDB + kc) * 4,
                  Wb + (size_t)n * K + kc);
        }
    };

    load_tile(0, 0);
    CP_COMMIT;

    const int T = K / BK;
    for (int t = 0; t < T; ++t) {
        const int cur = t & 1;
        if (t + 1 < T) { load_tile(t + 1, cur ^ 1); CP_COMMIT; CP_WAIT1; }
        else           { CP_WAIT0; }
        __syncthreads();

        const float* Ab = As + cur * A_BUF;
        const float* Bb = Bs + cur * B_BUF;
        #pragma unroll
        for (int kk = 0; kk < 4; ++kk) {
            uint32_t af[4][4], bf[8][2];
            #pragma unroll
            for (int mt = 0; mt < 4; ++mt) {
                const float* p = Ab + (wm + mt * 16 + gid) * LDA + kk * 8 + t4;
                af[mt][0] = f2tf(p[0]);
                af[mt][1] = f2tf(p[8 * LDA]);
                af[mt][2] = f2tf(p[4]);
                af[mt][3] = f2tf(p[8 * LDA + 4]);
            }
            #pragma unroll
            for (int nt = 0; nt < 8; ++nt) {
                const float* p = Bb + (wn + nt * 8 + gid) * LDB + kk * 8 + t4;
                bf[nt][0] = __float_as_uint(p[0]);     // pre-rounded
                bf[nt][1] = __float_as_uint(p[4]);
            }
            #pragma unroll
            for (int mt = 0; mt < 4; ++mt)
                #pragma unroll
                for (int nt = 0; nt < 8; ++nt)
                    mma_tf32(acc[mt][nt], af[mt], bf[nt]);
        }
        __syncthreads();
    }

    #pragma unroll
    for (int mt = 0; mt < 4; ++mt) {
        int r0 = bm + wm + mt * 16 + gid;
        #pragma unroll
        for (int nt = 0; nt < 8; ++nt) {
            int col = bn + wn + nt * 8 + 2 * t4;
            float b0 = bias[col], b1 = bias[col + 1];
            float2 v0, v1;
            v0.x = acc[mt][nt][0] + b0; v0.y = acc[mt][nt][1] + b1;
            v1.x = acc[mt][nt][2] + b0; v1.y = acc[mt][nt][3] + b1;
            if (RELU) {
                v0.x = fmaxf(v0.x, 0.f); v0.y = fmaxf(v0.y, 0.f);
                v1.x = fmaxf(v1.x, 0.f); v1.y = fmaxf(v1.y, 0.f);
            }
            *(float2*)&C[(size_t)r0 * N + col]       = v0;
            *(float2*)&C[(size_t)(r0 + 8) * N + col] = v1;
        }
    }
}

// ---------------------------------------------------------------------------
// Fused flash attention: per (q-tile of 128, b*h) CTA, 256 threads, 8 warps.
// Each warp owns 16 q-rows. KV tiles of 64. Online softmax in registers.
//   o[b,i,h*64+c] = softmax_j((q_i.k_j)*scale + mask) @ V
// smem: Qs[128x68] (reused as Ps), Ks[64x68], Vs[64x72]  = 70656 bytes.
// ---------------------------------------------------------------------------
namespace fa {
constexpr int BQ = 128, BJ = 64;
constexpr int LDQ = 68, LDK = 68, LDV = 72;
constexpr int KS_OFF = BQ * LDQ;             // 8704
constexpr int VS_OFF = KS_OFF + BJ * LDK;    // 13056
constexpr int SMEM_BYTES = (VS_OFF + BJ * LDV) * 4;   // 70656
}

__global__ __launch_bounds__(256) void flash_kernel(
    const float* __restrict__ qkv, float* __restrict__ o)
{
    using namespace fa;
    extern __shared__ float sm[];
    float* Qs = sm;              // later reused as P (per-warp private rows)
    float* Ks = sm + KS_OFF;
    float* Vs = sm + VS_OFF;

    const int it = blockIdx.x, bh = blockIdx.y;
    const int b = bh >> 3, h = bh & 7;
    const float* qbase = qkv + (size_t)b * SS * (3 * DD) + h * 64;
    const float* kbase = qbase + DD;
    const float* vbase = qbase + 2 * DD;

    const int tid = threadIdx.x;
    const int w = tid >> 5, lane = tid & 31;
    const int gid = lane >> 2, t4 = lane & 3;
    const int wm = w * 16;

    // ---- load Q tile into smem ----
    #pragma unroll
    for (int i = 0; i < 8; ++i) {
        int c = tid + i * 256;
        int r = c >> 4, cc = (c & 15) * 4;
        int qi = it * BQ + r;
        float4 v = make_float4(0, 0, 0, 0);
        if (qi < SS) v = *(const float4*)(qbase + (size_t)qi * (3 * DD) + cc);
        *(float4*)&Qs[r * LDQ + cc] = v;
    }
    __syncthreads();

    // ---- Q fragments to registers (warp's own 16 rows, K=64 => 8 kk) ----
    uint32_t qf[8][4];
    #pragma unroll
    for (int kk = 0; kk < 8; ++kk) {
        const float* p = Qs + (wm + gid) * LDQ + kk * 8 + t4;
        qf[kk][0] = f2tf(p[0]);
        qf[kk][1] = f2tf(p[8 * LDQ]);
        qf[kk][2] = f2tf(p[4]);
        qf[kk][3] = f2tf(p[8 * LDQ + 4]);
    }

    const int row0 = it * BQ + wm + gid;   // gi for acc vals 0,1
    const int row1 = row0 + 8;             // gi for acc vals 2,3

    float m0 = -3.4e38f, m1 = -3.4e38f, l0 = 0.f, l1 = 0.f;
    float acc_o[8][4];
    #pragma unroll
    for (int j = 0; j < 8; ++j)
        #pragma unroll
        for (int v = 0; v < 4; ++v) acc_o[j][v] = 0.f;

    const int nTiles = (SS + BJ - 1) / BJ;   // 10
    for (int jt = 0; jt < nTiles; ++jt) {
        const int j0 = jt * BJ;
        __syncthreads();   // Ks/Vs (and Ps) free to overwrite

        // ---- load K/V tiles ----
        #pragma unroll
        for (int i = 0; i < 4; ++i) {
            int c = tid + i * 256;
            int jl = c >> 4, cc = (c & 15) * 4;
            int j = j0 + jl;
            float4 kv = make_float4(0, 0, 0, 0), vv = make_float4(0, 0, 0, 0);
            if (j < SS) {
                kv = *(const float4*)(kbase + (size_t)j * (3 * DD) + cc);
                vv = *(const float4*)(vbase + (size_t)j * (3 * DD) + cc);
            }
            *(float4*)&Ks[jl * LDK + cc] = kv;
            *(float4*)&Vs[jl * LDV + cc] = vv;
        }
        __syncthreads();

        // ---- S = Q @ K^T  (warp: 16 x 64) ----
        float s[8][4];
        #pragma unroll
        for (int j = 0; j < 8; ++j)
            #pragma unroll
            for (int v = 0; v < 4; ++v) s[j][v] = 0.f;

        #pragma unroll
        for (int kk = 0; kk < 8; ++kk) {
            uint32_t bf[8][2];
            #pragma unroll
            for (int nt = 0; nt < 8; ++nt) {
                const float* p = Ks + (nt * 8 + gid) * LDK + kk * 8 + t4;
                bf[nt][0] = f2tf(p[0]);
                bf[nt][1] = f2tf(p[4]);
            }
            #pragma unroll
            for (int nt = 0; nt < 8; ++nt)
                mma_tf32(s[nt], qf[kk], bf[nt]);
        }

        // ---- scale + mask, tile row max ----
        float tmx0 = -3.4e38f, tmx1 = -3.4e38f;
        #pragma unroll
        for (int nt = 0; nt < 8; ++nt) {
            #pragma unroll
            for (int e = 0; e < 2; ++e) {
                int gj = j0 + nt * 8 + 2 * t4 + e;
                float v0 = s[nt][e] * ATT_SCALE;
                float v1 = s[nt][2 + e] * ATT_SCALE;
                bool al0 = (gj < PP) | (gj <= row0);
                bool al1 = (gj < PP) | (gj <= row1);
                v0 = al0 ? v0 : NEGBIG;
                v1 = al1 ? v1 : NEGBIG;
                s[nt][e] = v0; s[nt][2 + e] = v1;
                tmx0 = fmaxf(tmx0, v0);
                tmx1 = fmaxf(tmx1, v1);
            }
        }
        tmx0 = fmaxf(tmx0, __shfl_xor_sync(0xffffffffu, tmx0, 1));
        tmx0 = fmaxf(tmx0, __shfl_xor_sync(0xffffffffu, tmx0, 2));
        tmx1 = fmaxf(tmx1, __shfl_xor_sync(0xffffffffu, tmx1, 1));
        tmx1 = fmaxf(tmx1, __shfl_xor_sync(0xffffffffu, tmx1, 2));

        float nm0 = fmaxf(m0, tmx0), nm1 = fmaxf(m1, tmx1);
        float a0 = __expf(m0 - nm0), a1 = __expf(m1 - nm1);
        m0 = nm0; m1 = nm1;

        // ---- exp + row sum ----
        float sum0 = 0.f, sum1 = 0.f;
        #pragma unroll
        for (int nt = 0; nt < 8; ++nt) {
            #pragma unroll
            for (int e = 0; e < 2; ++e) {
                float p0 = __expf(s[nt][e] - nm0);
                float p1 = __expf(s[nt][2 + e] - nm1);
                s[nt][e] = p0; s[nt][2 + e] = p1;
                sum0 += p0; sum1 += p1;
            }
        }
        sum0 += __shfl_xor_sync(0xffffffffu, sum0, 1);
        sum0 += __shfl_xor_sync(0xffffffffu, sum0, 2);
        sum1 += __shfl_xor_sync(0xffffffffu, sum1, 1);
        sum1 += __shfl_xor_sync(0xffffffffu, sum1, 2);
        l0 = l0 * a0 + sum0;
        l1 = l1 * a1 + sum1;

        // ---- rescale O accumulators ----
        #pragma unroll
        for (int nt = 0; nt < 8; ++nt) {
            acc_o[nt][0] *= a0; acc_o[nt][1] *= a0;
            acc_o[nt][2] *= a1; acc_o[nt][3] *= a1;
        }

        // ---- write P (warp-private rows of Qs region) ----
        #pragma unroll
        for (int nt = 0; nt < 8; ++nt) {
            float2 p0; p0.x = s[nt][0]; p0.y = s[nt][1];
            float2 p1; p1.x = s[nt][2]; p1.y = s[nt][3];
            *(float2*)&Qs[(wm + gid) * LDQ + nt * 8 + 2 * t4]     = p0;
            *(float2*)&Qs[(wm + gid + 8) * LDQ + nt * 8 + 2 * t4] = p1;
        }
        __syncwarp();

        // ---- O += P @ V  (K dim = 64 local j, 8 kk steps) ----
        #pragma unroll
        for (int kk = 0; kk < 8; ++kk) {
            uint32_t af[4];
            const float* pa = Qs + (wm + gid) * LDQ + kk * 8 + t4;
            af[0] = f2tf(pa[0]);
            af[1] = f2tf(pa[8 * LDQ]);
            af[2] = f2tf(pa[4]);
            af[3] = f2tf(pa[8 * LDQ + 4]);
            #pragma unroll
            for (int nt = 0; nt < 8; ++nt) {
                const float* pv = Vs + (kk * 8 + t4) * LDV + nt * 8 + gid;
                uint32_t bf[2];
                bf[0] = f2tf(pv[0]);
                bf[1] = f2tf(pv[4 * LDV]);
                mma_tf32(acc_o[nt], af, bf);
            }
        }
    }

    // ---- epilogue: O / l ----
    float inv0 = 1.f / l0, inv1 = 1.f / l1;
    float* ob = o + (size_t)b * SS * DD + h * 64;
    #pragma unroll
    for (int nt = 0; nt < 8; ++nt) {
        int col = nt * 8 + 2 * t4;
        if (row0 < SS) {
            float2 v; v.x = acc_o[nt][0] * inv0; v.y = acc_o[nt][1] * inv0;
            *(float2*)&ob[(size_t)row0 * DD + col] = v;
        }
        if (row1 < SS) {
            float2 v; v.x = acc_o[nt][2] * inv1; v.y = acc_o[nt][3] * inv1;
            *(float2*)&ob[(size_t)row1 * DD + col] = v;
        }
    }
}

// ---------------------------------------------------------------------------
// x = LayerNorm(x + r) * g + b
// ---------------------------------------------------------------------------
__global__ __launch_bounds__(128) void add_ln_kernel(
    float* __restrict__ x, const float* __restrict__ r,
    const float* __restrict__ g, const float* __restrict__ bta)
{
    __shared__ float sm[4];
    const size_t n = blockIdx.x;
    const int tid = threadIdx.x;

    float4 v  = *(const float4*)&x[n * DD + tid * 4];
    float4 rv = *(const float4*)&r[n * DD + tid * 4];
    v.x += rv.x; v.y += rv.y; v.z += rv.z; v.w += rv.w;

    float s = v.x + v.y + v.z + v.w;
    #pragma unroll
    for (int o = 16; o > 0; o >>= 1) s += __shfl_xor_sync(0xffffffffu, s, o);
    if ((tid & 31) == 0) sm[tid >> 5] = s;
    __syncthreads();
    float mu = (sm[0] + sm[1] + sm[2] + sm[3]) * (1.f / DD);
    __syncthreads();

    float dx = v.x - mu, dy = v.y - mu, dz = v.z - mu, dw = v.w - mu;
    float sq = dx * dx + dy * dy + dz * dz + dw * dw;
    #pragma unroll
    for (int o = 16; o > 0; o >>= 1) sq += __shfl_xor_sync(0xffffffffu, sq, o);
    if ((tid & 31) == 0) sm[tid >> 5] = sq;
    __syncthreads();
    float var = (sm[0] + sm[1] + sm[2] + sm[3]) * (1.f / DD);
    float rinv = rsqrtf(var + 1e-5f);

    float4 gg = *(const float4*)&g[tid * 4];
    float4 bb = *(const float4*)&bta[tid * 4];
    float4 out;
    out.x = dx * rinv * gg.x + bb.x;
    out.y = dy * rinv * gg.y + bb.y;
    out.z = dz * rinv * gg.z + bb.z;
    out.w = dw * rinv * gg.w + bb.w;
    *(float4*)&x[n * DD + tid * 4] = out;
}

// ---------------------------------------------------------------------------
// fp32 SGEMM for the head (M=2112, N=256, K=512)
// ---------------------------------------------------------------------------
__global__ __launch_bounds__(256) void sgemm_head(
    const float* __restrict__ A, const float* __restrict__ W,
    const float* __restrict__ bias, float* __restrict__ C,
    int M, int N, int K)
{
    constexpr int BM = 128, BN = 128, BK = 8;
    __shared__ float As[BK][BM + 4];
    __shared__ float Bs[BK][BN + 4];

    const int tid  = threadIdx.x;
    const int bm   = blockIdx.x * BM;
    const int bn   = blockIdx.y * BN;
    const int lrow = tid >> 1;
    const int lcol = (tid & 1) << 2;
    const int tr   = (tid >> 4) << 3;
    const int tc   = (tid & 15) << 3;

    const bool aok = (bm + lrow) < M;
    const bool wok = (bn + lrow) < N;
    const float* Aptr = A + (size_t)(bm + lrow) * K + lcol;
    const float* Wptr = W + (size_t)(bn + lrow) * K + lcol;

    float acc[8][8];
    #pragma unroll
    for (int i = 0; i < 8; ++i)
        #pragma unroll
        for (int j = 0; j < 8; ++j) acc[i][j] = 0.f;

    for (int t = 0; t < K / BK; ++t) {
        float4 pa = aok ? *(const float4*)(Aptr + (size_t)t * BK) : make_float4(0, 0, 0, 0);
        float4 pw = wok ? *(const float4*)(Wptr + (size_t)t * BK) : make_float4(0, 0, 0, 0);
        As[lcol + 0][lrow] = pa.x; As[lcol + 1][lrow] = pa.y;
        As[lcol + 2][lrow] = pa.z; As[lcol + 3][lrow] = pa.w;
        Bs[lcol + 0][lrow] = pw.x; Bs[lcol + 1][lrow] = pw.y;
        Bs[lcol + 2][lrow] = pw.z; Bs[lcol + 3][lrow] = pw.w;
        __syncthreads();
        #pragma unroll
        for (int k = 0; k < BK; ++k) {
            float af[8], bf[8];
            *(float4*)&af[0] = *(const float4*)&As[k][tr];
            *(float4*)&af[4] = *(const float4*)&As[k][tr + 4];
            *(float4*)&bf[0] = *(const float4*)&Bs[k][tc];
            *(float4*)&bf[4] = *(const float4*)&Bs[k][tc + 4];
            #pragma unroll
            for (int i = 0; i < 8; ++i)
                #pragma unroll
                for (int j = 0; j < 8; ++j)
                    acc[i][j] += af[i] * bf[j];
        }
        __syncthreads();
    }

    #pragma unroll
    for (int i = 0; i < 8; ++i) {
        int gr = bm + tr + i;
        if (gr < M) {
            #pragma unroll
            for (int jj = 0; jj < 8; jj += 4) {
                float4 v;
                v.x = acc[i][jj + 0] + bias[bn + tc + jj + 0];
                v.y = acc[i][jj + 1] + bias[bn + tc + jj + 1];
                v.z = acc[i][jj + 2] + bias[bn + tc + jj + 2];
                v.w = acc[i][jj + 3] + bias[bn + tc + jj + 3];
                *(float4*)&C[(size_t)gr * N + bn + tc + jj] = v;
            }
        }
    }
}

// ---------------------------------------------------------------------------
// Launch
// ---------------------------------------------------------------------------
extern "C" void kernel_launch(void* const* d_in, const int* in_sizes, int n_in,
                              void* d_out, int out_size)
{
    const float* lang = (const float*)d_in[0];
    const float* vis  = (const float*)d_in[1];
    const int*   aidx = (const int*)  d_in[2];
    const float* aemb = (const float*)d_in[3];
    const float* Wqkv = (const float*)d_in[4];
    const float* bqkv = (const float*)d_in[5];
    const float* Wo   = (const float*)d_in[6];
    const float* bo   = (const float*)d_in[7];
    const float* W1   = (const float*)d_in[8];
    const float* b1   = (const float*)d_in[9];
    const float* W2   = (const float*)d_in[10];
    const float* b2   = (const float*)d_in[11];
    const float* ln1g = (const float*)d_in[12];
    const float* ln1b = (const float*)d_in[13];
    const float* ln2g = (const float*)d_in[14];
    const float* ln2b = (const float*)d_in[15];
    const float* hW   = (const float*)d_in[16];
    const float* hb   = (const float*)d_in[17];
    float* out = (float*)d_out;

    float *px, *pqkv, *po, *ph, *pxa, *pwr;
    cudaGetSymbolAddress((void**)&px,   g_x);
    cudaGetSymbolAddress((void**)&pqkv, g_qkv);
    cudaGetSymbolAddress((void**)&po,   g_o);
    cudaGetSymbolAddress((void**)&ph,   g_h);
    cudaGetSymbolAddress((void**)&pxa,  g_xa);
    cudaGetSymbolAddress((void**)&pwr,  g_wr);

    cudaFuncSetAttribute(gemm_tf32<false>,
        cudaFuncAttributeMaxDynamicSharedMemorySize, dg::SMEM_BYTES);
    cudaFuncSetAttribute(gemm_tf32<true>,
        cudaFuncAttributeMaxDynamicSharedMemorySize, dg::SMEM_BYTES);
    cudaFuncSetAttribute(flash_kernel,
        cudaFuncAttributeMaxDynamicSharedMemorySize, fa::SMEM_BYTES);

    // pre-round weights to tf32 (bit-exact with in-loop cvt.rna)
    round_w_kernel<<<(int)(W_QKV_N / 4 + 255) / 256, 256>>>(Wqkv, pwr + W_QKV_OFF, (int)(W_QKV_N / 4));
    round_w_kernel<<<(int)(W_O_N   / 4 + 255) / 256, 256>>>(Wo,   pwr + W_O_OFF,   (int)(W_O_N   / 4));
    round_w_kernel<<<(int)(W_1_N   / 4 + 255) / 256, 256>>>(W1,   pwr + W_1_OFF,   (int)(W_1_N   / 4));
    round_w_kernel<<<(int)(W_2_N   / 4 + 255) / 256, 256>>>(W2,   pwr + W_2_OFF,   (int)(W_2_N   / 4));

    embed_kernel<<<NTOK, 128>>>(lang, vis, aidx, aemb);

    for (int l = 0; l < LL; ++l) {
        // qkv = x @ Wqkv^T + bqkv
        gemm_tf32<false><<<dim3(NTOK / 256, (3 * DD) / 128), 256, dg::SMEM_BYTES>>>(
            px, pwr + W_QKV_OFF + (size_t)l * 3 * DD * DD, bqkv + l * 3 * DD,
            pqkv, 3 * DD, DD);
        // fused attention -> po
        flash_kernel<<<dim3((SS + fa::BQ - 1) / fa::BQ, Bz * HH), 256, fa::SMEM_BYTES>>>(
            pqkv, po);
        // o proj -> ph
        gemm_tf32<false><<<dim3(NTOK / 256, DD / 128), 256, dg::SMEM_BYTES>>>(
            po, pwr + W_O_OFF + (size_t)l * DD * DD, bo + l * DD, ph, DD, DD);
        // x = LN(x + oproj)
        add_ln_kernel<<<NTOK, 128>>>(px, ph, ln1g + l * DD, ln1b + l * DD);
        // ffn1 (ReLU) -> ph
        gemm_tf32<true><<<dim3(NTOK / 256, FF / 128), 256, dg::SMEM_BYTES>>>(
            px, pwr + W_1_OFF + (size_t)l * FF * DD, b1 + l * FF, ph, FF, DD);
        // ffn2 -> po
        gemm_tf32<false><<<dim3(NTOK / 256, DD / 128), 256, dg::SMEM_BYTES>>>(
            ph, pwr + W_2_OFF + (size_t)l * DD * FF, b2 + l * DD, po, DD, FF);
        // x = LN(x + ffn2)
        add_ln_kernel<<<NTOK, 128>>>(px, po, ln2g + l * DD, ln2b + l * DD);
    }

    // head on the 66 action positions
    gather_act_kernel<<<NACT, 128>>>();
    sgemm_head<<<dim3((NACT + 127) / 128, VV / 128), 256>>>(
        pxa, hW, hb, out, NACT, VV, DD);
}

// round 4
// speedup vs baseline: 3.5057x; 1.0746x over previous
#include <cuda_runtime.h>
#include <cstdint>

// ---------------------------------------------------------------------------
// RT1 transformer forward — tf32 mma, fused flash attention,
// pre-rounded operands (no cvt in inner loops), 3-stage cp.async GEMM.
// ---------------------------------------------------------------------------

namespace {
constexpr int Bz   = 32;
constexpr int KK   = 32;
constexpr int VIS  = 486;
constexpr int SS   = 584;
constexpr int DD   = 512;
constexpr int HH   = 8;
constexpr int LL   = 4;
constexpr int VV   = 256;
constexpr int AA   = 66;
constexpr int PP   = 518;
constexpr int FF   = 2048;
constexpr int NTOK = Bz * SS;    // 18688 = 73 * 256
constexpr int NACT = Bz * AA;    // 2112
constexpr float ATT_SCALE = 0.125f;
constexpr float NEGBIG    = -1e9f;

constexpr size_t W_QKV_OFF = 0;
constexpr size_t W_QKV_N   = (size_t)LL * 3 * DD * DD;
constexpr size_t W_O_OFF   = W_QKV_OFF + W_QKV_N;
constexpr size_t W_O_N     = (size_t)LL * DD * DD;
constexpr size_t W_1_OFF   = W_O_OFF + W_O_N;
constexpr size_t W_1_N     = (size_t)LL * FF * DD;
constexpr size_t W_2_OFF   = W_1_OFF + W_1_N;
constexpr size_t W_2_N     = (size_t)LL * DD * FF;
constexpr size_t W_TOTAL   = W_2_OFF + W_2_N;
}

// Scratch
__device__ float g_x  [NTOK * DD];     // exact activations (residual path)
__device__ float g_xr [NTOK * DD];     // tf32-rounded copy (GEMM inputs)
__device__ float g_qkv[NTOK * 3 * DD]; // rounded (written by QKV epilogue)
__device__ float g_o  [NTOK * DD];     // rounded (flash epilogue)
__device__ float g_h  [NTOK * FF];     // oproj out (exact) / ffn hidden (rounded)
__device__ float g_xa [NACT * DD];
__device__ float g_wr [W_TOTAL];       // rounded weights

// ---------------------------------------------------------------------------
// PTX helpers
// ---------------------------------------------------------------------------
__device__ __forceinline__ uint32_t f2tf(float x) {
    uint32_t u;
    asm("cvt.rna.tf32.f32 %0, %1;" : "=r"(u) : "f"(x));
    return u;
}
__device__ __forceinline__ float roundtf(float x) { return __uint_as_float(f2tf(x)); }

__device__ __forceinline__ void mma_tf32(float* c, const uint32_t* a, const uint32_t* b) {
    asm volatile(
        "mma.sync.aligned.m16n8k8.row.col.f32.tf32.tf32.f32 "
        "{%0,%1,%2,%3}, {%4,%5,%6,%7}, {%8,%9}, {%0,%1,%2,%3};\n"
        : "+f"(c[0]), "+f"(c[1]), "+f"(c[2]), "+f"(c[3])
        : "r"(a[0]), "r"(a[1]), "r"(a[2]), "r"(a[3]), "r"(b[0]), "r"(b[1]));
}

__device__ __forceinline__ void cpa16(uint32_t dst, const void* src) {
    asm volatile("cp.async.cg.shared.global [%0], [%1], 16;" :: "r"(dst), "l"(src));
}
#define CP_COMMIT asm volatile("cp.async.commit_group;\n" ::: "memory")
#define CP_WAIT0  asm volatile("cp.async.wait_group 0;\n" ::: "memory")
#define CP_WAIT1  asm volatile("cp.async.wait_group 1;\n" ::: "memory")

// ---------------------------------------------------------------------------
// Weight pre-rounding
// ---------------------------------------------------------------------------
__global__ __launch_bounds__(256) void round_w_kernel(
    const float* __restrict__ src, float* __restrict__ dst, int n4)
{
    int i = blockIdx.x * 256 + threadIdx.x;
    if (i < n4) {
        float4 v = ((const float4*)src)[i];
        v.x = roundtf(v.x); v.y = roundtf(v.y);
        v.z = roundtf(v.z); v.w = roundtf(v.w);
        ((float4*)dst)[i] = v;
    }
}

// ---------------------------------------------------------------------------
// Embedding / concat: writes exact x AND rounded xr
// ---------------------------------------------------------------------------
__global__ __launch_bounds__(128) void embed_kernel(
    const float* __restrict__ lang, const float* __restrict__ vis,
    const int* __restrict__ aidx, const float* __restrict__ aemb)
{
    int n = blockIdx.x;
    int b = n / SS, s = n % SS;
    const float* src;
    if (s < KK)       src = lang + ((size_t)b * KK + s) * DD;
    else if (s < PP)  src = vis + ((size_t)b * VIS + (s - KK)) * DD;
    else {
        int tok = aidx[b * AA + (s - PP)];
        src = aemb + (size_t)tok * DD;
    }
    float4 v = ((const float4*)src)[threadIdx.x];
    ((float4*)(g_x + (size_t)n * DD))[threadIdx.x] = v;
    v.x = roundtf(v.x); v.y = roundtf(v.y); v.z = roundtf(v.z); v.w = roundtf(v.w);
    ((float4*)(g_xr + (size_t)n * DD))[threadIdx.x] = v;
}

__global__ __launch_bounds__(128) void gather_act_kernel()
{
    int n = blockIdx.x;
    int b = n / AA, a = n % AA;
    ((float4*)(g_xa + (size_t)n * DD))[threadIdx.x] =
        ((const float4*)(g_x + ((size_t)(b * SS + PP + a)) * DD))[threadIdx.x];
}

// ---------------------------------------------------------------------------
// Dense tf32 GEMM: C = A @ W^T + bias  (A and W pre-rounded to tf32).
// BM=256, BN=128, BK=32, 256 thr, 8 warps 64x64, 3-stage cp.async pipeline.
// RELU: relu epilogue.  ROUND: round output to tf32 (when C feeds a GEMM).
// ---------------------------------------------------------------------------
namespace dg {
constexpr int BM = 256, BN = 128, BK = 32;
constexpr int LDA = 36, LDB = 36;
constexpr int A_BUF = BM * LDA;     // 9216
constexpr int B_BUF = BN * LDB;     // 4608
constexpr int SMEM_BYTES = 3 * (A_BUF + B_BUF) * 4;   // 165888
}

template<bool RELU, bool ROUND>
__global__ __launch_bounds__(256) void gemm_tf32(
    const float* __restrict__ A, const float* __restrict__ W,
    const float* __restrict__ bias, float* __restrict__ C,
    int N, int K)
{
    using namespace dg;
    extern __shared__ float smem[];
    float* As = smem;                  // 3 buffers
    float* Bs = smem + 3 * A_BUF;

    const int tid  = threadIdx.x;
    const int bm   = blockIdx.x * BM;
    const int bn   = blockIdx.y * BN;
    const int w    = tid >> 5, lane = tid & 31;
    const int gid  = lane >> 2, t4 = lane & 3;
    const int wm   = (w >> 1) * 64;
    const int wn   = (w & 1) * 64;

    const uint32_t sA = (uint32_t)__cvta_generic_to_shared(As);
    const uint32_t sB = (uint32_t)__cvta_generic_to_shared(Bs);

    float acc[4][8][4];
    #pragma unroll
    for (int i = 0; i < 4; ++i)
        #pragma unroll
        for (int j = 0; j < 8; ++j)
            #pragma unroll
            for (int v = 0; v < 4; ++v) acc[i][j][v] = 0.f;

    const float* Abase = A + (size_t)bm * K;
    const float* Wbase = W + (size_t)bn * K;

    auto load_tile = [&](int t, int buf) {
        const float* Ab = Abase + t * BK;
        const float* Wb = Wbase + t * BK;
        #pragma unroll
        for (int i = 0; i < 8; ++i) {
            int c = tid + i * 256;
            int m = c >> 3, kc = (c & 7) * 4;
            cpa16(sA + (uint32_t)(buf * A_BUF + m * LDA + kc) * 4,
                  Ab + (size_t)m * K + kc);
        }
        #pragma unroll
        for (int i = 0; i < 4; ++i) {
            int c = tid + i * 256;
            int n = c >> 3, kc = (c & 7) * 4;
            cpa16(sB + (uint32_t)(buf * B_BUF + n * LDB + kc) * 4,
                  Wb + (size_t)n * K + kc);
        }
    };

    const int T = K / BK;      // 16 or 64
    load_tile(0, 0); CP_COMMIT;
    if (T > 1) { load_tile(1, 1); CP_COMMIT; }

    for (int t = 0; t < T; ++t) {
        if (t + 1 < T) { CP_WAIT1; } else { CP_WAIT0; }
        __syncthreads();
        if (t + 2 < T) { load_tile(t + 2, (t + 2) % 3); CP_COMMIT; }

        const float* Ab = As + (t % 3) * A_BUF;
        const float* Bb = Bs + (t % 3) * B_BUF;
        #pragma unroll
        for (int kk = 0; kk < 4; ++kk) {
            uint32_t af[4][4], bf[8][2];
            #pragma unroll
            for (int mt = 0; mt < 4; ++mt) {
                const float* p = Ab + (wm + mt * 16 + gid) * LDA + kk * 8 + t4;
                af[mt][0] = __float_as_uint(p[0]);
                af[mt][1] = __float_as_uint(p[8 * LDA]);
                af[mt][2] = __float_as_uint(p[4]);
                af[mt][3] = __float_as_uint(p[8 * LDA + 4]);
            }
            #pragma unroll
            for (int nt = 0; nt < 8; ++nt) {
                const float* p = Bb + (wn + nt * 8 + gid) * LDB + kk * 8 + t4;
                bf[nt][0] = __float_as_uint(p[0]);
                bf[nt][1] = __float_as_uint(p[4]);
            }
            #pragma unroll
            for (int mt = 0; mt < 4; ++mt)
                #pragma unroll
                for (int nt = 0; nt < 8; ++nt)
                    mma_tf32(acc[mt][nt], af[mt], bf[nt]);
        }
        __syncthreads();   // protect buffer (t%3) before reuse at t+3... (covered by wait? no — needed)
    }

    #pragma unroll
    for (int mt = 0; mt < 4; ++mt) {
        int r0 = bm + wm + mt * 16 + gid;
        #pragma unroll
        for (int nt = 0; nt < 8; ++nt) {
            int col = bn + wn + nt * 8 + 2 * t4;
            float b0 = bias[col], b1 = bias[col + 1];
            float2 v0, v1;
            v0.x = acc[mt][nt][0] + b0; v0.y = acc[mt][nt][1] + b1;
            v1.x = acc[mt][nt][2] + b0; v1.y = acc[mt][nt][3] + b1;
            if (RELU) {
                v0.x = fmaxf(v0.x, 0.f); v0.y = fmaxf(v0.y, 0.f);
                v1.x = fmaxf(v1.x, 0.f); v1.y = fmaxf(v1.y, 0.f);
            }
            if (ROUND) {
                v0.x = roundtf(v0.x); v0.y = roundtf(v0.y);
                v1.x = roundtf(v1.x); v1.y = roundtf(v1.y);
            }
            *(float2*)&C[(size_t)r0 * N + col]       = v0;
            *(float2*)&C[(size_t)(r0 + 8) * N + col] = v1;
        }
    }
}

// ---------------------------------------------------------------------------
// Fused flash attention (q/k/v pre-rounded tf32). Output rounded.
// ---------------------------------------------------------------------------
namespace fa {
constexpr int BQ = 128, BJ = 64;
constexpr int LDQ = 68, LDK = 68, LDV = 72;
constexpr int KS_OFF = BQ * LDQ;
constexpr int VS_OFF = KS_OFF + BJ * LDK;
constexpr int SMEM_BYTES = (VS_OFF + BJ * LDV) * 4;   // 70656
}

__global__ __launch_bounds__(256) void flash_kernel(
    const float* __restrict__ qkv, float* __restrict__ o)
{
    using namespace fa;
    extern __shared__ float sm[];
    float* Qs = sm;
    float* Ks = sm + KS_OFF;
    float* Vs = sm + VS_OFF;

    const int it = blockIdx.x, bh = blockIdx.y;
    const int b = bh >> 3, h = bh & 7;
    const float* qbase = qkv + (size_t)b * SS * (3 * DD) + h * 64;
    const float* kbase = qbase + DD;
    const float* vbase = qbase + 2 * DD;

    const int tid = threadIdx.x;
    const int w = tid >> 5, lane = tid & 31;
    const int gid = lane >> 2, t4 = lane & 3;
    const int wm = w * 16;

    #pragma unroll
    for (int i = 0; i < 8; ++i) {
        int c = tid + i * 256;
        int r = c >> 4, cc = (c & 15) * 4;
        int qi = it * BQ + r;
        float4 v = make_float4(0, 0, 0, 0);
        if (qi < SS) v = *(const float4*)(qbase + (size_t)qi * (3 * DD) + cc);
        *(float4*)&Qs[r * LDQ + cc] = v;
    }
    __syncthreads();

    uint32_t qf[8][4];
    #pragma unroll
    for (int kk = 0; kk < 8; ++kk) {
        const float* p = Qs + (wm + gid) * LDQ + kk * 8 + t4;
        qf[kk][0] = __float_as_uint(p[0]);
        qf[kk][1] = __float_as_uint(p[8 * LDQ]);
        qf[kk][2] = __float_as_uint(p[4]);
        qf[kk][3] = __float_as_uint(p[8 * LDQ + 4]);
    }

    const int row0 = it * BQ + wm + gid;
    const int row1 = row0 + 8;

    float m0 = -3.4e38f, m1 = -3.4e38f, l0 = 0.f, l1 = 0.f;
    float acc_o[8][4];
    #pragma unroll
    for (int j = 0; j < 8; ++j)
        #pragma unroll
        for (int v = 0; v < 4; ++v) acc_o[j][v] = 0.f;

    const int nTiles = (SS + BJ - 1) / BJ;
    for (int jt = 0; jt < nTiles; ++jt) {
        const int j0 = jt * BJ;
        __syncthreads();

        #pragma unroll
        for (int i = 0; i < 4; ++i) {
            int c = tid + i * 256;
            int jl = c >> 4, cc = (c & 15) * 4;
            int j = j0 + jl;
            float4 kv = make_float4(0, 0, 0, 0), vv = make_float4(0, 0, 0, 0);
            if (j < SS) {
                kv = *(const float4*)(kbase + (size_t)j * (3 * DD) + cc);
                vv = *(const float4*)(vbase + (size_t)j * (3 * DD) + cc);
            }
            *(float4*)&Ks[jl * LDK + cc] = kv;
            *(float4*)&Vs[jl * LDV + cc] = vv;
        }
        __syncthreads();

        float s[8][4];
        #pragma unroll
        for (int j = 0; j < 8; ++j)
            #pragma unroll
            for (int v = 0; v < 4; ++v) s[j][v] = 0.f;

        #pragma unroll
        for (int kk = 0; kk < 8; ++kk) {
            uint32_t bf[8][2];
            #pragma unroll
            for (int nt = 0; nt < 8; ++nt) {
                const float* p = Ks + (nt * 8 + gid) * LDK + kk * 8 + t4;
                bf[nt][0] = __float_as_uint(p[0]);
                bf[nt][1] = __float_as_uint(p[4]);
            }
            #pragma unroll
            for (int nt = 0; nt < 8; ++nt)
                mma_tf32(s[nt], qf[kk], bf[nt]);
        }

        float tmx0 = -3.4e38f, tmx1 = -3.4e38f;
        #pragma unroll
        for (int nt = 0; nt < 8; ++nt) {
            #pragma unroll
            for (int e = 0; e < 2; ++e) {
                int gj = j0 + nt * 8 + 2 * t4 + e;
                float v0 = s[nt][e] * ATT_SCALE;
                float v1 = s[nt][2 + e] * ATT_SCALE;
                bool al0 = (gj < PP) | (gj <= row0);
                bool al1 = (gj < PP) | (gj <= row1);
                v0 = al0 ? v0 : NEGBIG;
                v1 = al1 ? v1 : NEGBIG;
                s[nt][e] = v0; s[nt][2 + e] = v1;
                tmx0 = fmaxf(tmx0, v0);
                tmx1 = fmaxf(tmx1, v1);
            }
        }
        tmx0 = fmaxf(tmx0, __shfl_xor_sync(0xffffffffu, tmx0, 1));
        tmx0 = fmaxf(tmx0, __shfl_xor_sync(0xffffffffu, tmx0, 2));
        tmx1 = fmaxf(tmx1, __shfl_xor_sync(0xffffffffu, tmx1, 1));
        tmx1 = fmaxf(tmx1, __shfl_xor_sync(0xffffffffu, tmx1, 2));

        float nm0 = fmaxf(m0, tmx0), nm1 = fmaxf(m1, tmx1);
        float a0 = __expf(m0 - nm0), a1 = __expf(m1 - nm1);
        m0 = nm0; m1 = nm1;

        float sum0 = 0.f, sum1 = 0.f;
        #pragma unroll
        for (int nt = 0; nt < 8; ++nt) {
            #pragma unroll
            for (int e = 0; e < 2; ++e) {
                float p0 = __expf(s[nt][e] - nm0);
                float p1 = __expf(s[nt][2 + e] - nm1);
                s[nt][e] = p0; s[nt][2 + e] = p1;
                sum0 += p0; sum1 += p1;
            }
        }
        sum0 += __shfl_xor_sync(0xffffffffu, sum0, 1);
        sum0 += __shfl_xor_sync(0xffffffffu, sum0, 2);
        sum1 += __shfl_xor_sync(0xffffffffu, sum1, 1);
        sum1 += __shfl_xor_sync(0xffffffffu, sum1, 2);
        l0 = l0 * a0 + sum0;
        l1 = l1 * a1 + sum1;

        #pragma unroll
        for (int nt = 0; nt < 8; ++nt) {
            acc_o[nt][0] *= a0; acc_o[nt][1] *= a0;
            acc_o[nt][2] *= a1; acc_o[nt][3] *= a1;
        }

        // write rounded P to warp-private rows of Qs region
        #pragma unroll
        for (int nt = 0; nt < 8; ++nt) {
            float2 p0; p0.x = roundtf(s[nt][0]); p0.y = roundtf(s[nt][1]);
            float2 p1; p1.x = roundtf(s[nt][2]); p1.y = roundtf(s[nt][3]);
            *(float2*)&Qs[(wm + gid) * LDQ + nt * 8 + 2 * t4]     = p0;
            *(float2*)&Qs[(wm + gid + 8) * LDQ + nt * 8 + 2 * t4] = p1;
        }
        __syncwarp();

        #pragma unroll
        for (int kk = 0; kk < 8; ++kk) {
            uint32_t af[4];
            const float* pa = Qs + (wm + gid) * LDQ + kk * 8 + t4;
            af[0] = __float_as_uint(pa[0]);
            af[1] = __float_as_uint(pa[8 * LDQ]);
            af[2] = __float_as_uint(pa[4]);
            af[3] = __float_as_uint(pa[8 * LDQ + 4]);
            #pragma unroll
            for (int nt = 0; nt < 8; ++nt) {
                const float* pv = Vs + (kk * 8 + t4) * LDV + nt * 8 + gid;
                uint32_t bf[2];
                bf[0] = __float_as_uint(pv[0]);
                bf[1] = __float_as_uint(pv[4 * LDV]);
                mma_tf32(acc_o[nt], af, bf);
            }
        }
    }

    // epilogue: O / l, rounded (feeds O-proj GEMM only)
    float inv0 = 1.f / l0, inv1 = 1.f / l1;
    float* ob = o + (size_t)b * SS * DD + h * 64;
    #pragma unroll
    for (int nt = 0; nt < 8; ++nt) {
        int col = nt * 8 + 2 * t4;
        if (row0 < SS) {
            float2 v;
            v.x = roundtf(acc_o[nt][0] * inv0);
            v.y = roundtf(acc_o[nt][1] * inv0);
            *(float2*)&ob[(size_t)row0 * DD + col] = v;
        }
        if (row1 < SS) {
            float2 v;
            v.x = roundtf(acc_o[nt][2] * inv1);
            v.y = roundtf(acc_o[nt][3] * inv1);
            *(float2*)&ob[(size_t)row1 * DD + col] = v;
        }
    }
}

// ---------------------------------------------------------------------------
// x = LayerNorm(x + r) * g + b ; writes exact x AND rounded xr
// ---------------------------------------------------------------------------
__global__ __launch_bounds__(128) void add_ln_kernel(
    float* __restrict__ x, float* __restrict__ xr, const float* __restrict__ r,
    const float* __restrict__ g, const float* __restrict__ bta)
{
    __shared__ float sm[4];
    const size_t n = blockIdx.x;
    const int tid = threadIdx.x;

    float4 v  = *(const float4*)&x[n * DD + tid * 4];
    float4 rv = *(const float4*)&r[n * DD + tid * 4];
    v.x += rv.x; v.y += rv.y; v.z += rv.z; v.w += rv.w;

    float s = v.x + v.y + v.z + v.w;
    #pragma unroll
    for (int o = 16; o > 0; o >>= 1) s += __shfl_xor_sync(0xffffffffu, s, o);
    if ((tid & 31) == 0) sm[tid >> 5] = s;
    __syncthreads();
    float mu = (sm[0] + sm[1] + sm[2] + sm[3]) * (1.f / DD);
    __syncthreads();

    float dx = v.x - mu, dy = v.y - mu, dz = v.z - mu, dw = v.w - mu;
    float sq = dx * dx + dy * dy + dz * dz + dw * dw;
    #pragma unroll
    for (int o = 16; o > 0; o >>= 1) sq += __shfl_xor_sync(0xffffffffu, sq, o);
    if ((tid & 31) == 0) sm[tid >> 5] = sq;
    __syncthreads();
    float var = (sm[0] + sm[1] + sm[2] + sm[3]) * (1.f / DD);
    float rinv = rsqrtf(var + 1e-5f);

    float4 gg = *(const float4*)&g[tid * 4];
    float4 bb = *(const float4*)&bta[tid * 4];
    float4 out;
    out.x = dx * rinv * gg.x + bb.x;
    out.y = dy * rinv * gg.y + bb.y;
    out.z = dz * rinv * gg.z + bb.z;
    out.w = dw * rinv * gg.w + bb.w;
    *(float4*)&x[n * DD + tid * 4] = out;
    out.x = roundtf(out.x); out.y = roundtf(out.y);
    out.z = roundtf(out.z); out.w = roundtf(out.w);
    *(float4*)&xr[n * DD + tid * 4] = out;
}

// ---------------------------------------------------------------------------
// fp32 SGEMM for the head (M=2112, N=256, K=512) — exact fp32 path
// ---------------------------------------------------------------------------
__global__ __launch_bounds__(256) void sgemm_head(
    const float* __restrict__ A, const float* __restrict__ W,
    const float* __restrict__ bias, float* __restrict__ C,
    int M, int N, int K)
{
    constexpr int BM = 128, BN = 128, BK = 8;
    __shared__ float As[BK][BM + 4];
    __shared__ float Bs[BK][BN + 4];

    const int tid  = threadIdx.x;
    const int bm   = blockIdx.x * BM;
    const int bn   = blockIdx.y * BN;
    const int lrow = tid >> 1;
    const int lcol = (tid & 1) << 2;
    const int tr   = (tid >> 4) << 3;
    const int tc   = (tid & 15) << 3;

    const bool aok = (bm + lrow) < M;
    const bool wok = (bn + lrow) < N;
    const float* Aptr = A + (size_t)(bm + lrow) * K + lcol;
    const float* Wptr = W + (size_t)(bn + lrow) * K + lcol;

    float acc[8][8];
    #pragma unroll
    for (int i = 0; i < 8; ++i)
        #pragma unroll
        for (int j = 0; j < 8; ++j) acc[i][j] = 0.f;

    for (int t = 0; t < K / BK; ++t) {
        float4 pa = aok ? *(const float4*)(Aptr + (size_t)t * BK) : make_float4(0, 0, 0, 0);
        float4 pw = wok ? *(const float4*)(Wptr + (size_t)t * BK) : make_float4(0, 0, 0, 0);
        As[lcol + 0][lrow] = pa.x; As[lcol + 1][lrow] = pa.y;
        As[lcol + 2][lrow] = pa.z; As[lcol + 3][lrow] = pa.w;
        Bs[lcol + 0][lrow] = pw.x; Bs[lcol + 1][lrow] = pw.y;
        Bs[lcol + 2][lrow] = pw.z; Bs[lcol + 3][lrow] = pw.w;
        __syncthreads();
        #pragma unroll
        for (int k = 0; k < BK; ++k) {
            float af[8], bf[8];
            *(float4*)&af[0] = *(const float4*)&As[k][tr];
            *(float4*)&af[4] = *(const float4*)&As[k][tr + 4];
            *(float4*)&bf[0] = *(const float4*)&Bs[k][tc];
            *(float4*)&bf[4] = *(const float4*)&Bs[k][tc + 4];
            #pragma unroll
            for (int i = 0; i < 8; ++i)
                #pragma unroll
                for (int j = 0; j < 8; ++j)
                    acc[i][j] += af[i] * bf[j];
        }
        __syncthreads();
    }

    #pragma unroll
    for (int i = 0; i < 8; ++i) {
        int gr = bm + tr + i;
        if (gr < M) {
            #pragma unroll
            for (int jj = 0; jj < 8; jj += 4) {
                float4 v;
                v.x = acc[i][jj + 0] + bias[bn + tc + jj + 0];
                v.y = acc[i][jj + 1] + bias[bn + tc + jj + 1];
                v.z = acc[i][jj + 2] + bias[bn + tc + jj + 2];
                v.w = acc[i][jj + 3] + bias[bn + tc + jj + 3];
                *(float4*)&C[(size_t)gr * N + bn + tc + jj] = v;
            }
        }
    }
}

// ---------------------------------------------------------------------------
// Launch
// ---------------------------------------------------------------------------
extern "C" void kernel_launch(void* const* d_in, const int* in_sizes, int n_in,
                              void* d_out, int out_size)
{
    const float* lang = (const float*)d_in[0];
    const float* vis  = (const float*)d_in[1];
    const int*   aidx = (const int*)  d_in[2];
    const float* aemb = (const float*)d_in[3];
    const float* Wqkv = (const float*)d_in[4];
    const float* bqkv = (const float*)d_in[5];
    const float* Wo   = (const float*)d_in[6];
    const float* bo   = (const float*)d_in[7];
    const float* W1   = (const float*)d_in[8];
    const float* b1   = (const float*)d_in[9];
    const float* W2   = (const float*)d_in[10];
    const float* b2   = (const float*)d_in[11];
    const float* ln1g = (const float*)d_in[12];
    const float* ln1b = (const float*)d_in[13];
    const float* ln2g = (const float*)d_in[14];
    const float* ln2b = (const float*)d_in[15];
    const float* hW   = (const float*)d_in[16];
    const float* hb   = (const float*)d_in[17];
    float* out = (float*)d_out;

    float *px, *pxr, *pqkv, *po, *ph, *pxa, *pwr;
    cudaGetSymbolAddress((void**)&px,   g_x);
    cudaGetSymbolAddress((void**)&pxr,  g_xr);
    cudaGetSymbolAddress((void**)&pqkv, g_qkv);
    cudaGetSymbolAddress((void**)&po,   g_o);
    cudaGetSymbolAddress((void**)&ph,   g_h);
    cudaGetSymbolAddress((void**)&pxa,  g_xa);
    cudaGetSymbolAddress((void**)&pwr,  g_wr);

    cudaFuncSetAttribute(gemm_tf32<false, false>,
        cudaFuncAttributeMaxDynamicSharedMemorySize, dg::SMEM_BYTES);
    cudaFuncSetAttribute(gemm_tf32<false, true>,
        cudaFuncAttributeMaxDynamicSharedMemorySize, dg::SMEM_BYTES);
    cudaFuncSetAttribute(gemm_tf32<true, true>,
        cudaFuncAttributeMaxDynamicSharedMemorySize, dg::SMEM_BYTES);
    cudaFuncSetAttribute(flash_kernel,
        cudaFuncAttributeMaxDynamicSharedMemorySize, fa::SMEM_BYTES);

    round_w_kernel<<<(int)(W_QKV_N / 4 + 255) / 256, 256>>>(Wqkv, pwr + W_QKV_OFF, (int)(W_QKV_N / 4));
    round_w_kernel<<<(int)(W_O_N   / 4 + 255) / 256, 256>>>(Wo,   pwr + W_O_OFF,   (int)(W_O_N   / 4));
    round_w_kernel<<<(int)(W_1_N   / 4 + 255) / 256, 256>>>(W1,   pwr + W_1_OFF,   (int)(W_1_N   / 4));
    round_w_kernel<<<(int)(W_2_N   / 4 + 255) / 256, 256>>>(W2,   pwr + W_2_OFF,   (int)(W_2_N   / 4));

    embed_kernel<<<NTOK, 128>>>(lang, vis, aidx, aemb);

    for (int l = 0; l < LL; ++l) {
        // qkv = xr @ Wqkv^T + bqkv   (output rounded — feeds flash)
        gemm_tf32<false, true><<<dim3(NTOK / 256, (3 * DD) / 128), 256, dg::SMEM_BYTES>>>(
            pxr, pwr + W_QKV_OFF + (size_t)l * 3 * DD * DD, bqkv + l * 3 * DD,
            pqkv, 3 * DD, DD);
        // fused attention -> po (rounded)
        flash_kernel<<<dim3((SS + fa::BQ - 1) / fa::BQ, Bz * HH), 256, fa::SMEM_BYTES>>>(
            pqkv, po);
        // o proj -> ph (exact — feeds residual)
        gemm_tf32<false, false><<<dim3(NTOK / 256, DD / 128), 256, dg::SMEM_BYTES>>>(
            po, pwr + W_O_OFF + (size_t)l * DD * DD, bo + l * DD, ph, DD, DD);
        // x = LN(x + oproj); xr = round(x)
        add_ln_kernel<<<NTOK, 128>>>(px, pxr, ph, ln1g + l * DD, ln1b + l * DD);
        // ffn1 (ReLU) -> ph (rounded — feeds ffn2)
        gemm_tf32<true, true><<<dim3(NTOK / 256, FF / 128), 256, dg::SMEM_BYTES>>>(
            pxr, pwr + W_1_OFF + (size_t)l * FF * DD, b1 + l * FF, ph, FF, DD);
        // ffn2 -> po (exact — feeds residual)
        gemm_tf32<false, false><<<dim3(NTOK / 256, DD / 128), 256, dg::SMEM_BYTES>>>(
            ph, pwr + W_2_OFF + (size_t)l * DD * FF, b2 + l * DD, po, DD, FF);
        // x = LN(x + ffn2); xr = round(x)
        add_ln_kernel<<<NTOK, 128>>>(px, pxr, po, ln2g + l * DD, ln2b + l * DD);
    }

    gather_act_kernel<<<NACT, 128>>>();
    sgemm_head<<<dim3((NACT + 127) / 128, VV / 128), 256>>>(
        pxa, hW, hb, out, NACT, VV, DD);
}

// round 6
// speedup vs baseline: 6.1078x; 1.7422x over previous
#include <cuda_runtime.h>
#include <cuda_fp16.h>
#include <cstdint>

// ---------------------------------------------------------------------------
// RT1 transformer forward — fp16 mma.sync(m16n8k16) + ldmatrix everywhere,
// fp32 accumulate, fp32 residual/LN path. (tcgen05 unavailable: harness
// compiles for sm_100, not sm_100a.)
// ---------------------------------------------------------------------------

namespace {
constexpr int Bz   = 32;
constexpr int KK   = 32;
constexpr int VIS  = 486;
constexpr int SS   = 584;
constexpr int DD   = 512;
constexpr int HH   = 8;
constexpr int LL   = 4;
constexpr int VV   = 256;
constexpr int AA   = 66;
constexpr int PP   = 518;
constexpr int FF   = 2048;
constexpr int NTOK = Bz * SS;    // 18688 = 73 * 256
constexpr int NACT = Bz * AA;    // 2112
constexpr float ATT_SCALE = 0.125f;
constexpr float NEGBIG    = -1e9f;

constexpr size_t W_QKV_OFF = 0;
constexpr size_t W_QKV_N   = (size_t)LL * 3 * DD * DD;
constexpr size_t W_O_OFF   = W_QKV_OFF + W_QKV_N;
constexpr size_t W_O_N     = (size_t)LL * DD * DD;
constexpr size_t W_1_OFF   = W_O_OFF + W_O_N;
constexpr size_t W_1_N     = (size_t)LL * FF * DD;
constexpr size_t W_2_OFF   = W_1_OFF + W_1_N;
constexpr size_t W_2_N     = (size_t)LL * DD * FF;
constexpr size_t W_TOTAL   = W_2_OFF + W_2_N;
}

// Scratch (static; cudaMalloc forbidden)
__device__ float  g_x   [NTOK * DD];        // exact activations (residual)
__device__ float  g_r   [NTOK * DD];        // fp32 branch outputs (oproj/ffn2)
__device__ __half g_xh  [NTOK * DD];        // half activations (GEMM A)
__device__ __half g_qkvh[NTOK * 3 * DD];    // half qkv
__device__ __half g_oh  [NTOK * DD];        // half attn out
__device__ __half g_hh  [NTOK * FF];        // half ffn hidden
__device__ float  g_xa  [NACT * DD];
__device__ __half g_wh  [W_TOTAL];          // half weights

// ---------------------------------------------------------------------------
// PTX helpers
// ---------------------------------------------------------------------------
__device__ __forceinline__ void mma_f16(float* c, const uint32_t* a, const uint32_t* b) {
    asm volatile(
        "mma.sync.aligned.m16n8k16.row.col.f32.f16.f16.f32 "
        "{%0,%1,%2,%3}, {%4,%5,%6,%7}, {%8,%9}, {%0,%1,%2,%3};\n"
        : "+f"(c[0]), "+f"(c[1]), "+f"(c[2]), "+f"(c[3])
        : "r"(a[0]), "r"(a[1]), "r"(a[2]), "r"(a[3]), "r"(b[0]), "r"(b[1]));
}

__device__ __forceinline__ void ldsm4(uint32_t* r, uint32_t addr) {
    asm volatile("ldmatrix.sync.aligned.m8n8.x4.shared.b16 {%0,%1,%2,%3}, [%4];"
        : "=r"(r[0]), "=r"(r[1]), "=r"(r[2]), "=r"(r[3]) : "r"(addr));
}

__device__ __forceinline__ void cpa16(uint32_t dst, const void* src) {
    asm volatile("cp.async.cg.shared.global [%0], [%1], 16;" :: "r"(dst), "l"(src));
}
#define CP_COMMIT asm volatile("cp.async.commit_group;\n" ::: "memory")
#define CP_WAIT0  asm volatile("cp.async.wait_group 0;\n" ::: "memory")
#define CP_WAIT1  asm volatile("cp.async.wait_group 1;\n" ::: "memory")

// ---------------------------------------------------------------------------
// Weight conversion fp32 -> fp16
// ---------------------------------------------------------------------------
__global__ __launch_bounds__(256) void round_wh_kernel(
    const float* __restrict__ src, __half* __restrict__ dst, int n4)
{
    int i = blockIdx.x * 256 + threadIdx.x;
    if (i < n4) {
        float4 v = ((const float4*)src)[i];
        ((__half2*)dst)[2 * i + 0] = __floats2half2_rn(v.x, v.y);
        ((__half2*)dst)[2 * i + 1] = __floats2half2_rn(v.z, v.w);
    }
}

// ---------------------------------------------------------------------------
// Embedding / concat: exact x + half xh
// ---------------------------------------------------------------------------
__global__ __launch_bounds__(128) void embed_kernel(
    const float* __restrict__ lang, const float* __restrict__ vis,
    const int* __restrict__ aidx, const float* __restrict__ aemb)
{
    int n = blockIdx.x;
    int b = n / SS, s = n % SS;
    const float* src;
    if (s < KK)       src = lang + ((size_t)b * KK + s) * DD;
    else if (s < PP)  src = vis + ((size_t)b * VIS + (s - KK)) * DD;
    else {
        int tok = aidx[b * AA + (s - PP)];
        src = aemb + (size_t)tok * DD;
    }
    float4 v = ((const float4*)src)[threadIdx.x];
    ((float4*)(g_x + (size_t)n * DD))[threadIdx.x] = v;
    __half2* dh = (__half2*)(g_xh + (size_t)n * DD);
    dh[2 * threadIdx.x + 0] = __floats2half2_rn(v.x, v.y);
    dh[2 * threadIdx.x + 1] = __floats2half2_rn(v.z, v.w);
}

__global__ __launch_bounds__(128) void gather_act_kernel()
{
    int n = blockIdx.x;
    int b = n / AA, a = n % AA;
    ((float4*)(g_xa + (size_t)n * DD))[threadIdx.x] =
        ((const float4*)(g_x + ((size_t)(b * SS + PP + a)) * DD))[threadIdx.x];
}

// ---------------------------------------------------------------------------
// fp16 GEMM: C[M,N] = A[M,K] @ W[N,K]^T + bias[N]   (fp32 accumulate)
// BM=256, BN=128, BK=64, 256 thr, 8 warps 64x64, 3-stage cp.async, ldmatrix.
// Requires M%256==0, N%128==0, K%64==0.
// ---------------------------------------------------------------------------
namespace dg {
constexpr int BM = 256, BN = 128, BK = 64, ST = 3;
constexpr int LDH = 72;                 // halves per row (144 B, 16B-mult, ≡4 words mod 32)
constexpr int A_H = BM * LDH;           // 18432 halves
constexpr int B_H = BN * LDH;           // 9216
constexpr int STAGE_H = A_H + B_H;      // 27648 halves = 55296 B
constexpr int SMEM_BYTES = ST * STAGE_H * 2;   // 165888
}

template<bool RELU, bool HOUT>
__global__ __launch_bounds__(256) void gemm_f16(
    const __half* __restrict__ A, const __half* __restrict__ W,
    const float* __restrict__ bias, void* __restrict__ Cv, int N, int K)
{
    using namespace dg;
    extern __shared__ __half hs[];
    const uint32_t sbase = (uint32_t)__cvta_generic_to_shared(hs);

    const int tid = threadIdx.x, w = tid >> 5, lane = tid & 31;
    const int gid = lane >> 2, t4 = lane & 3;
    const int lrow = lane & 7, lsel = lane >> 3;
    const int bm = blockIdx.x * BM, bn = blockIdx.y * BN;
    const int wm = (w >> 1) * 64, wn = (w & 1) * 64;

    float acc[4][8][4];
    #pragma unroll
    for (int i = 0; i < 4; ++i)
        #pragma unroll
        for (int j = 0; j < 8; ++j)
            #pragma unroll
            for (int v = 0; v < 4; ++v) acc[i][j][v] = 0.f;

    auto load_tile = [&](int t, int s) {
        const __half* Ab = A + (size_t)bm * K + t * BK;
        const __half* Wb = W + (size_t)bn * K + t * BK;
        const uint32_t sa = sbase + (uint32_t)(s * STAGE_H) * 2;
        const uint32_t sb = sa + A_H * 2;
        #pragma unroll
        for (int j = 0; j < 8; ++j) {
            int c = tid + j * 256;
            int r = c >> 3, kc = c & 7;
            cpa16(sa + (uint32_t)(r * LDH + kc * 8) * 2, Ab + (size_t)r * K + kc * 8);
        }
        #pragma unroll
        for (int j = 0; j < 4; ++j) {
            int c = tid + j * 256;
            int r = c >> 3, kc = c & 7;
            cpa16(sb + (uint32_t)(r * LDH + kc * 8) * 2, Wb + (size_t)r * K + kc * 8);
        }
        CP_COMMIT;
    };

    const int T = K / BK;
    load_tile(0, 0);
    load_tile(1, 1);

    for (int t = 0; t < T; ++t) {
        if (t + 1 < T) { CP_WAIT1; } else { CP_WAIT0; }
        __syncthreads();
        if (t + 2 < T) load_tile(t + 2, (t + 2) % ST);

        const uint32_t sa = sbase + (uint32_t)((t % ST) * STAGE_H) * 2;
        const uint32_t sb = sa + A_H * 2;
        #pragma unroll
        for (int kk = 0; kk < 4; ++kk) {
            uint32_t af[4][4], bf[8][2];
            #pragma unroll
            for (int mt = 0; mt < 4; ++mt) {
                uint32_t addr = sa + (uint32_t)(
                    (wm + mt * 16 + (lsel & 1) * 8 + lrow) * LDH
                    + kk * 16 + (lsel >> 1) * 8) * 2;
                ldsm4(af[mt], addr);
            }
            #pragma unroll
            for (int np = 0; np < 4; ++np) {
                uint32_t r4[4];
                uint32_t addr = sb + (uint32_t)(
                    (wn + np * 16 + (lsel >> 1) * 8 + lrow) * LDH
                    + kk * 16 + (lsel & 1) * 8) * 2;
                ldsm4(r4, addr);
                bf[np * 2][0]     = r4[0]; bf[np * 2][1]     = r4[1];
                bf[np * 2 + 1][0] = r4[2]; bf[np * 2 + 1][1] = r4[3];
            }
            #pragma unroll
            for (int mt = 0; mt < 4; ++mt)
                #pragma unroll
                for (int nt = 0; nt < 8; ++nt)
                    mma_f16(acc[mt][nt], af[mt], bf[nt]);
        }
    }

    // epilogue
    #pragma unroll
    for (int mt = 0; mt < 4; ++mt) {
        int r0 = bm + wm + mt * 16 + gid;
        #pragma unroll
        for (int nt = 0; nt < 8; ++nt) {
            int col = bn + wn + nt * 8 + 2 * t4;
            float b0 = bias[col], b1 = bias[col + 1];
            float2 v0, v1;
            v0.x = acc[mt][nt][0] + b0; v0.y = acc[mt][nt][1] + b1;
            v1.x = acc[mt][nt][2] + b0; v1.y = acc[mt][nt][3] + b1;
            if (RELU) {
                v0.x = fmaxf(v0.x, 0.f); v0.y = fmaxf(v0.y, 0.f);
                v1.x = fmaxf(v1.x, 0.f); v1.y = fmaxf(v1.y, 0.f);
            }
            if (HOUT) {
                __half2* C2 = (__half2*)Cv;
                C2[((size_t)r0 * N + col) >> 1]       = __floats2half2_rn(v0.x, v0.y);
                C2[((size_t)(r0 + 8) * N + col) >> 1] = __floats2half2_rn(v1.x, v1.y);
            } else {
                float* C = (float*)Cv;
                *(float2*)&C[(size_t)r0 * N + col]       = v0;
                *(float2*)&C[(size_t)(r0 + 8) * N + col] = v1;
            }
        }
    }
}

// ---------------------------------------------------------------------------
// Fused flash attention, fp16 operands, fp32 softmax/accumulate.
// CTA: 128 q-rows x (b*h); 8 warps x 16 rows. KV tiles of 64.
// ---------------------------------------------------------------------------
namespace fa {
constexpr int BQ = 128, BJ = 64, LDH = 72;
}

__global__ __launch_bounds__(256) void flash_kernel(
    const __half* __restrict__ qkv, __half* __restrict__ o)
{
    using namespace fa;
    __shared__ __half Qs[BQ * LDH];    // reused as P (warp-private rows)
    __shared__ __half Ks[BJ * LDH];    // rows j, cols d
    __shared__ __half Vt[BJ * LDH];    // rows d, cols j (transposed V)

    const int it = blockIdx.x, bh = blockIdx.y;
    const int b = bh >> 3, h = bh & 7;
    const __half* qbase = qkv + (size_t)b * SS * (3 * DD) + h * 64;
    const __half* kbase = qbase + DD;
    const __half* vbase = qbase + 2 * DD;

    const int tid = threadIdx.x;
    const int w = tid >> 5, lane = tid & 31;
    const int gid = lane >> 2, t4 = lane & 3;
    const int lrow = lane & 7, lsel = lane >> 3;
    const int wm = w * 16;

    const uint32_t qs_a = (uint32_t)__cvta_generic_to_shared(Qs);
    const uint32_t ks_a = (uint32_t)__cvta_generic_to_shared(Ks);
    const uint32_t vt_a = (uint32_t)__cvta_generic_to_shared(Vt);

    // ---- load Q tile (128 x 64 halves) ----
    #pragma unroll
    for (int i = 0; i < 4; ++i) {
        int c = tid + i * 256;
        int r = c >> 3, kc = c & 7;
        int qi = it * BQ + r;
        uint4 v = make_uint4(0, 0, 0, 0);
        if (qi < SS) v = *(const uint4*)(qbase + (size_t)qi * (3 * DD) + kc * 8);
        *(uint4*)&Qs[r * LDH + kc * 8] = v;
    }
    __syncthreads();

    // ---- Q fragments to registers (warp rows, dh=64 -> 4 k16 steps) ----
    uint32_t qf[4][4];
    #pragma unroll
    for (int kk = 0; kk < 4; ++kk) {
        uint32_t addr = qs_a + (uint32_t)(
            (wm + (lsel & 1) * 8 + lrow) * LDH + kk * 16 + (lsel >> 1) * 8) * 2;
        ldsm4(qf[kk], addr);
    }

    const int row0 = it * BQ + wm + gid;
    const int row1 = row0 + 8;

    float m0 = -3.4e38f, m1 = -3.4e38f, l0 = 0.f, l1 = 0.f;
    float acc_o[8][4];
    #pragma unroll
    for (int j = 0; j < 8; ++j)
        #pragma unroll
        for (int v = 0; v < 4; ++v) acc_o[j][v] = 0.f;

    const int nTiles = (SS + BJ - 1) / BJ;   // 10
    for (int jt = 0; jt < nTiles; ++jt) {
        const int j0 = jt * BJ;
        __syncthreads();

        // K tile: rows j (64) x 64 d-halves
        #pragma unroll
        for (int i = 0; i < 2; ++i) {
            int c = tid + i * 256;
            int r = c >> 3, kc = c & 7;
            int j = j0 + r;
            uint4 v = make_uint4(0, 0, 0, 0);
            if (j < SS) v = *(const uint4*)(kbase + (size_t)j * (3 * DD) + kc * 8);
            *(uint4*)&Ks[r * LDH + kc * 8] = v;
        }
        // V tile transposed: warp w owns d rows w*8..w*8+7; lane jp = j pair
        {
            int jp = lane;                       // 0..31
            int jA = j0 + 2 * jp, jB = jA + 1;
            uint4 va = make_uint4(0, 0, 0, 0), vb = make_uint4(0, 0, 0, 0);
            if (jA < SS) va = *(const uint4*)(vbase + (size_t)jA * (3 * DD) + w * 8);
            if (jB < SS) vb = *(const uint4*)(vbase + (size_t)jB * (3 * DD) + w * 8);
            const __half* ha = (const __half*)&va;
            const __half* hb = (const __half*)&vb;
            #pragma unroll
            for (int i = 0; i < 8; ++i) {
                *(__half2*)&Vt[(w * 8 + i) * LDH + 2 * jp] =
                    __halves2half2(ha[i], hb[i]);
            }
        }
        __syncthreads();

        // ---- S = Q @ K^T  (warp 16 x 64) ----
        float s[8][4];
        #pragma unroll
        for (int j = 0; j < 8; ++j)
            #pragma unroll
            for (int v = 0; v < 4; ++v) s[j][v] = 0.f;

        #pragma unroll
        for (int kk = 0; kk < 4; ++kk) {
            uint32_t bf[8][2];
            #pragma unroll
            for (int np = 0; np < 4; ++np) {
                uint32_t r4[4];
                uint32_t addr = ks_a + (uint32_t)(
                    (np * 16 + (lsel >> 1) * 8 + lrow) * LDH
                    + kk * 16 + (lsel & 1) * 8) * 2;
                ldsm4(r4, addr);
                bf[np * 2][0]     = r4[0]; bf[np * 2][1]     = r4[1];
                bf[np * 2 + 1][0] = r4[2]; bf[np * 2 + 1][1] = r4[3];
            }
            #pragma unroll
            for (int nt = 0; nt < 8; ++nt)
                mma_f16(s[nt], qf[kk], bf[nt]);
        }

        // ---- scale + mask, tile max ----
        float tmx0 = -3.4e38f, tmx1 = -3.4e38f;
        #pragma unroll
        for (int nt = 0; nt < 8; ++nt) {
            #pragma unroll
            for (int e = 0; e < 2; ++e) {
                int gj = j0 + nt * 8 + 2 * t4 + e;
                float v0 = s[nt][e] * ATT_SCALE;
                float v1 = s[nt][2 + e] * ATT_SCALE;
                bool al0 = (gj < PP) | (gj <= row0);
                bool al1 = (gj < PP) | (gj <= row1);
                v0 = al0 ? v0 : NEGBIG;
                v1 = al1 ? v1 : NEGBIG;
                s[nt][e] = v0; s[nt][2 + e] = v1;
                tmx0 = fmaxf(tmx0, v0);
                tmx1 = fmaxf(tmx1, v1);
            }
        }
        tmx0 = fmaxf(tmx0, __shfl_xor_sync(0xffffffffu, tmx0, 1));
        tmx0 = fmaxf(tmx0, __shfl_xor_sync(0xffffffffu, tmx0, 2));
        tmx1 = fmaxf(tmx1, __shfl_xor_sync(0xffffffffu, tmx1, 1));
        tmx1 = fmaxf(tmx1, __shfl_xor_sync(0xffffffffu, tmx1, 2));

        float nm0 = fmaxf(m0, tmx0), nm1 = fmaxf(m1, tmx1);
        float a0 = __expf(m0 - nm0), a1 = __expf(m1 - nm1);
        m0 = nm0; m1 = nm1;

        float sum0 = 0.f, sum1 = 0.f;
        #pragma unroll
        for (int nt = 0; nt < 8; ++nt) {
            #pragma unroll
            for (int e = 0; e < 2; ++e) {
                float p0 = __expf(s[nt][e] - nm0);
                float p1 = __expf(s[nt][2 + e] - nm1);
                s[nt][e] = p0; s[nt][2 + e] = p1;
                sum0 += p0; sum1 += p1;
            }
        }
        sum0 += __shfl_xor_sync(0xffffffffu, sum0, 1);
        sum0 += __shfl_xor_sync(0xffffffffu, sum0, 2);
        sum1 += __shfl_xor_sync(0xffffffffu, sum1, 1);
        sum1 += __shfl_xor_sync(0xffffffffu, sum1, 2);
        l0 = l0 * a0 + sum0;
        l1 = l1 * a1 + sum1;

        #pragma unroll
        for (int nt = 0; nt < 8; ++nt) {
            acc_o[nt][0] *= a0; acc_o[nt][1] *= a0;
            acc_o[nt][2] *= a1; acc_o[nt][3] *= a1;
        }

        // ---- write half P to warp-private rows of Qs ----
        #pragma unroll
        for (int nt = 0; nt < 8; ++nt) {
            *(__half2*)&Qs[(wm + gid) * LDH + nt * 8 + 2 * t4] =
                __floats2half2_rn(s[nt][0], s[nt][1]);
            *(__half2*)&Qs[(wm + gid + 8) * LDH + nt * 8 + 2 * t4] =
                __floats2half2_rn(s[nt][2], s[nt][3]);
        }
        __syncwarp();

        // ---- O += P @ V  (k = 64 local j, 4 k16 steps) ----
        #pragma unroll
        for (int kk = 0; kk < 4; ++kk) {
            uint32_t af[4];
            uint32_t addr = qs_a + (uint32_t)(
                (wm + (lsel & 1) * 8 + lrow) * LDH + kk * 16 + (lsel >> 1) * 8) * 2;
            ldsm4(af, addr);
            uint32_t bf[8][2];
            #pragma unroll
            for (int np = 0; np < 4; ++np) {
                uint32_t r4[4];
                uint32_t vaddr = vt_a + (uint32_t)(
                    (np * 16 + (lsel >> 1) * 8 + lrow) * LDH
                    + kk * 16 + (lsel & 1) * 8) * 2;
                ldsm4(r4, vaddr);
                bf[np * 2][0]     = r4[0]; bf[np * 2][1]     = r4[1];
                bf[np * 2 + 1][0] = r4[2]; bf[np * 2 + 1][1] = r4[3];
            }
            #pragma unroll
            for (int nt = 0; nt < 8; ++nt)
                mma_f16(acc_o[nt], af, bf[nt]);
        }
    }

    // ---- epilogue: O / l -> half ----
    float inv0 = 1.f / l0, inv1 = 1.f / l1;
    __half* ob = o + (size_t)b * SS * DD + h * 64;
    #pragma unroll
    for (int nt = 0; nt < 8; ++nt) {
        int col = nt * 8 + 2 * t4;
        if (row0 < SS)
            *(__half2*)&ob[(size_t)row0 * DD + col] =
                __floats2half2_rn(acc_o[nt][0] * inv0, acc_o[nt][1] * inv0);
        if (row1 < SS)
            *(__half2*)&ob[(size_t)row1 * DD + col] =
                __floats2half2_rn(acc_o[nt][2] * inv1, acc_o[nt][3] * inv1);
    }
}

// ---------------------------------------------------------------------------
// x = LayerNorm(x + r) * g + b ; writes exact x AND half xh
// ---------------------------------------------------------------------------
__global__ __launch_bounds__(128) void add_ln_kernel(
    float* __restrict__ x, __half* __restrict__ xh, const float* __restrict__ r,
    const float* __restrict__ g, const float* __restrict__ bta)
{
    __shared__ float sm[4];
    const size_t n = blockIdx.x;
    const int tid = threadIdx.x;

    float4 v  = *(const float4*)&x[n * DD + tid * 4];
    float4 rv = *(const float4*)&r[n * DD + tid * 4];
    v.x += rv.x; v.y += rv.y; v.z += rv.z; v.w += rv.w;

    float s = v.x + v.y + v.z + v.w;
    #pragma unroll
    for (int o = 16; o > 0; o >>= 1) s += __shfl_xor_sync(0xffffffffu, s, o);
    if ((tid & 31) == 0) sm[tid >> 5] = s;
    __syncthreads();
    float mu = (sm[0] + sm[1] + sm[2] + sm[3]) * (1.f / DD);
    __syncthreads();

    float dx = v.x - mu, dy = v.y - mu, dz = v.z - mu, dw = v.w - mu;
    float sq = dx * dx + dy * dy + dz * dz + dw * dw;
    #pragma unroll
    for (int o = 16; o > 0; o >>= 1) sq += __shfl_xor_sync(0xffffffffu, sq, o);
    if ((tid & 31) == 0) sm[tid >> 5] = sq;
    __syncthreads();
    float var = (sm[0] + sm[1] + sm[2] + sm[3]) * (1.f / DD);
    float rinv = rsqrtf(var + 1e-5f);

    float4 gg = *(const float4*)&g[tid * 4];
    float4 bb = *(const float4*)&bta[tid * 4];
    float4 out;
    out.x = dx * rinv * gg.x + bb.x;
    out.y = dy * rinv * gg.y + bb.y;
    out.z = dz * rinv * gg.z + bb.z;
    out.w = dw * rinv * gg.w + bb.w;
    *(float4*)&x[n * DD + tid * 4] = out;
    __half2* dh = (__half2*)(xh + n * DD);
    dh[2 * tid + 0] = __floats2half2_rn(out.x, out.y);
    dh[2 * tid + 1] = __floats2half2_rn(out.z, out.w);
}

// ---------------------------------------------------------------------------
// fp32 SGEMM for the head (M=2112, N=256, K=512) — exact
// ---------------------------------------------------------------------------
__global__ __launch_bounds__(256) void sgemm_head(
    const float* __restrict__ A, const float* __restrict__ W,
    const float* __restrict__ bias, float* __restrict__ C,
    int M, int N, int K)
{
    constexpr int BM = 128, BN = 128, BK = 8;
    __shared__ float As[BK][BM + 4];
    __shared__ float Bs[BK][BN + 4];

    const int tid  = threadIdx.x;
    const int bm   = blockIdx.x * BM;
    const int bn   = blockIdx.y * BN;
    const int lrow = tid >> 1;
    const int lcol = (tid & 1) << 2;
    const int tr   = (tid >> 4) << 3;
    const int tc   = (tid & 15) << 3;

    const bool aok = (bm + lrow) < M;
    const bool wok = (bn + lrow) < N;
    const float* Aptr = A + (size_t)(bm + lrow) * K + lcol;
    const float* Wptr = W + (size_t)(bn + lrow) * K + lcol;

    float acc[8][8];
    #pragma unroll
    for (int i = 0; i < 8; ++i)
        #pragma unroll
        for (int j = 0; j < 8; ++j) acc[i][j] = 0.f;

    for (int t = 0; t < K / BK; ++t) {
        float4 pa = aok ? *(const float4*)(Aptr + (size_t)t * BK) : make_float4(0, 0, 0, 0);
        float4 pw = wok ? *(const float4*)(Wptr + (size_t)t * BK) : make_float4(0, 0, 0, 0);
        As[lcol + 0][lrow] = pa.x; As[lcol + 1][lrow] = pa.y;
        As[lcol + 2][lrow] = pa.z; As[lcol + 3][lrow] = pa.w;
        Bs[lcol + 0][lrow] = pw.x; Bs[lcol + 1][lrow] = pw.y;
        Bs[lcol + 2][lrow] = pw.z; Bs[lcol + 3][lrow] = pw.w;
        __syncthreads();
        #pragma unroll
        for (int k = 0; k < BK; ++k) {
            float af[8], bf[8];
            *(float4*)&af[0] = *(const float4*)&As[k][tr];
            *(float4*)&af[4] = *(const float4*)&As[k][tr + 4];
            *(float4*)&bf[0] = *(const float4*)&Bs[k][tc];
            *(float4*)&bf[4] = *(const float4*)&Bs[k][tc + 4];
            #pragma unroll
            for (int i = 0; i < 8; ++i)
                #pragma unroll
                for (int j = 0; j < 8; ++j)
                    acc[i][j] += af[i] * bf[j];
        }
        __syncthreads();
    }

    #pragma unroll
    for (int i = 0; i < 8; ++i) {
        int gr = bm + tr + i;
        if (gr < M) {
            #pragma unroll
            for (int jj = 0; jj < 8; jj += 4) {
                float4 v;
                v.x = acc[i][jj + 0] + bias[bn + tc + jj + 0];
                v.y = acc[i][jj + 1] + bias[bn + tc + jj + 1];
                v.z = acc[i][jj + 2] + bias[bn + tc + jj + 2];
                v.w = acc[i][jj + 3] + bias[bn + tc + jj + 3];
                *(float4*)&C[(size_t)gr * N + bn + tc + jj] = v;
            }
        }
    }
}

// ---------------------------------------------------------------------------
// Launch
// ---------------------------------------------------------------------------
extern "C" void kernel_launch(void* const* d_in, const int* in_sizes, int n_in,
                              void* d_out, int out_size)
{
    const float* lang = (const float*)d_in[0];
    const float* vis  = (const float*)d_in[1];
    const int*   aidx = (const int*)  d_in[2];
    const float* aemb = (const float*)d_in[3];
    const float* Wqkv = (const float*)d_in[4];
    const float* bqkv = (const float*)d_in[5];
    const float* Wo   = (const float*)d_in[6];
    const float* bo   = (const float*)d_in[7];
    const float* W1   = (const float*)d_in[8];
    const float* b1   = (const float*)d_in[9];
    const float* W2   = (const float*)d_in[10];
    const float* b2   = (const float*)d_in[11];
    const float* ln1g = (const float*)d_in[12];
    const float* ln1b = (const float*)d_in[13];
    const float* ln2g = (const float*)d_in[14];
    const float* ln2b = (const float*)d_in[15];
    const float* hW   = (const float*)d_in[16];
    const float* hb   = (const float*)d_in[17];
    float* out = (float*)d_out;

    float *px, *pr, *pxa;
    __half *pxh, *pqkvh, *poh, *phh, *pwh;
    cudaGetSymbolAddress((void**)&px,    g_x);
    cudaGetSymbolAddress((void**)&pr,    g_r);
    cudaGetSymbolAddress((void**)&pxa,   g_xa);
    cudaGetSymbolAddress((void**)&pxh,   g_xh);
    cudaGetSymbolAddress((void**)&pqkvh, g_qkvh);
    cudaGetSymbolAddress((void**)&poh,   g_oh);
    cudaGetSymbolAddress((void**)&phh,   g_hh);
    cudaGetSymbolAddress((void**)&pwh,   g_wh);

    cudaFuncSetAttribute(gemm_f16<false, false>,
        cudaFuncAttributeMaxDynamicSharedMemorySize, dg::SMEM_BYTES);
    cudaFuncSetAttribute(gemm_f16<false, true>,
        cudaFuncAttributeMaxDynamicSharedMemorySize, dg::SMEM_BYTES);
    cudaFuncSetAttribute(gemm_f16<true, true>,
        cudaFuncAttributeMaxDynamicSharedMemorySize, dg::SMEM_BYTES);

    round_wh_kernel<<<(int)(W_QKV_N / 4 + 255) / 256, 256>>>(Wqkv, pwh + W_QKV_OFF, (int)(W_QKV_N / 4));
    round_wh_kernel<<<(int)(W_O_N   / 4 + 255) / 256, 256>>>(Wo,   pwh + W_O_OFF,   (int)(W_O_N   / 4));
    round_wh_kernel<<<(int)(W_1_N   / 4 + 255) / 256, 256>>>(W1,   pwh + W_1_OFF,   (int)(W_1_N   / 4));
    round_wh_kernel<<<(int)(W_2_N   / 4 + 255) / 256, 256>>>(W2,   pwh + W_2_OFF,   (int)(W_2_N   / 4));

    embed_kernel<<<NTOK, 128>>>(lang, vis, aidx, aemb);

    for (int l = 0; l < LL; ++l) {
        // qkv = xh @ Wqkv^T + bqkv  -> half
        gemm_f16<false, true><<<dim3(NTOK / 256, (3 * DD) / 128), 256, dg::SMEM_BYTES>>>(
            pxh, pwh + W_QKV_OFF + (size_t)l * 3 * DD * DD, bqkv + l * 3 * DD,
            pqkvh, 3 * DD, DD);
        // fused attention -> half
        flash_kernel<<<dim3((SS + fa::BQ - 1) / fa::BQ, Bz * HH), 256>>>(pqkvh, poh);
        // o proj -> fp32 residual branch
        gemm_f16<false, false><<<dim3(NTOK / 256, DD / 128), 256, dg::SMEM_BYTES>>>(
            poh, pwh + W_O_OFF + (size_t)l * DD * DD, bo + l * DD, pr, DD, DD);
        // x = LN(x + oproj); xh = half(x)
        add_ln_kernel<<<NTOK, 128>>>(px, pxh, pr, ln1g + l * DD, ln1b + l * DD);
        // ffn1 (ReLU) -> half hidden
        gemm_f16<true, true><<<dim3(NTOK / 256, FF / 128), 256, dg::SMEM_BYTES>>>(
            pxh, pwh + W_1_OFF + (size_t)l * FF * DD, b1 + l * FF, phh, FF, DD);
        // ffn2 -> fp32 residual branch
        gemm_f16<false, false><<<dim3(NTOK / 256, DD / 128), 256, dg::SMEM_BYTES>>>(
            phh, pwh + W_2_OFF + (size_t)l * DD * FF, b2 + l * DD, pr, DD, FF);
        // x = LN(x + ffn2); xh = half(x)
        add_ln_kernel<<<NTOK, 128>>>(px, pxh, pr, ln2g + l * DD, ln2b + l * DD);
    }

    gather_act_kernel<<<NACT, 128>>>();
    sgemm_head<<<dim3((NACT + 127) / 128, VV / 128), 256>>>(
        pxa, hW, hb, out, NACT, VV, DD);
}

// round 7
// speedup vs baseline: 6.4349x; 1.0536x over previous
#include <cuda_runtime.h>
#include <cuda_fp16.h>
#include <cstdint>

// ---------------------------------------------------------------------------
// RT1 transformer forward — fp16 mma.sync(m16n8k16), fp32 accumulate.
// R7: dense GEMM retiled 128x128 (2 CTAs/SM) to hide barrier/epilogue bubbles.
// ---------------------------------------------------------------------------

namespace {
constexpr int Bz   = 32;
constexpr int KK   = 32;
constexpr int VIS  = 486;
constexpr int SS   = 584;
constexpr int DD   = 512;
constexpr int HH   = 8;
constexpr int LL   = 4;
constexpr int VV   = 256;
constexpr int AA   = 66;
constexpr int PP   = 518;
constexpr int FF   = 2048;
constexpr int NTOK = Bz * SS;    // 18688 = 146 * 128
constexpr int NACT = Bz * AA;    // 2112
constexpr float ATT_SCALE = 0.125f;
constexpr float NEGBIG    = -1e9f;

constexpr size_t W_QKV_OFF = 0;
constexpr size_t W_QKV_N   = (size_t)LL * 3 * DD * DD;
constexpr size_t W_O_OFF   = W_QKV_OFF + W_QKV_N;
constexpr size_t W_O_N     = (size_t)LL * DD * DD;
constexpr size_t W_1_OFF   = W_O_OFF + W_O_N;
constexpr size_t W_1_N     = (size_t)LL * FF * DD;
constexpr size_t W_2_OFF   = W_1_OFF + W_1_N;
constexpr size_t W_2_N     = (size_t)LL * DD * FF;
constexpr size_t W_TOTAL   = W_2_OFF + W_2_N;
}

// Scratch (static; cudaMalloc forbidden)
__device__ float  g_x   [NTOK * DD];
__device__ float  g_r   [NTOK * DD];
__device__ __half g_xh  [NTOK * DD];
__device__ __half g_qkvh[NTOK * 3 * DD];
__device__ __half g_oh  [NTOK * DD];
__device__ __half g_hh  [NTOK * FF];
__device__ float  g_xa  [NACT * DD];
__device__ __half g_wh  [W_TOTAL];

// ---------------------------------------------------------------------------
// PTX helpers
// ---------------------------------------------------------------------------
__device__ __forceinline__ void mma_f16(float* c, const uint32_t* a, const uint32_t* b) {
    asm volatile(
        "mma.sync.aligned.m16n8k16.row.col.f32.f16.f16.f32 "
        "{%0,%1,%2,%3}, {%4,%5,%6,%7}, {%8,%9}, {%0,%1,%2,%3};\n"
        : "+f"(c[0]), "+f"(c[1]), "+f"(c[2]), "+f"(c[3])
        : "r"(a[0]), "r"(a[1]), "r"(a[2]), "r"(a[3]), "r"(b[0]), "r"(b[1]));
}

__device__ __forceinline__ void ldsm4(uint32_t* r, uint32_t addr) {
    asm volatile("ldmatrix.sync.aligned.m8n8.x4.shared.b16 {%0,%1,%2,%3}, [%4];"
        : "=r"(r[0]), "=r"(r[1]), "=r"(r[2]), "=r"(r[3]) : "r"(addr));
}

__device__ __forceinline__ void cpa16(uint32_t dst, const void* src) {
    asm volatile("cp.async.cg.shared.global [%0], [%1], 16;" :: "r"(dst), "l"(src));
}
#define CP_COMMIT asm volatile("cp.async.commit_group;\n" ::: "memory")
#define CP_WAIT0  asm volatile("cp.async.wait_group 0;\n" ::: "memory")
#define CP_WAIT1  asm volatile("cp.async.wait_group 1;\n" ::: "memory")

// ---------------------------------------------------------------------------
// Weight conversion fp32 -> fp16
// ---------------------------------------------------------------------------
__global__ __launch_bounds__(256) void round_wh_kernel(
    const float* __restrict__ src, __half* __restrict__ dst, int n4)
{
    int i = blockIdx.x * 256 + threadIdx.x;
    if (i < n4) {
        float4 v = ((const float4*)src)[i];
        ((__half2*)dst)[2 * i + 0] = __floats2half2_rn(v.x, v.y);
        ((__half2*)dst)[2 * i + 1] = __floats2half2_rn(v.z, v.w);
    }
}

// ---------------------------------------------------------------------------
// Embedding / concat: exact x + half xh
// ---------------------------------------------------------------------------
__global__ __launch_bounds__(128) void embed_kernel(
    const float* __restrict__ lang, const float* __restrict__ vis,
    const int* __restrict__ aidx, const float* __restrict__ aemb)
{
    int n = blockIdx.x;
    int b = n / SS, s = n % SS;
    const float* src;
    if (s < KK)       src = lang + ((size_t)b * KK + s) * DD;
    else if (s < PP)  src = vis + ((size_t)b * VIS + (s - KK)) * DD;
    else {
        int tok = aidx[b * AA + (s - PP)];
        src = aemb + (size_t)tok * DD;
    }
    float4 v = ((const float4*)src)[threadIdx.x];
    ((float4*)(g_x + (size_t)n * DD))[threadIdx.x] = v;
    __half2* dh = (__half2*)(g_xh + (size_t)n * DD);
    dh[2 * threadIdx.x + 0] = __floats2half2_rn(v.x, v.y);
    dh[2 * threadIdx.x + 1] = __floats2half2_rn(v.z, v.w);
}

__global__ __launch_bounds__(128) void gather_act_kernel()
{
    int n = blockIdx.x;
    int b = n / AA, a = n % AA;
    ((float4*)(g_xa + (size_t)n * DD))[threadIdx.x] =
        ((const float4*)(g_x + ((size_t)(b * SS + PP + a)) * DD))[threadIdx.x];
}

// ---------------------------------------------------------------------------
// fp16 GEMM: C[M,N] = A[M,K] @ W[N,K]^T + bias[N]   (fp32 accumulate)
// BM=128, BN=128, BK=64, 256 thr, 8 warps 64x32 (2m x 4n), 3-stage cp.async.
// smem 110.6 KB -> 2 CTAs/SM; regs capped at 128 via launch_bounds(256,2).
// Requires M%128==0, N%128==0, K%64==0.
// ---------------------------------------------------------------------------
namespace dg {
constexpr int BM = 128, BN = 128, BK = 64, ST = 3;
constexpr int LDH = 72;                 // halves per row (144 B)
constexpr int A_H = BM * LDH;           // 9216 halves
constexpr int B_H = BN * LDH;           // 9216
constexpr int STAGE_H = A_H + B_H;      // 18432 halves = 36864 B
constexpr int SMEM_BYTES = ST * STAGE_H * 2;   // 110592
}

template<bool RELU, bool HOUT>
__global__ __launch_bounds__(256, 2) void gemm_f16(
    const __half* __restrict__ A, const __half* __restrict__ W,
    const float* __restrict__ bias, void* __restrict__ Cv, int N, int K)
{
    using namespace dg;
    extern __shared__ __half hs[];
    const uint32_t sbase = (uint32_t)__cvta_generic_to_shared(hs);

    const int tid = threadIdx.x, w = tid >> 5, lane = tid & 31;
    const int gid = lane >> 2, t4 = lane & 3;
    const int lrow = lane & 7, lsel = lane >> 3;
    const int bm = blockIdx.x * BM, bn = blockIdx.y * BN;
    const int wm = (w >> 2) * 64, wn = (w & 3) * 32;   // 2 m-warps x 4 n-warps

    float acc[4][4][4];
    #pragma unroll
    for (int i = 0; i < 4; ++i)
        #pragma unroll
        for (int j = 0; j < 4; ++j)
            #pragma unroll
            for (int v = 0; v < 4; ++v) acc[i][j][v] = 0.f;

    auto load_tile = [&](int t, int s) {
        const __half* Ab = A + (size_t)bm * K + t * BK;
        const __half* Wb = W + (size_t)bn * K + t * BK;
        const uint32_t sa = sbase + (uint32_t)(s * STAGE_H) * 2;
        const uint32_t sb = sa + A_H * 2;
        #pragma unroll
        for (int j = 0; j < 4; ++j) {
            int c = tid + j * 256;
            int r = c >> 3, kc = c & 7;
            cpa16(sa + (uint32_t)(r * LDH + kc * 8) * 2, Ab + (size_t)r * K + kc * 8);
        }
        #pragma unroll
        for (int j = 0; j < 4; ++j) {
            int c = tid + j * 256;
            int r = c >> 3, kc = c & 7;
            cpa16(sb + (uint32_t)(r * LDH + kc * 8) * 2, Wb + (size_t)r * K + kc * 8);
        }
        CP_COMMIT;
    };

    const int T = K / BK;
    load_tile(0, 0);
    load_tile(1, 1);

    for (int t = 0; t < T; ++t) {
        if (t + 1 < T) { CP_WAIT1; } else { CP_WAIT0; }
        __syncthreads();
        if (t + 2 < T) load_tile(t + 2, (t + 2) % ST);

        const uint32_t sa = sbase + (uint32_t)((t % ST) * STAGE_H) * 2;
        const uint32_t sb = sa + A_H * 2;
        #pragma unroll
        for (int kk = 0; kk < 4; ++kk) {
            uint32_t af[4][4], bf[4][2];
            #pragma unroll
            for (int mt = 0; mt < 4; ++mt) {
                uint32_t addr = sa + (uint32_t)(
                    (wm + mt * 16 + (lsel & 1) * 8 + lrow) * LDH
                    + kk * 16 + (lsel >> 1) * 8) * 2;
                ldsm4(af[mt], addr);
            }
            #pragma unroll
            for (int np = 0; np < 2; ++np) {
                uint32_t r4[4];
                uint32_t addr = sb + (uint32_t)(
                    (wn + np * 16 + (lsel >> 1) * 8 + lrow) * LDH
                    + kk * 16 + (lsel & 1) * 8) * 2;
                ldsm4(r4, addr);
                bf[np * 2][0]     = r4[0]; bf[np * 2][1]     = r4[1];
                bf[np * 2 + 1][0] = r4[2]; bf[np * 2 + 1][1] = r4[3];
            }
            #pragma unroll
            for (int mt = 0; mt < 4; ++mt)
                #pragma unroll
                for (int nt = 0; nt < 4; ++nt)
                    mma_f16(acc[mt][nt], af[mt], bf[nt]);
        }
    }

    // epilogue
    #pragma unroll
    for (int mt = 0; mt < 4; ++mt) {
        int r0 = bm + wm + mt * 16 + gid;
        #pragma unroll
        for (int nt = 0; nt < 4; ++nt) {
            int col = bn + wn + nt * 8 + 2 * t4;
            float b0 = bias[col], b1 = bias[col + 1];
            float2 v0, v1;
            v0.x = acc[mt][nt][0] + b0; v0.y = acc[mt][nt][1] + b1;
            v1.x = acc[mt][nt][2] + b0; v1.y = acc[mt][nt][3] + b1;
            if (RELU) {
                v0.x = fmaxf(v0.x, 0.f); v0.y = fmaxf(v0.y, 0.f);
                v1.x = fmaxf(v1.x, 0.f); v1.y = fmaxf(v1.y, 0.f);
            }
            if (HOUT) {
                __half2* C2 = (__half2*)Cv;
                C2[((size_t)r0 * N + col) >> 1]       = __floats2half2_rn(v0.x, v0.y);
                C2[((size_t)(r0 + 8) * N + col) >> 1] = __floats2half2_rn(v1.x, v1.y);
            } else {
                float* C = (float*)Cv;
                *(float2*)&C[(size_t)r0 * N + col]       = v0;
                *(float2*)&C[(size_t)(r0 + 8) * N + col] = v1;
            }
        }
    }
}

// ---------------------------------------------------------------------------
// Fused flash attention, fp16 operands, fp32 softmax/accumulate.
// ---------------------------------------------------------------------------
namespace fa {
constexpr int BQ = 128, BJ = 64, LDH = 72;
}

__global__ __launch_bounds__(256) void flash_kernel(
    const __half* __restrict__ qkv, __half* __restrict__ o)
{
    using namespace fa;
    __shared__ __half Qs[BQ * LDH];
    __shared__ __half Ks[BJ * LDH];
    __shared__ __half Vt[BJ * LDH];

    const int it = blockIdx.x, bh = blockIdx.y;
    const int b = bh >> 3, h = bh & 7;
    const __half* qbase = qkv + (size_t)b * SS * (3 * DD) + h * 64;
    const __half* kbase = qbase + DD;
    const __half* vbase = qbase + 2 * DD;

    const int tid = threadIdx.x;
    const int w = tid >> 5, lane = tid & 31;
    const int gid = lane >> 2, t4 = lane & 3;
    const int lrow = lane & 7, lsel = lane >> 3;
    const int wm = w * 16;

    const uint32_t qs_a = (uint32_t)__cvta_generic_to_shared(Qs);
    const uint32_t ks_a = (uint32_t)__cvta_generic_to_shared(Ks);
    const uint32_t vt_a = (uint32_t)__cvta_generic_to_shared(Vt);

    #pragma unroll
    for (int i = 0; i < 4; ++i) {
        int c = tid + i * 256;
        int r = c >> 3, kc = c & 7;
        int qi = it * BQ + r;
        uint4 v = make_uint4(0, 0, 0, 0);
        if (qi < SS) v = *(const uint4*)(qbase + (size_t)qi * (3 * DD) + kc * 8);
        *(uint4*)&Qs[r * LDH + kc * 8] = v;
    }
    __syncthreads();

    uint32_t qf[4][4];
    #pragma unroll
    for (int kk = 0; kk < 4; ++kk) {
        uint32_t addr = qs_a + (uint32_t)(
            (wm + (lsel & 1) * 8 + lrow) * LDH + kk * 16 + (lsel >> 1) * 8) * 2;
        ldsm4(qf[kk], addr);
    }

    const int row0 = it * BQ + wm + gid;
    const int row1 = row0 + 8;

    float m0 = -3.4e38f, m1 = -3.4e38f, l0 = 0.f, l1 = 0.f;
    float acc_o[8][4];
    #pragma unroll
    for (int j = 0; j < 8; ++j)
        #pragma unroll
        for (int v = 0; v < 4; ++v) acc_o[j][v] = 0.f;

    const int nTiles = (SS + BJ - 1) / BJ;
    for (int jt = 0; jt < nTiles; ++jt) {
        const int j0 = jt * BJ;
        __syncthreads();

        #pragma unroll
        for (int i = 0; i < 2; ++i) {
            int c = tid + i * 256;
            int r = c >> 3, kc = c & 7;
            int j = j0 + r;
            uint4 v = make_uint4(0, 0, 0, 0);
            if (j < SS) v = *(const uint4*)(kbase + (size_t)j * (3 * DD) + kc * 8);
            *(uint4*)&Ks[r * LDH + kc * 8] = v;
        }
        {
            int jp = lane;
            int jA = j0 + 2 * jp, jB = jA + 1;
            uint4 va = make_uint4(0, 0, 0, 0), vb = make_uint4(0, 0, 0, 0);
            if (jA < SS) va = *(const uint4*)(vbase + (size_t)jA * (3 * DD) + w * 8);
            if (jB < SS) vb = *(const uint4*)(vbase + (size_t)jB * (3 * DD) + w * 8);
            const __half* ha = (const __half*)&va;
            const __half* hb = (const __half*)&vb;
            #pragma unroll
            for (int i = 0; i < 8; ++i) {
                *(__half2*)&Vt[(w * 8 + i) * LDH + 2 * jp] =
                    __halves2half2(ha[i], hb[i]);
            }
        }
        __syncthreads();

        float s[8][4];
        #pragma unroll
        for (int j = 0; j < 8; ++j)
            #pragma unroll
            for (int v = 0; v < 4; ++v) s[j][v] = 0.f;

        #pragma unroll
        for (int kk = 0; kk < 4; ++kk) {
            uint32_t bf[8][2];
            #pragma unroll
            for (int np = 0; np < 4; ++np) {
                uint32_t r4[4];
                uint32_t addr = ks_a + (uint32_t)(
                    (np * 16 + (lsel >> 1) * 8 + lrow) * LDH
                    + kk * 16 + (lsel & 1) * 8) * 2;
                ldsm4(r4, addr);
                bf[np * 2][0]     = r4[0]; bf[np * 2][1]     = r4[1];
                bf[np * 2 + 1][0] = r4[2]; bf[np * 2 + 1][1] = r4[3];
            }
            #pragma unroll
            for (int nt = 0; nt < 8; ++nt)
                mma_f16(s[nt], qf[kk], bf[nt]);
        }

        float tmx0 = -3.4e38f, tmx1 = -3.4e38f;
        #pragma unroll
        for (int nt = 0; nt < 8; ++nt) {
            #pragma unroll
            for (int e = 0; e < 2; ++e) {
                int gj = j0 + nt * 8 + 2 * t4 + e;
                float v0 = s[nt][e] * ATT_SCALE;
                float v1 = s[nt][2 + e] * ATT_SCALE;
                bool al0 = (gj < PP) | (gj <= row0);
                bool al1 = (gj < PP) | (gj <= row1);
                v0 = al0 ? v0 : NEGBIG;
                v1 = al1 ? v1 : NEGBIG;
                s[nt][e] = v0; s[nt][2 + e] = v1;
                tmx0 = fmaxf(tmx0, v0);
                tmx1 = fmaxf(tmx1, v1);
            }
        }
        tmx0 = fmaxf(tmx0, __shfl_xor_sync(0xffffffffu, tmx0, 1));
        tmx0 = fmaxf(tmx0, __shfl_xor_sync(0xffffffffu, tmx0, 2));
        tmx1 = fmaxf(tmx1, __shfl_xor_sync(0xffffffffu, tmx1, 1));
        tmx1 = fmaxf(tmx1, __shfl_xor_sync(0xffffffffu, tmx1, 2));

        float nm0 = fmaxf(m0, tmx0), nm1 = fmaxf(m1, tmx1);
        float a0 = __expf(m0 - nm0), a1 = __expf(m1 - nm1);
        m0 = nm0; m1 = nm1;

        float sum0 = 0.f, sum1 = 0.f;
        #pragma unroll
        for (int nt = 0; nt < 8; ++nt) {
            #pragma unroll
            for (int e = 0; e < 2; ++e) {
                float p0 = __expf(s[nt][e] - nm0);
                float p1 = __expf(s[nt][2 + e] - nm1);
                s[nt][e] = p0; s[nt][2 + e] = p1;
                sum0 += p0; sum1 += p1;
            }
        }
        sum0 += __shfl_xor_sync(0xffffffffu, sum0, 1);
        sum0 += __shfl_xor_sync(0xffffffffu, sum0, 2);
        sum1 += __shfl_xor_sync(0xffffffffu, sum1, 1);
        sum1 += __shfl_xor_sync(0xffffffffu, sum1, 2);
        l0 = l0 * a0 + sum0;
        l1 = l1 * a1 + sum1;

        #pragma unroll
        for (int nt = 0; nt < 8; ++nt) {
            acc_o[nt][0] *= a0; acc_o[nt][1] *= a0;
            acc_o[nt][2] *= a1; acc_o[nt][3] *= a1;
        }

        #pragma unroll
        for (int nt = 0; nt < 8; ++nt) {
            *(__half2*)&Qs[(wm + gid) * LDH + nt * 8 + 2 * t4] =
                __floats2half2_rn(s[nt][0], s[nt][1]);
            *(__half2*)&Qs[(wm + gid + 8) * LDH + nt * 8 + 2 * t4] =
                __floats2half2_rn(s[nt][2], s[nt][3]);
        }
        __syncwarp();

        #pragma unroll
        for (int kk = 0; kk < 4; ++kk) {
            uint32_t af[4];
            uint32_t addr = qs_a + (uint32_t)(
                (wm + (lsel & 1) * 8 + lrow) * LDH + kk * 16 + (lsel >> 1) * 8) * 2;
            ldsm4(af, addr);
            uint32_t bf[8][2];
            #pragma unroll
            for (int np = 0; np < 4; ++np) {
                uint32_t r4[4];
                uint32_t vaddr = vt_a + (uint32_t)(
                    (np * 16 + (lsel >> 1) * 8 + lrow) * LDH
                    + kk * 16 + (lsel & 1) * 8) * 2;
                ldsm4(r4, vaddr);
                bf[np * 2][0]     = r4[0]; bf[np * 2][1]     = r4[1];
                bf[np * 2 + 1][0] = r4[2]; bf[np * 2 + 1][1] = r4[3];
            }
            #pragma unroll
            for (int nt = 0; nt < 8; ++nt)
                mma_f16(acc_o[nt], af, bf[nt]);
        }
    }

    float inv0 = 1.f / l0, inv1 = 1.f / l1;
    __half* ob = o + (size_t)b * SS * DD + h * 64;
    #pragma unroll
    for (int nt = 0; nt < 8; ++nt) {
        int col = nt * 8 + 2 * t4;
        if (row0 < SS)
            *(__half2*)&ob[(size_t)row0 * DD + col] =
                __floats2half2_rn(acc_o[nt][0] * inv0, acc_o[nt][1] * inv0);
        if (row1 < SS)
            *(__half2*)&ob[(size_t)row1 * DD + col] =
                __floats2half2_rn(acc_o[nt][2] * inv1, acc_o[nt][3] * inv1);
    }
}

// ---------------------------------------------------------------------------
// x = LayerNorm(x + r) * g + b ; writes exact x AND half xh
// ---------------------------------------------------------------------------
__global__ __launch_bounds__(128) void add_ln_kernel(
    float* __restrict__ x, __half* __restrict__ xh, const float* __restrict__ r,
    const float* __restrict__ g, const float* __restrict__ bta)
{
    __shared__ float sm[4];
    const size_t n = blockIdx.x;
    const int tid = threadIdx.x;

    float4 v  = *(const float4*)&x[n * DD + tid * 4];
    float4 rv = *(const float4*)&r[n * DD + tid * 4];
    v.x += rv.x; v.y += rv.y; v.z += rv.z; v.w += rv.w;

    float s = v.x + v.y + v.z + v.w;
    #pragma unroll
    for (int o = 16; o > 0; o >>= 1) s += __shfl_xor_sync(0xffffffffu, s, o);
    if ((tid & 31) == 0) sm[tid >> 5] = s;
    __syncthreads();
    float mu = (sm[0] + sm[1] + sm[2] + sm[3]) * (1.f / DD);
    __syncthreads();

    float dx = v.x - mu, dy = v.y - mu, dz = v.z - mu, dw = v.w - mu;
    float sq = dx * dx + dy * dy + dz * dz + dw * dw;
    #pragma unroll
    for (int o = 16; o > 0; o >>= 1) sq += __shfl_xor_sync(0xffffffffu, sq, o);
    if ((tid & 31) == 0) sm[tid >> 5] = sq;
    __syncthreads();
    float var = (sm[0] + sm[1] + sm[2] + sm[3]) * (1.f / DD);
    float rinv = rsqrtf(var + 1e-5f);

    float4 gg = *(const float4*)&g[tid * 4];
    float4 bb = *(const float4*)&bta[tid * 4];
    float4 out;
    out.x = dx * rinv * gg.x + bb.x;
    out.y = dy * rinv * gg.y + bb.y;
    out.z = dz * rinv * gg.z + bb.z;
    out.w = dw * rinv * gg.w + bb.w;
    *(float4*)&x[n * DD + tid * 4] = out;
    __half2* dh = (__half2*)(xh + n * DD);
    dh[2 * tid + 0] = __floats2half2_rn(out.x, out.y);
    dh[2 * tid + 1] = __floats2half2_rn(out.z, out.w);
}

// ---------------------------------------------------------------------------
// fp32 SGEMM for the head (M=2112, N=256, K=512)
// ---------------------------------------------------------------------------
__global__ __launch_bounds__(256) void sgemm_head(
    const float* __restrict__ A, const float* __restrict__ W,
    const float* __restrict__ bias, float* __restrict__ C,
    int M, int N, int K)
{
    constexpr int BM = 128, BN = 128, BK = 8;
    __shared__ float As[BK][BM + 4];
    __shared__ float Bs[BK][BN + 4];

    const int tid  = threadIdx.x;
    const int bm   = blockIdx.x * BM;
    const int bn   = blockIdx.y * BN;
    const int lrow = tid >> 1;
    const int lcol = (tid & 1) << 2;
    const int tr   = (tid >> 4) << 3;
    const int tc   = (tid & 15) << 3;

    const bool aok = (bm + lrow) < M;
    const bool wok = (bn + lrow) < N;
    const float* Aptr = A + (size_t)(bm + lrow) * K + lcol;
    const float* Wptr = W + (size_t)(bn + lrow) * K + lcol;

    float acc[8][8];
    #pragma unroll
    for (int i = 0; i < 8; ++i)
        #pragma unroll
        for (int j = 0; j < 8; ++j) acc[i][j] = 0.f;

    for (int t = 0; t < K / BK; ++t) {
        float4 pa = aok ? *(const float4*)(Aptr + (size_t)t * BK) : make_float4(0, 0, 0, 0);
        float4 pw = wok ? *(const float4*)(Wptr + (size_t)t * BK) : make_float4(0, 0, 0, 0);
        As[lcol + 0][lrow] = pa.x; As[lcol + 1][lrow] = pa.y;
        As[lcol + 2][lrow] = pa.z; As[lcol + 3][lrow] = pa.w;
        Bs[lcol + 0][lrow] = pw.x; Bs[lcol + 1][lrow] = pw.y;
        Bs[lcol + 2][lrow] = pw.z; Bs[lcol + 3][lrow] = pw.w;
        __syncthreads();
        #pragma unroll
        for (int k = 0; k < BK; ++k) {
            float af[8], bf[8];
            *(float4*)&af[0] = *(const float4*)&As[k][tr];
            *(float4*)&af[4] = *(const float4*)&As[k][tr + 4];
            *(float4*)&bf[0] = *(const float4*)&Bs[k][tc];
            *(float4*)&bf[4] = *(const float4*)&Bs[k][tc + 4];
            #pragma unroll
            for (int i = 0; i < 8; ++i)
                #pragma unroll
                for (int j = 0; j < 8; ++j)
                    acc[i][j] += af[i] * bf[j];
        }
        __syncthreads();
    }

    #pragma unroll
    for (int i = 0; i < 8; ++i) {
        int gr = bm + tr + i;
        if (gr < M) {
            #pragma unroll
            for (int jj = 0; jj < 8; jj += 4) {
                float4 v;
                v.x = acc[i][jj + 0] + bias[bn + tc + jj + 0];
                v.y = acc[i][jj + 1] + bias[bn + tc + jj + 1];
                v.z = acc[i][jj + 2] + bias[bn + tc + jj + 2];
                v.w = acc[i][jj + 3] + bias[bn + tc + jj + 3];
                *(float4*)&C[(size_t)gr * N + bn + tc + jj] = v;
            }
        }
    }
}

// ---------------------------------------------------------------------------
// Launch
// ---------------------------------------------------------------------------
extern "C" void kernel_launch(void* const* d_in, const int* in_sizes, int n_in,
                              void* d_out, int out_size)
{
    const float* lang = (const float*)d_in[0];
    const float* vis  = (const float*)d_in[1];
    const int*   aidx = (const int*)  d_in[2];
    const float* aemb = (const float*)d_in[3];
    const float* Wqkv = (const float*)d_in[4];
    const float* bqkv = (const float*)d_in[5];
    const float* Wo   = (const float*)d_in[6];
    const float* bo   = (const float*)d_in[7];
    const float* W1   = (const float*)d_in[8];
    const float* b1   = (const float*)d_in[9];
    const float* W2   = (const float*)d_in[10];
    const float* b2   = (const float*)d_in[11];
    const float* ln1g = (const float*)d_in[12];
    const float* ln1b = (const float*)d_in[13];
    const float* ln2g = (const float*)d_in[14];
    const float* ln2b = (const float*)d_in[15];
    const float* hW   = (const float*)d_in[16];
    const float* hb   = (const float*)d_in[17];
    float* out = (float*)d_out;

    float *px, *pr, *pxa;
    __half *pxh, *pqkvh, *poh, *phh, *pwh;
    cudaGetSymbolAddress((void**)&px,    g_x);
    cudaGetSymbolAddress((void**)&pr,    g_r);
    cudaGetSymbolAddress((void**)&pxa,   g_xa);
    cudaGetSymbolAddress((void**)&pxh,   g_xh);
    cudaGetSymbolAddress((void**)&pqkvh, g_qkvh);
    cudaGetSymbolAddress((void**)&poh,   g_oh);
    cudaGetSymbolAddress((void**)&phh,   g_hh);
    cudaGetSymbolAddress((void**)&pwh,   g_wh);

    cudaFuncSetAttribute(gemm_f16<false, false>,
        cudaFuncAttributeMaxDynamicSharedMemorySize, dg::SMEM_BYTES);
    cudaFuncSetAttribute(gemm_f16<false, true>,
        cudaFuncAttributeMaxDynamicSharedMemorySize, dg::SMEM_BYTES);
    cudaFuncSetAttribute(gemm_f16<true, true>,
        cudaFuncAttributeMaxDynamicSharedMemorySize, dg::SMEM_BYTES);

    round_wh_kernel<<<(int)(W_QKV_N / 4 + 255) / 256, 256>>>(Wqkv, pwh + W_QKV_OFF, (int)(W_QKV_N / 4));
    round_wh_kernel<<<(int)(W_O_N   / 4 + 255) / 256, 256>>>(Wo,   pwh + W_O_OFF,   (int)(W_O_N   / 4));
    round_wh_kernel<<<(int)(W_1_N   / 4 + 255) / 256, 256>>>(W1,   pwh + W_1_OFF,   (int)(W_1_N   / 4));
    round_wh_kernel<<<(int)(W_2_N   / 4 + 255) / 256, 256>>>(W2,   pwh + W_2_OFF,   (int)(W_2_N   / 4));

    embed_kernel<<<NTOK, 128>>>(lang, vis, aidx, aemb);

    for (int l = 0; l < LL; ++l) {
        // qkv = xh @ Wqkv^T + bqkv  -> half
        gemm_f16<false, true><<<dim3(NTOK / 128, (3 * DD) / 128), 256, dg::SMEM_BYTES>>>(
            pxh, pwh + W_QKV_OFF + (size_t)l * 3 * DD * DD, bqkv + l * 3 * DD,
            pqkvh, 3 * DD, DD);
        // fused attention -> half
        flash_kernel<<<dim3((SS + fa::BQ - 1) / fa::BQ, Bz * HH), 256>>>(pqkvh, poh);
        // o proj -> fp32 residual branch
        gemm_f16<false, false><<<dim3(NTOK / 128, DD / 128), 256, dg::SMEM_BYTES>>>(
            poh, pwh + W_O_OFF + (size_t)l * DD * DD, bo + l * DD, pr, DD, DD);
        // x = LN(x + oproj); xh = half(x)
        add_ln_kernel<<<NTOK, 128>>>(px, pxh, pr, ln1g + l * DD, ln1b + l * DD);
        // ffn1 (ReLU) -> half hidden
        gemm_f16<true, true><<<dim3(NTOK / 128, FF / 128), 256, dg::SMEM_BYTES>>>(
            pxh, pwh + W_1_OFF + (size_t)l * FF * DD, b1 + l * FF, phh, FF, DD);
        // ffn2 -> fp32 residual branch
        gemm_f16<false, false><<<dim3(NTOK / 128, DD / 128), 256, dg::SMEM_BYTES>>>(
            phh, pwh + W_2_OFF + (size_t)l * DD * FF, b2 + l * DD, pr, DD, FF);
        // x = LN(x + ffn2); xh = half(x)
        add_ln_kernel<<<NTOK, 128>>>(px, pxh, pr, ln2g + l * DD, ln2b + l * DD);
    }

    gather_act_kernel<<<NACT, 128>>>();
    sgemm_head<<<dim3((NACT + 127) / 128, VV / 128), 256>>>(
        pxa, hW, hb, out, NACT, VV, DD);
}

// round 9
// speedup vs baseline: 6.6244x; 1.0295x over previous
#include <cuda_runtime.h>
#include <cuda_fp16.h>
#include <cstdint>

// ---------------------------------------------------------------------------
// RT1 transformer forward — fp16 mma.sync(m16n8k16), fp32 accumulate.
// R9: R8 flash pipeline with DYNAMIC smem (static 48KB limit hit in R8);
// head GEMM on fp16 mma path.
// ---------------------------------------------------------------------------

namespace {
constexpr int Bz   = 32;
constexpr int KK   = 32;
constexpr int VIS  = 486;
constexpr int SS   = 584;
constexpr int DD   = 512;
constexpr int HH   = 8;
constexpr int LL   = 4;
constexpr int VV   = 256;
constexpr int AA   = 66;
constexpr int PP   = 518;
constexpr int FF   = 2048;
constexpr int NTOK = Bz * SS;    // 18688 = 146 * 128
constexpr int NACT = Bz * AA;    // 2112
constexpr int NACT_PAD = 2176;   // 17 * 128
constexpr float ATT_SCALE = 0.125f;
constexpr float NEGBIG    = -1e9f;

constexpr size_t W_QKV_OFF = 0;
constexpr size_t W_QKV_N   = (size_t)LL * 3 * DD * DD;
constexpr size_t W_O_OFF   = W_QKV_OFF + W_QKV_N;
constexpr size_t W_O_N     = (size_t)LL * DD * DD;
constexpr size_t W_1_OFF   = W_O_OFF + W_O_N;
constexpr size_t W_1_N     = (size_t)LL * FF * DD;
constexpr size_t W_2_OFF   = W_1_OFF + W_1_N;
constexpr size_t W_2_N     = (size_t)LL * DD * FF;
constexpr size_t W_H_OFF   = W_2_OFF + W_2_N;
constexpr size_t W_H_N     = (size_t)VV * DD;
constexpr size_t W_TOTAL   = W_H_OFF + W_H_N;
}

// Scratch (static; cudaMalloc forbidden)
__device__ float  g_x   [NTOK * DD];
__device__ float  g_r   [NTOK * DD];
__device__ __half g_xh  [NTOK * DD];
__device__ __half g_qkvh[NTOK * 3 * DD];
__device__ __half g_oh  [NTOK * DD];
__device__ __half g_hh  [NTOK * FF];
__device__ __half g_xah [NACT_PAD * DD];
__device__ __half g_wh  [W_TOTAL];

// ---------------------------------------------------------------------------
// PTX helpers
// ---------------------------------------------------------------------------
__device__ __forceinline__ void mma_f16(float* c, const uint32_t* a, const uint32_t* b) {
    asm volatile(
        "mma.sync.aligned.m16n8k16.row.col.f32.f16.f16.f32 "
        "{%0,%1,%2,%3}, {%4,%5,%6,%7}, {%8,%9}, {%0,%1,%2,%3};\n"
        : "+f"(c[0]), "+f"(c[1]), "+f"(c[2]), "+f"(c[3])
        : "r"(a[0]), "r"(a[1]), "r"(a[2]), "r"(a[3]), "r"(b[0]), "r"(b[1]));
}

__device__ __forceinline__ void ldsm4(uint32_t* r, uint32_t addr) {
    asm volatile("ldmatrix.sync.aligned.m8n8.x4.shared.b16 {%0,%1,%2,%3}, [%4];"
        : "=r"(r[0]), "=r"(r[1]), "=r"(r[2]), "=r"(r[3]) : "r"(addr));
}

__device__ __forceinline__ void cpa16(uint32_t dst, const void* src) {
    asm volatile("cp.async.cg.shared.global [%0], [%1], 16;" :: "r"(dst), "l"(src));
}
// zero-fill variant: src-size 0 -> fills 16B of zeros (no global read)
__device__ __forceinline__ void cpa16z(uint32_t dst, const void* src, int sz) {
    asm volatile("cp.async.cg.shared.global [%0], [%1], 16, %2;"
        :: "r"(dst), "l"(src), "r"(sz));
}
#define CP_COMMIT asm volatile("cp.async.commit_group;\n" ::: "memory")
#define CP_WAIT0  asm volatile("cp.async.wait_group 0;\n" ::: "memory")
#define CP_WAIT1  asm volatile("cp.async.wait_group 1;\n" ::: "memory")

// ---------------------------------------------------------------------------
// Weight conversion fp32 -> fp16
// ---------------------------------------------------------------------------
__global__ __launch_bounds__(256) void round_wh_kernel(
    const float* __restrict__ src, __half* __restrict__ dst, int n4)
{
    int i = blockIdx.x * 256 + threadIdx.x;
    if (i < n4) {
        float4 v = ((const float4*)src)[i];
        ((__half2*)dst)[2 * i + 0] = __floats2half2_rn(v.x, v.y);
        ((__half2*)dst)[2 * i + 1] = __floats2half2_rn(v.z, v.w);
    }
}

// ---------------------------------------------------------------------------
// Embedding / concat: exact x + half xh
// ---------------------------------------------------------------------------
__global__ __launch_bounds__(128) void embed_kernel(
    const float* __restrict__ lang, const float* __restrict__ vis,
    const int* __restrict__ aidx, const float* __restrict__ aemb)
{
    int n = blockIdx.x;
    int b = n / SS, s = n % SS;
    const float* src;
    if (s < KK)       src = lang + ((size_t)b * KK + s) * DD;
    else if (s < PP)  src = vis + ((size_t)b * VIS + (s - KK)) * DD;
    else {
        int tok = aidx[b * AA + (s - PP)];
        src = aemb + (size_t)tok * DD;
    }
    float4 v = ((const float4*)src)[threadIdx.x];
    ((float4*)(g_x + (size_t)n * DD))[threadIdx.x] = v;
    __half2* dh = (__half2*)(g_xh + (size_t)n * DD);
    dh[2 * threadIdx.x + 0] = __floats2half2_rn(v.x, v.y);
    dh[2 * threadIdx.x + 1] = __floats2half2_rn(v.z, v.w);
}

// gather action rows as half, zero-padded to NACT_PAD rows
__global__ __launch_bounds__(128) void gather_act_kernel()
{
    int n = blockIdx.x;          // 0..NACT_PAD-1
    __half2* dst = (__half2*)(g_xah + (size_t)n * DD);
    if (n < NACT) {
        int b = n / AA, a = n % AA;
        float4 v = ((const float4*)(g_x + ((size_t)(b * SS + PP + a)) * DD))[threadIdx.x];
        dst[2 * threadIdx.x + 0] = __floats2half2_rn(v.x, v.y);
        dst[2 * threadIdx.x + 1] = __floats2half2_rn(v.z, v.w);
    } else {
        __half2 z = __floats2half2_rn(0.f, 0.f);
        dst[2 * threadIdx.x + 0] = z;
        dst[2 * threadIdx.x + 1] = z;
    }
}

// ---------------------------------------------------------------------------
// fp16 GEMM: C[M,N] = A[M,K] @ W[N,K]^T + bias[N]   (fp32 accumulate)
// BM=128, BN=128, BK=64, 256 thr, 8 warps 64x32 (2m x 4n), 3-stage cp.async.
// Mlim guards output rows (for the padded head GEMM).
// ---------------------------------------------------------------------------
namespace dg {
constexpr int BM = 128, BN = 128, BK = 64, ST = 3;
constexpr int LDH = 72;
constexpr int A_H = BM * LDH;
constexpr int B_H = BN * LDH;
constexpr int STAGE_H = A_H + B_H;
constexpr int SMEM_BYTES = ST * STAGE_H * 2;   // 110592
}

template<bool RELU, bool HOUT>
__global__ __launch_bounds__(256, 2) void gemm_f16(
    const __half* __restrict__ A, const __half* __restrict__ W,
    const float* __restrict__ bias, void* __restrict__ Cv, int N, int K, int Mlim)
{
    using namespace dg;
    extern __shared__ __half hs[];
    const uint32_t sbase = (uint32_t)__cvta_generic_to_shared(hs);

    const int tid = threadIdx.x, w = tid >> 5, lane = tid & 31;
    const int gid = lane >> 2, t4 = lane & 3;
    const int lrow = lane & 7, lsel = lane >> 3;
    const int bm = blockIdx.x * BM, bn = blockIdx.y * BN;
    const int wm = (w >> 2) * 64, wn = (w & 3) * 32;

    float acc[4][4][4];
    #pragma unroll
    for (int i = 0; i < 4; ++i)
        #pragma unroll
        for (int j = 0; j < 4; ++j)
            #pragma unroll
            for (int v = 0; v < 4; ++v) acc[i][j][v] = 0.f;

    auto load_tile = [&](int t, int s) {
        const __half* Ab = A + (size_t)bm * K + t * BK;
        const __half* Wb = W + (size_t)bn * K + t * BK;
        const uint32_t sa = sbase + (uint32_t)(s * STAGE_H) * 2;
        const uint32_t sb = sa + A_H * 2;
        #pragma unroll
        for (int j = 0; j < 4; ++j) {
            int c = tid + j * 256;
            int r = c >> 3, kc = c & 7;
            cpa16(sa + (uint32_t)(r * LDH + kc * 8) * 2, Ab + (size_t)r * K + kc * 8);
        }
        #pragma unroll
        for (int j = 0; j < 4; ++j) {
            int c = tid + j * 256;
            int r = c >> 3, kc = c & 7;
            cpa16(sb + (uint32_t)(r * LDH + kc * 8) * 2, Wb + (size_t)r * K + kc * 8);
        }
        CP_COMMIT;
    };

    const int T = K / BK;
    load_tile(0, 0);
    load_tile(1, 1);

    for (int t = 0; t < T; ++t) {
        if (t + 1 < T) { CP_WAIT1; } else { CP_WAIT0; }
        __syncthreads();
        if (t + 2 < T) load_tile(t + 2, (t + 2) % ST);

        const uint32_t sa = sbase + (uint32_t)((t % ST) * STAGE_H) * 2;
        const uint32_t sb = sa + A_H * 2;
        #pragma unroll
        for (int kk = 0; kk < 4; ++kk) {
            uint32_t af[4][4], bf[4][2];
            #pragma unroll
            for (int mt = 0; mt < 4; ++mt) {
                uint32_t addr = sa + (uint32_t)(
                    (wm + mt * 16 + (lsel & 1) * 8 + lrow) * LDH
                    + kk * 16 + (lsel >> 1) * 8) * 2;
                ldsm4(af[mt], addr);
            }
            #pragma unroll
            for (int np = 0; np < 2; ++np) {
                uint32_t r4[4];
                uint32_t addr = sb + (uint32_t)(
                    (wn + np * 16 + (lsel >> 1) * 8 + lrow) * LDH
                    + kk * 16 + (lsel & 1) * 8) * 2;
                ldsm4(r4, addr);
                bf[np * 2][0]     = r4[0]; bf[np * 2][1]     = r4[1];
                bf[np * 2 + 1][0] = r4[2]; bf[np * 2 + 1][1] = r4[3];
            }
            #pragma unroll
            for (int mt = 0; mt < 4; ++mt)
                #pragma unroll
                for (int nt = 0; nt < 4; ++nt)
                    mma_f16(acc[mt][nt], af[mt], bf[nt]);
        }
    }

    // epilogue
    #pragma unroll
    for (int mt = 0; mt < 4; ++mt) {
        int r0 = bm + wm + mt * 16 + gid;
        #pragma unroll
        for (int nt = 0; nt < 4; ++nt) {
            int col = bn + wn + nt * 8 + 2 * t4;
            float b0 = bias[col], b1 = bias[col + 1];
            float2 v0, v1;
            v0.x = acc[mt][nt][0] + b0; v0.y = acc[mt][nt][1] + b1;
            v1.x = acc[mt][nt][2] + b0; v1.y = acc[mt][nt][3] + b1;
            if (RELU) {
                v0.x = fmaxf(v0.x, 0.f); v0.y = fmaxf(v0.y, 0.f);
                v1.x = fmaxf(v1.x, 0.f); v1.y = fmaxf(v1.y, 0.f);
            }
            if (HOUT) {
                __half2* C2 = (__half2*)Cv;
                if (r0 < Mlim)
                    C2[((size_t)r0 * N + col) >> 1]       = __floats2half2_rn(v0.x, v0.y);
                if (r0 + 8 < Mlim)
                    C2[((size_t)(r0 + 8) * N + col) >> 1] = __floats2half2_rn(v1.x, v1.y);
            } else {
                float* C = (float*)Cv;
                if (r0 < Mlim)
                    *(float2*)&C[(size_t)r0 * N + col]       = v0;
                if (r0 + 8 < Mlim)
                    *(float2*)&C[(size_t)(r0 + 8) * N + col] = v1;
            }
        }
    }
}

// ---------------------------------------------------------------------------
// Fused flash attention, fp16 operands, fp32 softmax/accumulate.
// K double-buffered via cp.async (zero-fill tails); V prefetched to regs one
// tile ahead, staged transposed into double-buffered Vt. Dynamic smem.
// Layout (halves): Qs[0 .. BQ*LDH) | Ks[2][BJ*LDH] | Vt[2][BJ*LDH]
// Total = (128 + 4*64) * 72 * 2 = 55296 bytes.
// ---------------------------------------------------------------------------
namespace fa {
constexpr int BQ = 128, BJ = 64, LDH = 72;
constexpr int KS_OFF = BQ * LDH;                 // 9216
constexpr int VT_OFF = KS_OFF + 2 * BJ * LDH;    // 18432
constexpr int SMEM_BYTES = (VT_OFF + 2 * BJ * LDH) * 2;   // 55296
}

__global__ __launch_bounds__(256) void flash_kernel(
    const __half* __restrict__ qkv, __half* __restrict__ o)
{
    using namespace fa;
    extern __shared__ __half fsm[];
    __half* Qs = fsm;
    __half* Ksm = fsm + KS_OFF;    // [2][BJ*LDH]
    __half* Vtm = fsm + VT_OFF;    // [2][BJ*LDH]

    const int it = blockIdx.x, bh = blockIdx.y;
    const int b = bh >> 3, h = bh & 7;
    const __half* qbase = qkv + (size_t)b * SS * (3 * DD) + h * 64;
    const __half* kbase = qbase + DD;
    const __half* vbase = qbase + 2 * DD;

    const int tid = threadIdx.x;
    const int w = tid >> 5, lane = tid & 31;
    const int gid = lane >> 2, t4 = lane & 3;
    const int lrow = lane & 7, lsel = lane >> 3;
    const int wm = w * 16;

    const uint32_t qs_a = (uint32_t)__cvta_generic_to_shared(Qs);
    const uint32_t ks_a = (uint32_t)__cvta_generic_to_shared(Ksm);
    const uint32_t vt_a = (uint32_t)__cvta_generic_to_shared(Vtm);

    auto load_K = [&](int jt, int buf) {
        #pragma unroll
        for (int i = 0; i < 2; ++i) {
            int c = tid + i * 256;
            int r = c >> 3, kc = c & 7;
            int j = jt * BJ + r;
            int sz = (j < SS) ? 16 : 0;
            cpa16z(ks_a + (uint32_t)(buf * BJ * LDH + r * LDH + kc * 8) * 2,
                   kbase + (size_t)j * (3 * DD) + kc * 8, sz);
        }
        CP_COMMIT;
    };
    auto load_V = [&](int jt, uint4& va, uint4& vb) {
        int jA = jt * BJ + 2 * lane, jB = jA + 1;
        va = make_uint4(0, 0, 0, 0); vb = make_uint4(0, 0, 0, 0);
        if (jA < SS) va = *(const uint4*)(vbase + (size_t)jA * (3 * DD) + w * 8);
        if (jB < SS) vb = *(const uint4*)(vbase + (size_t)jB * (3 * DD) + w * 8);
    };

    // ---- prologue ----
    load_K(0, 0);
    uint4 va, vb;
    load_V(0, va, vb);

    #pragma unroll
    for (int i = 0; i < 4; ++i) {
        int c = tid + i * 256;
        int r = c >> 3, kc = c & 7;
        int qi = it * BQ + r;
        uint4 v = make_uint4(0, 0, 0, 0);
        if (qi < SS) v = *(const uint4*)(qbase + (size_t)qi * (3 * DD) + kc * 8);
        *(uint4*)&Qs[r * LDH + kc * 8] = v;
    }
    __syncthreads();

    uint32_t qf[4][4];
    #pragma unroll
    for (int kk = 0; kk < 4; ++kk) {
        uint32_t addr = qs_a + (uint32_t)(
            (wm + (lsel & 1) * 8 + lrow) * LDH + kk * 16 + (lsel >> 1) * 8) * 2;
        ldsm4(qf[kk], addr);
    }

    const int row0 = it * BQ + wm + gid;
    const int row1 = row0 + 8;

    float m0 = -3.4e38f, m1 = -3.4e38f, l0 = 0.f, l1 = 0.f;
    float acc_o[8][4];
    #pragma unroll
    for (int j = 0; j < 8; ++j)
        #pragma unroll
        for (int v = 0; v < 4; ++v) acc_o[j][v] = 0.f;

    const int nTiles = (SS + BJ - 1) / BJ;   // 10
    for (int jt = 0; jt < nTiles; ++jt) {
        const int bsel = jt & 1;
        const int j0 = jt * BJ;
        __syncthreads();   // buffers bsel free (consumed at jt-2), Vt[bsel] free

        if (jt + 1 < nTiles) load_K(jt + 1, bsel ^ 1);

        // stage V(jt) transposed into Vt[bsel]
        {
            const __half* ha = (const __half*)&va;
            const __half* hb2 = (const __half*)&vb;
            #pragma unroll
            for (int i = 0; i < 8; ++i) {
                *(__half2*)&Vtm[bsel * BJ * LDH + (w * 8 + i) * LDH + 2 * lane] =
                    __halves2half2(ha[i], hb2[i]);
            }
        }
        if (jt + 1 < nTiles) { load_V(jt + 1, va, vb); CP_WAIT1; }
        else                 { CP_WAIT0; }
        __syncthreads();   // Ks[bsel] + Vt[bsel] ready

        // ---- S = Q @ K^T ----
        float s[8][4];
        #pragma unroll
        for (int j = 0; j < 8; ++j)
            #pragma unroll
            for (int v = 0; v < 4; ++v) s[j][v] = 0.f;

        const uint32_t ksb = ks_a + (uint32_t)(bsel * BJ * LDH) * 2;
        #pragma unroll
        for (int kk = 0; kk < 4; ++kk) {
            uint32_t bf[8][2];
            #pragma unroll
            for (int np = 0; np < 4; ++np) {
                uint32_t r4[4];
                uint32_t addr = ksb + (uint32_t)(
                    (np * 16 + (lsel >> 1) * 8 + lrow) * LDH
                    + kk * 16 + (lsel & 1) * 8) * 2;
                ldsm4(r4, addr);
                bf[np * 2][0]     = r4[0]; bf[np * 2][1]     = r4[1];
                bf[np * 2 + 1][0] = r4[2]; bf[np * 2 + 1][1] = r4[3];
            }
            #pragma unroll
            for (int nt = 0; nt < 8; ++nt)
                mma_f16(s[nt], qf[kk], bf[nt]);
        }

        // ---- scale + mask, tile max ----
        float tmx0 = -3.4e38f, tmx1 = -3.4e38f;
        #pragma unroll
        for (int nt = 0; nt < 8; ++nt) {
            #pragma unroll
            for (int e = 0; e < 2; ++e) {
                int gj = j0 + nt * 8 + 2 * t4 + e;
                float v0 = s[nt][e] * ATT_SCALE;
                float v1 = s[nt][2 + e] * ATT_SCALE;
                bool al0 = (gj < PP) | (gj <= row0);
                bool al1 = (gj < PP) | (gj <= row1);
                v0 = al0 ? v0 : NEGBIG;
                v1 = al1 ? v1 : NEGBIG;
                s[nt][e] = v0; s[nt][2 + e] = v1;
                tmx0 = fmaxf(tmx0, v0);
                tmx1 = fmaxf(tmx1, v1);
            }
        }
        tmx0 = fmaxf(tmx0, __shfl_xor_sync(0xffffffffu, tmx0, 1));
        tmx0 = fmaxf(tmx0, __shfl_xor_sync(0xffffffffu, tmx0, 2));
        tmx1 = fmaxf(tmx1, __shfl_xor_sync(0xffffffffu, tmx1, 1));
        tmx1 = fmaxf(tmx1, __shfl_xor_sync(0xffffffffu, tmx1, 2));

        float nm0 = fmaxf(m0, tmx0), nm1 = fmaxf(m1, tmx1);
        float a0 = __expf(m0 - nm0), a1 = __expf(m1 - nm1);
        m0 = nm0; m1 = nm1;

        float sum0 = 0.f, sum1 = 0.f;
        #pragma unroll
        for (int nt = 0; nt < 8; ++nt) {
            #pragma unroll
            for (int e = 0; e < 2; ++e) {
                float p0 = __expf(s[nt][e] - nm0);
                float p1 = __expf(s[nt][2 + e] - nm1);
                s[nt][e] = p0; s[nt][2 + e] = p1;
                sum0 += p0; sum1 += p1;
            }
        }
        sum0 += __shfl_xor_sync(0xffffffffu, sum0, 1);
        sum0 += __shfl_xor_sync(0xffffffffu, sum0, 2);
        sum1 += __shfl_xor_sync(0xffffffffu, sum1, 1);
        sum1 += __shfl_xor_sync(0xffffffffu, sum1, 2);
        l0 = l0 * a0 + sum0;
        l1 = l1 * a1 + sum1;

        #pragma unroll
        for (int nt = 0; nt < 8; ++nt) {
            acc_o[nt][0] *= a0; acc_o[nt][1] *= a0;
            acc_o[nt][2] *= a1; acc_o[nt][3] *= a1;
        }

        // ---- write half P to warp-private rows of Qs ----
        #pragma unroll
        for (int nt = 0; nt < 8; ++nt) {
            *(__half2*)&Qs[(wm + gid) * LDH + nt * 8 + 2 * t4] =
                __floats2half2_rn(s[nt][0], s[nt][1]);
            *(__half2*)&Qs[(wm + gid + 8) * LDH + nt * 8 + 2 * t4] =
                __floats2half2_rn(s[nt][2], s[nt][3]);
        }
        __syncwarp();

        // ---- O += P @ V ----
        const uint32_t vtb = vt_a + (uint32_t)(bsel * BJ * LDH) * 2;
        #pragma unroll
        for (int kk = 0; kk < 4; ++kk) {
            uint32_t af[4];
            uint32_t addr = qs_a + (uint32_t)(
                (wm + (lsel & 1) * 8 + lrow) * LDH + kk * 16 + (lsel >> 1) * 8) * 2;
            ldsm4(af, addr);
            uint32_t bf[8][2];
            #pragma unroll
            for (int np = 0; np < 4; ++np) {
                uint32_t r4[4];
                uint32_t vaddr = vtb + (uint32_t)(
                    (np * 16 + (lsel >> 1) * 8 + lrow) * LDH
                    + kk * 16 + (lsel & 1) * 8) * 2;
                ldsm4(r4, vaddr);
                bf[np * 2][0]     = r4[0]; bf[np * 2][1]     = r4[1];
                bf[np * 2 + 1][0] = r4[2]; bf[np * 2 + 1][1] = r4[3];
            }
            #pragma unroll
            for (int nt = 0; nt < 8; ++nt)
                mma_f16(acc_o[nt], af, bf[nt]);
        }
    }

    float inv0 = 1.f / l0, inv1 = 1.f / l1;
    __half* ob = o + (size_t)b * SS * DD + h * 64;
    #pragma unroll
    for (int nt = 0; nt < 8; ++nt) {
        int col = nt * 8 + 2 * t4;
        if (row0 < SS)
            *(__half2*)&ob[(size_t)row0 * DD + col] =
                __floats2half2_rn(acc_o[nt][0] * inv0, acc_o[nt][1] * inv0);
        if (row1 < SS)
            *(__half2*)&ob[(size_t)row1 * DD + col] =
                __floats2half2_rn(acc_o[nt][2] * inv1, acc_o[nt][3] * inv1);
    }
}

// ---------------------------------------------------------------------------
// x = LayerNorm(x + r) * g + b ; writes exact x AND half xh
// ---------------------------------------------------------------------------
__global__ __launch_bounds__(128) void add_ln_kernel(
    float* __restrict__ x, __half* __restrict__ xh, const float* __restrict__ r,
    const float* __restrict__ g, const float* __restrict__ bta)
{
    __shared__ float sm[4];
    const size_t n = blockIdx.x;
    const int tid = threadIdx.x;

    float4 v  = *(const float4*)&x[n * DD + tid * 4];
    float4 rv = *(const float4*)&r[n * DD + tid * 4];
    v.x += rv.x; v.y += rv.y; v.z += rv.z; v.w += rv.w;

    float s = v.x + v.y + v.z + v.w;
    #pragma unroll
    for (int o = 16; o > 0; o >>= 1) s += __shfl_xor_sync(0xffffffffu, s, o);
    if ((tid & 31) == 0) sm[tid >> 5] = s;
    __syncthreads();
    float mu = (sm[0] + sm[1] + sm[2] + sm[3]) * (1.f / DD);
    __syncthreads();

    float dx = v.x - mu, dy = v.y - mu, dz = v.z - mu, dw = v.w - mu;
    float sq = dx * dx + dy * dy + dz * dz + dw * dw;
    #pragma unroll
    for (int o = 16; o > 0; o >>= 1) sq += __shfl_xor_sync(0xffffffffu, sq, o);
    if ((tid & 31) == 0) sm[tid >> 5] = sq;
    __syncthreads();
    float var = (sm[0] + sm[1] + sm[2] + sm[3]) * (1.f / DD);
    float rinv = rsqrtf(var + 1e-5f);

    float4 gg = *(const float4*)&g[tid * 4];
    float4 bb = *(const float4*)&bta[tid * 4];
    float4 out;
    out.x = dx * rinv * gg.x + bb.x;
    out.y = dy * rinv * gg.y + bb.y;
    out.z = dz * rinv * gg.z + bb.z;
    out.w = dw * rinv * gg.w + bb.w;
    *(float4*)&x[n * DD + tid * 4] = out;
    __half2* dh = (__half2*)(xh + n * DD);
    dh[2 * tid + 0] = __floats2half2_rn(out.x, out.y);
    dh[2 * tid + 1] = __floats2half2_rn(out.z, out.w);
}

// ---------------------------------------------------------------------------
// Launch
// ---------------------------------------------------------------------------
extern "C" void kernel_launch(void* const* d_in, const int* in_sizes, int n_in,
                              void* d_out, int out_size)
{
    const float* lang = (const float*)d_in[0];
    const float* vis  = (const float*)d_in[1];
    const int*   aidx = (const int*)  d_in[2];
    const float* aemb = (const float*)d_in[3];
    const float* Wqkv = (const float*)d_in[4];
    const float* bqkv = (const float*)d_in[5];
    const float* Wo   = (const float*)d_in[6];
    const float* bo   = (const float*)d_in[7];
    const float* W1   = (const float*)d_in[8];
    const float* b1   = (const float*)d_in[9];
    const float* W2   = (const float*)d_in[10];
    const float* b2   = (const float*)d_in[11];
    const float* ln1g = (const float*)d_in[12];
    const float* ln1b = (const float*)d_in[13];
    const float* ln2g = (const float*)d_in[14];
    const float* ln2b = (const float*)d_in[15];
    const float* hW   = (const float*)d_in[16];
    const float* hb   = (const float*)d_in[17];
    float* out = (float*)d_out;

    float *px, *pr;
    __half *pxh, *pqkvh, *poh, *phh, *pxah, *pwh;
    cudaGetSymbolAddress((void**)&px,    g_x);
    cudaGetSymbolAddress((void**)&pr,    g_r);
    cudaGetSymbolAddress((void**)&pxh,   g_xh);
    cudaGetSymbolAddress((void**)&pqkvh, g_qkvh);
    cudaGetSymbolAddress((void**)&poh,   g_oh);
    cudaGetSymbolAddress((void**)&phh,   g_hh);
    cudaGetSymbolAddress((void**)&pxah,  g_xah);
    cudaGetSymbolAddress((void**)&pwh,   g_wh);

    cudaFuncSetAttribute(gemm_f16<false, false>,
        cudaFuncAttributeMaxDynamicSharedMemorySize, dg::SMEM_BYTES);
    cudaFuncSetAttribute(gemm_f16<false, true>,
        cudaFuncAttributeMaxDynamicSharedMemorySize, dg::SMEM_BYTES);
    cudaFuncSetAttribute(gemm_f16<true, true>,
        cudaFuncAttributeMaxDynamicSharedMemorySize, dg::SMEM_BYTES);
    cudaFuncSetAttribute(flash_kernel,
        cudaFuncAttributeMaxDynamicSharedMemorySize, fa::SMEM_BYTES);

    round_wh_kernel<<<(int)(W_QKV_N / 4 + 255) / 256, 256>>>(Wqkv, pwh + W_QKV_OFF, (int)(W_QKV_N / 4));
    round_wh_kernel<<<(int)(W_O_N   / 4 + 255) / 256, 256>>>(Wo,   pwh + W_O_OFF,   (int)(W_O_N   / 4));
    round_wh_kernel<<<(int)(W_1_N   / 4 + 255) / 256, 256>>>(W1,   pwh + W_1_OFF,   (int)(W_1_N   / 4));
    round_wh_kernel<<<(int)(W_2_N   / 4 + 255) / 256, 256>>>(W2,   pwh + W_2_OFF,   (int)(W_2_N   / 4));
    round_wh_kernel<<<(int)(W_H_N   / 4 + 255) / 256, 256>>>(hW,   pwh + W_H_OFF,   (int)(W_H_N   / 4));

    embed_kernel<<<NTOK, 128>>>(lang, vis, aidx, aemb);

    for (int l = 0; l < LL; ++l) {
        // qkv = xh @ Wqkv^T + bqkv  -> half
        gemm_f16<false, true><<<dim3(NTOK / 128, (3 * DD) / 128), 256, dg::SMEM_BYTES>>>(
            pxh, pwh + W_QKV_OFF + (size_t)l * 3 * DD * DD, bqkv + l * 3 * DD,
            pqkvh, 3 * DD, DD, NTOK);
        // fused attention -> half
        flash_kernel<<<dim3((SS + fa::BQ - 1) / fa::BQ, Bz * HH), 256, fa::SMEM_BYTES>>>(
            pqkvh, poh);
        // o proj -> fp32 residual branch
        gemm_f16<false, false><<<dim3(NTOK / 128, DD / 128), 256, dg::SMEM_BYTES>>>(
            poh, pwh + W_O_OFF + (size_t)l * DD * DD, bo + l * DD, pr, DD, DD, NTOK);
        // x = LN(x + oproj); xh = half(x)
        add_ln_kernel<<<NTOK, 128>>>(px, pxh, pr, ln1g + l * DD, ln1b + l * DD);
        // ffn1 (ReLU) -> half hidden
        gemm_f16<true, true><<<dim3(NTOK / 128, FF / 128), 256, dg::SMEM_BYTES>>>(
            pxh, pwh + W_1_OFF + (size_t)l * FF * DD, b1 + l * FF, phh, FF, DD, NTOK);
        // ffn2 -> fp32 residual branch
        gemm_f16<false, false><<<dim3(NTOK / 128, DD / 128), 256, dg::SMEM_BYTES>>>(
            phh, pwh + W_2_OFF + (size_t)l * DD * FF, b2 + l * DD, pr, DD, FF, NTOK);
        // x = LN(x + ffn2); xh = half(x)
        add_ln_kernel<<<NTOK, 128>>>(px, pxh, pr, ln2g + l * DD, ln2b + l * DD);
    }

    // head on the 66 action positions (fp16 mma, padded M, guarded stores)
    gather_act_kernel<<<NACT_PAD, 128>>>();
    gemm_f16<false, false><<<dim3(NACT_PAD / 128, VV / 128), 256, dg::SMEM_BYTES>>>(
        pxah, pwh + W_H_OFF, hb, out, VV, DD, NACT);
}

// round 12
// speedup vs baseline: 6.9365x; 1.0471x over previous
#include <cuda_runtime.h>
#include <cuda_fp16.h>
#include <cstdint>

// ---------------------------------------------------------------------------
// RT1 transformer forward — fp16 mma.sync(m16n8k16), fp32 accumulate.
// R12 = R10 resubmitted (two broker-level infra failures, no kernel signal):
// flash at 2 CTAs/SM (launch_bounds cap); warp-per-token add_ln.
// ---------------------------------------------------------------------------

namespace {
constexpr int Bz   = 32;
constexpr int KK   = 32;
constexpr int VIS  = 486;
constexpr int SS   = 584;
constexpr int DD   = 512;
constexpr int HH   = 8;
constexpr int LL   = 4;
constexpr int VV   = 256;
constexpr int AA   = 66;
constexpr int PP   = 518;
constexpr int FF   = 2048;
constexpr int NTOK = Bz * SS;    // 18688 = 146 * 128 = 2336 * 8
constexpr int NACT = Bz * AA;    // 2112
constexpr int NACT_PAD = 2176;   // 17 * 128
constexpr float ATT_SCALE = 0.125f;
constexpr float NEGBIG    = -1e9f;

constexpr size_t W_QKV_OFF = 0;
constexpr size_t W_QKV_N   = (size_t)LL * 3 * DD * DD;
constexpr size_t W_O_OFF   = W_QKV_OFF + W_QKV_N;
constexpr size_t W_O_N     = (size_t)LL * DD * DD;
constexpr size_t W_1_OFF   = W_O_OFF + W_O_N;
constexpr size_t W_1_N     = (size_t)LL * FF * DD;
constexpr size_t W_2_OFF   = W_1_OFF + W_1_N;
constexpr size_t W_2_N     = (size_t)LL * DD * FF;
constexpr size_t W_H_OFF   = W_2_OFF + W_2_N;
constexpr size_t W_H_N     = (size_t)VV * DD;
constexpr size_t W_TOTAL   = W_H_OFF + W_H_N;
}

// Scratch (static; cudaMalloc forbidden)
__device__ float  g_x   [NTOK * DD];
__device__ float  g_r   [NTOK * DD];
__device__ __half g_xh  [NTOK * DD];
__device__ __half g_qkvh[NTOK * 3 * DD];
__device__ __half g_oh  [NTOK * DD];
__device__ __half g_hh  [NTOK * FF];
__device__ __half g_xah [NACT_PAD * DD];
__device__ __half g_wh  [W_TOTAL];

// ---------------------------------------------------------------------------
// PTX helpers
// ---------------------------------------------------------------------------
__device__ __forceinline__ void mma_f16(float* c, const uint32_t* a, const uint32_t* b) {
    asm volatile(
        "mma.sync.aligned.m16n8k16.row.col.f32.f16.f16.f32 "
        "{%0,%1,%2,%3}, {%4,%5,%6,%7}, {%8,%9}, {%0,%1,%2,%3};\n"
        : "+f"(c[0]), "+f"(c[1]), "+f"(c[2]), "+f"(c[3])
        : "r"(a[0]), "r"(a[1]), "r"(a[2]), "r"(a[3]), "r"(b[0]), "r"(b[1]));
}

__device__ __forceinline__ void ldsm4(uint32_t* r, uint32_t addr) {
    asm volatile("ldmatrix.sync.aligned.m8n8.x4.shared.b16 {%0,%1,%2,%3}, [%4];"
        : "=r"(r[0]), "=r"(r[1]), "=r"(r[2]), "=r"(r[3]) : "r"(addr));
}

__device__ __forceinline__ void cpa16(uint32_t dst, const void* src) {
    asm volatile("cp.async.cg.shared.global [%0], [%1], 16;" :: "r"(dst), "l"(src));
}
__device__ __forceinline__ void cpa16z(uint32_t dst, const void* src, int sz) {
    asm volatile("cp.async.cg.shared.global [%0], [%1], 16, %2;"
        :: "r"(dst), "l"(src), "r"(sz));
}
#define CP_COMMIT asm volatile("cp.async.commit_group;\n" ::: "memory")
#define CP_WAIT0  asm volatile("cp.async.wait_group 0;\n" ::: "memory")
#define CP_WAIT1  asm volatile("cp.async.wait_group 1;\n" ::: "memory")

// ---------------------------------------------------------------------------
// Weight conversion fp32 -> fp16
// ---------------------------------------------------------------------------
__global__ __launch_bounds__(256) void round_wh_kernel(
    const float* __restrict__ src, __half* __restrict__ dst, int n4)
{
    int i = blockIdx.x * 256 + threadIdx.x;
    if (i < n4) {
        float4 v = ((const float4*)src)[i];
        ((__half2*)dst)[2 * i + 0] = __floats2half2_rn(v.x, v.y);
        ((__half2*)dst)[2 * i + 1] = __floats2half2_rn(v.z, v.w);
    }
}

// ---------------------------------------------------------------------------
// Embedding / concat: exact x + half xh
// ---------------------------------------------------------------------------
__global__ __launch_bounds__(128) void embed_kernel(
    const float* __restrict__ lang, const float* __restrict__ vis,
    const int* __restrict__ aidx, const float* __restrict__ aemb)
{
    int n = blockIdx.x;
    int b = n / SS, s = n % SS;
    const float* src;
    if (s < KK)       src = lang + ((size_t)b * KK + s) * DD;
    else if (s < PP)  src = vis + ((size_t)b * VIS + (s - KK)) * DD;
    else {
        int tok = aidx[b * AA + (s - PP)];
        src = aemb + (size_t)tok * DD;
    }
    float4 v = ((const float4*)src)[threadIdx.x];
    ((float4*)(g_x + (size_t)n * DD))[threadIdx.x] = v;
    __half2* dh = (__half2*)(g_xh + (size_t)n * DD);
    dh[2 * threadIdx.x + 0] = __floats2half2_rn(v.x, v.y);
    dh[2 * threadIdx.x + 1] = __floats2half2_rn(v.z, v.w);
}

// gather action rows as half, zero-padded to NACT_PAD rows
__global__ __launch_bounds__(128) void gather_act_kernel()
{
    int n = blockIdx.x;
    __half2* dst = (__half2*)(g_xah + (size_t)n * DD);
    if (n < NACT) {
        int b = n / AA, a = n % AA;
        float4 v = ((const float4*)(g_x + ((size_t)(b * SS + PP + a)) * DD))[threadIdx.x];
        dst[2 * threadIdx.x + 0] = __floats2half2_rn(v.x, v.y);
        dst[2 * threadIdx.x + 1] = __floats2half2_rn(v.z, v.w);
    } else {
        __half2 z = __floats2half2_rn(0.f, 0.f);
        dst[2 * threadIdx.x + 0] = z;
        dst[2 * threadIdx.x + 1] = z;
    }
}

// ---------------------------------------------------------------------------
// fp16 GEMM: C[M,N] = A[M,K] @ W[N,K]^T + bias[N]   (fp32 accumulate)
// BM=128, BN=128, BK=64, 256 thr, 8 warps 64x32, 3-stage cp.async, 2 CTAs/SM.
// ---------------------------------------------------------------------------
namespace dg {
constexpr int BM = 128, BN = 128, BK = 64, ST = 3;
constexpr int LDH = 72;
constexpr int A_H = BM * LDH;
constexpr int B_H = BN * LDH;
constexpr int STAGE_H = A_H + B_H;
constexpr int SMEM_BYTES = ST * STAGE_H * 2;   // 110592
}

template<bool RELU, bool HOUT>
__global__ __launch_bounds__(256, 2) void gemm_f16(
    const __half* __restrict__ A, const __half* __restrict__ W,
    const float* __restrict__ bias, void* __restrict__ Cv, int N, int K, int Mlim)
{
    using namespace dg;
    extern __shared__ __half hs[];
    const uint32_t sbase = (uint32_t)__cvta_generic_to_shared(hs);

    const int tid = threadIdx.x, w = tid >> 5, lane = tid & 31;
    const int gid = lane >> 2, t4 = lane & 3;
    const int lrow = lane & 7, lsel = lane >> 3;
    const int bm = blockIdx.x * BM, bn = blockIdx.y * BN;
    const int wm = (w >> 2) * 64, wn = (w & 3) * 32;

    float acc[4][4][4];
    #pragma unroll
    for (int i = 0; i < 4; ++i)
        #pragma unroll
        for (int j = 0; j < 4; ++j)
            #pragma unroll
            for (int v = 0; v < 4; ++v) acc[i][j][v] = 0.f;

    auto load_tile = [&](int t, int s) {
        const __half* Ab = A + (size_t)bm * K + t * BK;
        const __half* Wb = W + (size_t)bn * K + t * BK;
        const uint32_t sa = sbase + (uint32_t)(s * STAGE_H) * 2;
        const uint32_t sb = sa + A_H * 2;
        #pragma unroll
        for (int j = 0; j < 4; ++j) {
            int c = tid + j * 256;
            int r = c >> 3, kc = c & 7;
            cpa16(sa + (uint32_t)(r * LDH + kc * 8) * 2, Ab + (size_t)r * K + kc * 8);
        }
        #pragma unroll
        for (int j = 0; j < 4; ++j) {
            int c = tid + j * 256;
            int r = c >> 3, kc = c & 7;
            cpa16(sb + (uint32_t)(r * LDH + kc * 8) * 2, Wb + (size_t)r * K + kc * 8);
        }
        CP_COMMIT;
    };

    const int T = K / BK;
    load_tile(0, 0);
    load_tile(1, 1);

    for (int t = 0; t < T; ++t) {
        if (t + 1 < T) { CP_WAIT1; } else { CP_WAIT0; }
        __syncthreads();
        if (t + 2 < T) load_tile(t + 2, (t + 2) % ST);

        const uint32_t sa = sbase + (uint32_t)((t % ST) * STAGE_H) * 2;
        const uint32_t sb = sa + A_H * 2;
        #pragma unroll
        for (int kk = 0; kk < 4; ++kk) {
            uint32_t af[4][4], bf[4][2];
            #pragma unroll
            for (int mt = 0; mt < 4; ++mt) {
                uint32_t addr = sa + (uint32_t)(
                    (wm + mt * 16 + (lsel & 1) * 8 + lrow) * LDH
                    + kk * 16 + (lsel >> 1) * 8) * 2;
                ldsm4(af[mt], addr);
            }
            #pragma unroll
            for (int np = 0; np < 2; ++np) {
                uint32_t r4[4];
                uint32_t addr = sb + (uint32_t)(
                    (wn + np * 16 + (lsel >> 1) * 8 + lrow) * LDH
                    + kk * 16 + (lsel & 1) * 8) * 2;
                ldsm4(r4, addr);
                bf[np * 2][0]     = r4[0]; bf[np * 2][1]     = r4[1];
                bf[np * 2 + 1][0] = r4[2]; bf[np * 2 + 1][1] = r4[3];
            }
            #pragma unroll
            for (int mt = 0; mt < 4; ++mt)
                #pragma unroll
                for (int nt = 0; nt < 4; ++nt)
                    mma_f16(acc[mt][nt], af[mt], bf[nt]);
        }
    }

    // epilogue
    #pragma unroll
    for (int mt = 0; mt < 4; ++mt) {
        int r0 = bm + wm + mt * 16 + gid;
        #pragma unroll
        for (int nt = 0; nt < 4; ++nt) {
            int col = bn + wn + nt * 8 + 2 * t4;
            float b0 = bias[col], b1 = bias[col + 1];
            float2 v0, v1;
            v0.x = acc[mt][nt][0] + b0; v0.y = acc[mt][nt][1] + b1;
            v1.x = acc[mt][nt][2] + b0; v1.y = acc[mt][nt][3] + b1;
            if (RELU) {
                v0.x = fmaxf(v0.x, 0.f); v0.y = fmaxf(v0.y, 0.f);
                v1.x = fmaxf(v1.x, 0.f); v1.y = fmaxf(v1.y, 0.f);
            }
            if (HOUT) {
                __half2* C2 = (__half2*)Cv;
                if (r0 < Mlim)
                    C2[((size_t)r0 * N + col) >> 1]       = __floats2half2_rn(v0.x, v0.y);
                if (r0 + 8 < Mlim)
                    C2[((size_t)(r0 + 8) * N + col) >> 1] = __floats2half2_rn(v1.x, v1.y);
            } else {
                float* C = (float*)Cv;
                if (r0 < Mlim)
                    *(float2*)&C[(size_t)r0 * N + col]       = v0;
                if (r0 + 8 < Mlim)
                    *(float2*)&C[(size_t)(r0 + 8) * N + col] = v1;
            }
        }
    }
}

// ---------------------------------------------------------------------------
// Fused flash attention, fp16 operands, fp32 softmax/accumulate.
// K cp.async double-buffer; V reg-prefetch + transposed staging. 2 CTAs/SM.
// ---------------------------------------------------------------------------
namespace fa {
constexpr int BQ = 128, BJ = 64, LDH = 72;
constexpr int KS_OFF = BQ * LDH;
constexpr int VT_OFF = KS_OFF + 2 * BJ * LDH;
constexpr int SMEM_BYTES = (VT_OFF + 2 * BJ * LDH) * 2;   // 55296
}

__global__ __launch_bounds__(256, 2) void flash_kernel(
    const __half* __restrict__ qkv, __half* __restrict__ o)
{
    using namespace fa;
    extern __shared__ __half fsm[];
    __half* Qs = fsm;
    __half* Ksm = fsm + KS_OFF;
    __half* Vtm = fsm + VT_OFF;

    const int it = blockIdx.x, bh = blockIdx.y;
    const int b = bh >> 3, h = bh & 7;
    const __half* qbase = qkv + (size_t)b * SS * (3 * DD) + h * 64;
    const __half* kbase = qbase + DD;
    const __half* vbase = qbase + 2 * DD;

    const int tid = threadIdx.x;
    const int w = tid >> 5, lane = tid & 31;
    const int gid = lane >> 2, t4 = lane & 3;
    const int lrow = lane & 7, lsel = lane >> 3;
    const int wm = w * 16;

    const uint32_t qs_a = (uint32_t)__cvta_generic_to_shared(Qs);
    const uint32_t ks_a = (uint32_t)__cvta_generic_to_shared(Ksm);
    const uint32_t vt_a = (uint32_t)__cvta_generic_to_shared(Vtm);

    auto load_K = [&](int jt, int buf) {
        #pragma unroll
        for (int i = 0; i < 2; ++i) {
            int c = tid + i * 256;
            int r = c >> 3, kc = c & 7;
            int j = jt * BJ + r;
            int sz = (j < SS) ? 16 : 0;
            cpa16z(ks_a + (uint32_t)(buf * BJ * LDH + r * LDH + kc * 8) * 2,
                   kbase + (size_t)j * (3 * DD) + kc * 8, sz);
        }
        CP_COMMIT;
    };
    auto load_V = [&](int jt, uint4& va, uint4& vb) {
        int jA = jt * BJ + 2 * lane, jB = jA + 1;
        va = make_uint4(0, 0, 0, 0); vb = make_uint4(0, 0, 0, 0);
        if (jA < SS) va = *(const uint4*)(vbase + (size_t)jA * (3 * DD) + w * 8);
        if (jB < SS) vb = *(const uint4*)(vbase + (size_t)jB * (3 * DD) + w * 8);
    };

    load_K(0, 0);
    uint4 va, vb;
    load_V(0, va, vb);

    #pragma unroll
    for (int i = 0; i < 4; ++i) {
        int c = tid + i * 256;
        int r = c >> 3, kc = c & 7;
        int qi = it * BQ + r;
        uint4 v = make_uint4(0, 0, 0, 0);
        if (qi < SS) v = *(const uint4*)(qbase + (size_t)qi * (3 * DD) + kc * 8);
        *(uint4*)&Qs[r * LDH + kc * 8] = v;
    }
    __syncthreads();

    uint32_t qf[4][4];
    #pragma unroll
    for (int kk = 0; kk < 4; ++kk) {
        uint32_t addr = qs_a + (uint32_t)(
            (wm + (lsel & 1) * 8 + lrow) * LDH + kk * 16 + (lsel >> 1) * 8) * 2;
        ldsm4(qf[kk], addr);
    }

    const int row0 = it * BQ + wm + gid;
    const int row1 = row0 + 8;

    float m0 = -3.4e38f, m1 = -3.4e38f, l0 = 0.f, l1 = 0.f;
    float acc_o[8][4];
    #pragma unroll
    for (int j = 0; j < 8; ++j)
        #pragma unroll
        for (int v = 0; v < 4; ++v) acc_o[j][v] = 0.f;

    const int nTiles = (SS + BJ - 1) / BJ;
    for (int jt = 0; jt < nTiles; ++jt) {
        const int bsel = jt & 1;
        const int j0 = jt * BJ;
        __syncthreads();

        if (jt + 1 < nTiles) load_K(jt + 1, bsel ^ 1);

        {
            const __half* ha = (const __half*)&va;
            const __half* hb2 = (const __half*)&vb;
            #pragma unroll
            for (int i = 0; i < 8; ++i) {
                *(__half2*)&Vtm[bsel * BJ * LDH + (w * 8 + i) * LDH + 2 * lane] =
                    __halves2half2(ha[i], hb2[i]);
            }
        }
        if (jt + 1 < nTiles) { load_V(jt + 1, va, vb); CP_WAIT1; }
        else                 { CP_WAIT0; }
        __syncthreads();

        float s[8][4];
        #pragma unroll
        for (int j = 0; j < 8; ++j)
            #pragma unroll
            for (int v = 0; v < 4; ++v) s[j][v] = 0.f;

        const uint32_t ksb = ks_a + (uint32_t)(bsel * BJ * LDH) * 2;
        #pragma unroll
        for (int kk = 0; kk < 4; ++kk) {
            uint32_t bf[8][2];
            #pragma unroll
            for (int np = 0; np < 4; ++np) {
                uint32_t r4[4];
                uint32_t addr = ksb + (uint32_t)(
                    (np * 16 + (lsel >> 1) * 8 + lrow) * LDH
                    + kk * 16 + (lsel & 1) * 8) * 2;
                ldsm4(r4, addr);
                bf[np * 2][0]     = r4[0]; bf[np * 2][1]     = r4[1];
                bf[np * 2 + 1][0] = r4[2]; bf[np * 2 + 1][1] = r4[3];
            }
            #pragma unroll
            for (int nt = 0; nt < 8; ++nt)
                mma_f16(s[nt], qf[kk], bf[nt]);
        }

        float tmx0 = -3.4e38f, tmx1 = -3.4e38f;
        #pragma unroll
        for (int nt = 0; nt < 8; ++nt) {
            #pragma unroll
            for (int e = 0; e < 2; ++e) {
                int gj = j0 + nt * 8 + 2 * t4 + e;
                float v0 = s[nt][e] * ATT_SCALE;
                float v1 = s[nt][2 + e] * ATT_SCALE;
                bool al0 = (gj < PP) | (gj <= row0);
                bool al1 = (gj < PP) | (gj <= row1);
                v0 = al0 ? v0 : NEGBIG;
                v1 = al1 ? v1 : NEGBIG;
                s[nt][e] = v0; s[nt][2 + e] = v1;
                tmx0 = fmaxf(tmx0, v0);
                tmx1 = fmaxf(tmx1, v1);
            }
        }
        tmx0 = fmaxf(tmx0, __shfl_xor_sync(0xffffffffu, tmx0, 1));
        tmx0 = fmaxf(tmx0, __shfl_xor_sync(0xffffffffu, tmx0, 2));
        tmx1 = fmaxf(tmx1, __shfl_xor_sync(0xffffffffu, tmx1, 1));
        tmx1 = fmaxf(tmx1, __shfl_xor_sync(0xffffffffu, tmx1, 2));

        float nm0 = fmaxf(m0, tmx0), nm1 = fmaxf(m1, tmx1);
        float a0 = __expf(m0 - nm0), a1 = __expf(m1 - nm1);
        m0 = nm0; m1 = nm1;

        float sum0 = 0.f, sum1 = 0.f;
        #pragma unroll
        for (int nt = 0; nt < 8; ++nt) {
            #pragma unroll
            for (int e = 0; e < 2; ++e) {
                float p0 = __expf(s[nt][e] - nm0);
                float p1 = __expf(s[nt][2 + e] - nm1);
                s[nt][e] = p0; s[nt][2 + e] = p1;
                sum0 += p0; sum1 += p1;
            }
        }
        sum0 += __shfl_xor_sync(0xffffffffu, sum0, 1);
        sum0 += __shfl_xor_sync(0xffffffffu, sum0, 2);
        sum1 += __shfl_xor_sync(0xffffffffu, sum1, 1);
        sum1 += __shfl_xor_sync(0xffffffffu, sum1, 2);
        l0 = l0 * a0 + sum0;
        l1 = l1 * a1 + sum1;

        #pragma unroll
        for (int nt = 0; nt < 8; ++nt) {
            acc_o[nt][0] *= a0; acc_o[nt][1] *= a0;
            acc_o[nt][2] *= a1; acc_o[nt][3] *= a1;
        }

        #pragma unroll
        for (int nt = 0; nt < 8; ++nt) {
            *(__half2*)&Qs[(wm + gid) * LDH + nt * 8 + 2 * t4] =
                __floats2half2_rn(s[nt][0], s[nt][1]);
            *(__half2*)&Qs[(wm + gid + 8) * LDH + nt * 8 + 2 * t4] =
                __floats2half2_rn(s[nt][2], s[nt][3]);
        }
        __syncwarp();

        const uint32_t vtb = vt_a + (uint32_t)(bsel * BJ * LDH) * 2;
        #pragma unroll
        for (int kk = 0; kk < 4; ++kk) {
            uint32_t af[4];
            uint32_t addr = qs_a + (uint32_t)(
                (wm + (lsel & 1) * 8 + lrow) * LDH + kk * 16 + (lsel >> 1) * 8) * 2;
            ldsm4(af, addr);
            uint32_t bf[8][2];
            #pragma unroll
            for (int np = 0; np < 4; ++np) {
                uint32_t r4[4];
                uint32_t vaddr = vtb + (uint32_t)(
                    (np * 16 + (lsel >> 1) * 8 + lrow) * LDH
                    + kk * 16 + (lsel & 1) * 8) * 2;
                ldsm4(r4, vaddr);
                bf[np * 2][0]     = r4[0]; bf[np * 2][1]     = r4[1];
                bf[np * 2 + 1][0] = r4[2]; bf[np * 2 + 1][1] = r4[3];
            }
            #pragma unroll
            for (int nt = 0; nt < 8; ++nt)
                mma_f16(acc_o[nt], af, bf[nt]);
        }
    }

    float inv0 = 1.f / l0, inv1 = 1.f / l1;
    __half* ob = o + (size_t)b * SS * DD + h * 64;
    #pragma unroll
    for (int nt = 0; nt < 8; ++nt) {
        int col = nt * 8 + 2 * t4;
        if (row0 < SS)
            *(__half2*)&ob[(size_t)row0 * DD + col] =
                __floats2half2_rn(acc_o[nt][0] * inv0, acc_o[nt][1] * inv0);
        if (row1 < SS)
            *(__half2*)&ob[(size_t)row1 * DD + col] =
                __floats2half2_rn(acc_o[nt][2] * inv1, acc_o[nt][3] * inv1);
    }
}

// ---------------------------------------------------------------------------
// x = LayerNorm(x + r) * g + b ; warp-per-token (8 tokens / 256-thr block).
// Shuffle-only reductions; writes exact x AND half xh.
// ---------------------------------------------------------------------------
__global__ __launch_bounds__(256) void add_ln_kernel(
    float* __restrict__ x, __half* __restrict__ xh, const float* __restrict__ r,
    const float* __restrict__ g, const float* __restrict__ bta)
{
    const int n = blockIdx.x * 8 + (threadIdx.x >> 5);   // token
    const int lane = threadIdx.x & 31;

    float4* xp = (float4*)(x + (size_t)n * DD);
    const float4* rp = (const float4*)(r + (size_t)n * DD);

    float4 v[4];
    float s = 0.f;
    #pragma unroll
    for (int i = 0; i < 4; ++i) {
        v[i] = xp[lane + i * 32];
        float4 rv = rp[lane + i * 32];
        v[i].x += rv.x; v[i].y += rv.y; v[i].z += rv.z; v[i].w += rv.w;
        s += v[i].x + v[i].y + v[i].z + v[i].w;
    }
    #pragma unroll
    for (int o = 16; o > 0; o >>= 1) s += __shfl_xor_sync(0xffffffffu, s, o);
    float mu = s * (1.f / DD);

    float sq = 0.f;
    #pragma unroll
    for (int i = 0; i < 4; ++i) {
        v[i].x -= mu; v[i].y -= mu; v[i].z -= mu; v[i].w -= mu;
        sq += v[i].x * v[i].x + v[i].y * v[i].y + v[i].z * v[i].z + v[i].w * v[i].w;
    }
    #pragma unroll
    for (int o = 16; o > 0; o >>= 1) sq += __shfl_xor_sync(0xffffffffu, sq, o);
    float rinv = rsqrtf(sq * (1.f / DD) + 1e-5f);

    __half2* dh = (__half2*)(xh + (size_t)n * DD);
    #pragma unroll
    for (int i = 0; i < 4; ++i) {
        float4 gg = ((const float4*)g)[lane + i * 32];
        float4 bb = ((const float4*)bta)[lane + i * 32];
        float4 out;
        out.x = v[i].x * rinv * gg.x + bb.x;
        out.y = v[i].y * rinv * gg.y + bb.y;
        out.z = v[i].z * rinv * gg.z + bb.z;
        out.w = v[i].w * rinv * gg.w + bb.w;
        xp[lane + i * 32] = out;
        dh[2 * (lane + i * 32) + 0] = __floats2half2_rn(out.x, out.y);
        dh[2 * (lane + i * 32) + 1] = __floats2half2_rn(out.z, out.w);
    }
}

// ---------------------------------------------------------------------------
// Launch
// ---------------------------------------------------------------------------
extern "C" void kernel_launch(void* const* d_in, const int* in_sizes, int n_in,
                              void* d_out, int out_size)
{
    const float* lang = (const float*)d_in[0];
    const float* vis  = (const float*)d_in[1];
    const int*   aidx = (const int*)  d_in[2];
    const float* aemb = (const float*)d_in[3];
    const float* Wqkv = (const float*)d_in[4];
    const float* bqkv = (const float*)d_in[5];
    const float* Wo   = (const float*)d_in[6];
    const float* bo   = (const float*)d_in[7];
    const float* W1   = (const float*)d_in[8];
    const float* b1   = (const float*)d_in[9];
    const float* W2   = (const float*)d_in[10];
    const float* b2   = (const float*)d_in[11];
    const float* ln1g = (const float*)d_in[12];
    const float* ln1b = (const float*)d_in[13];
    const float* ln2g = (const float*)d_in[14];
    const float* ln2b = (const float*)d_in[15];
    const float* hW   = (const float*)d_in[16];
    const float* hb   = (const float*)d_in[17];
    float* out = (float*)d_out;

    float *px, *pr;
    __half *pxh, *pqkvh, *poh, *phh, *pxah, *pwh;
    cudaGetSymbolAddress((void**)&px,    g_x);
    cudaGetSymbolAddress((void**)&pr,    g_r);
    cudaGetSymbolAddress((void**)&pxh,   g_xh);
    cudaGetSymbolAddress((void**)&pqkvh, g_qkvh);
    cudaGetSymbolAddress((void**)&poh,   g_oh);
    cudaGetSymbolAddress((void**)&phh,   g_hh);
    cudaGetSymbolAddress((void**)&pxah,  g_xah);
    cudaGetSymbolAddress((void**)&pwh,   g_wh);

    cudaFuncSetAttribute(gemm_f16<false, false>,
        cudaFuncAttributeMaxDynamicSharedMemorySize, dg::SMEM_BYTES);
    cudaFuncSetAttribute(gemm_f16<false, true>,
        cudaFuncAttributeMaxDynamicSharedMemorySize, dg::SMEM_BYTES);
    cudaFuncSetAttribute(gemm_f16<true, true>,
        cudaFuncAttributeMaxDynamicSharedMemorySize, dg::SMEM_BYTES);
    cudaFuncSetAttribute(flash_kernel,
        cudaFuncAttributeMaxDynamicSharedMemorySize, fa::SMEM_BYTES);

    round_wh_kernel<<<(int)(W_QKV_N / 4 + 255) / 256, 256>>>(Wqkv, pwh + W_QKV_OFF, (int)(W_QKV_N / 4));
    round_wh_kernel<<<(int)(W_O_N   / 4 + 255) / 256, 256>>>(Wo,   pwh + W_O_OFF,   (int)(W_O_N   / 4));
    round_wh_kernel<<<(int)(W_1_N   / 4 + 255) / 256, 256>>>(W1,   pwh + W_1_OFF,   (int)(W_1_N   / 4));
    round_wh_kernel<<<(int)(W_2_N   / 4 + 255) / 256, 256>>>(W2,   pwh + W_2_OFF,   (int)(W_2_N   / 4));
    round_wh_kernel<<<(int)(W_H_N   / 4 + 255) / 256, 256>>>(hW,   pwh + W_H_OFF,   (int)(W_H_N   / 4));

    embed_kernel<<<NTOK, 128>>>(lang, vis, aidx, aemb);

    for (int l = 0; l < LL; ++l) {
        gemm_f16<false, true><<<dim3(NTOK / 128, (3 * DD) / 128), 256, dg::SMEM_BYTES>>>(
            pxh, pwh + W_QKV_OFF + (size_t)l * 3 * DD * DD, bqkv + l * 3 * DD,
            pqkvh, 3 * DD, DD, NTOK);
        flash_kernel<<<dim3((SS + fa::BQ - 1) / fa::BQ, Bz * HH), 256, fa::SMEM_BYTES>>>(
            pqkvh, poh);
        gemm_f16<false, false><<<dim3(NTOK / 128, DD / 128), 256, dg::SMEM_BYTES>>>(
            poh, pwh + W_O_OFF + (size_t)l * DD * DD, bo + l * DD, pr, DD, DD, NTOK);
        add_ln_kernel<<<NTOK / 8, 256>>>(px, pxh, pr, ln1g + l * DD, ln1b + l * DD);
        gemm_f16<true, true><<<dim3(NTOK / 128, FF / 128), 256, dg::SMEM_BYTES>>>(
            pxh, pwh + W_1_OFF + (size_t)l * FF * DD, b1 + l * FF, phh, FF, DD, NTOK);
        gemm_f16<false, false><<<dim3(NTOK / 128, DD / 128), 256, dg::SMEM_BYTES>>>(
            phh, pwh + W_2_OFF + (size_t)l * DD * FF, b2 + l * DD, pr, DD, FF, NTOK);
        add_ln_kernel<<<NTOK / 8, 256>>>(px, pxh, pr, ln2g + l * DD, ln2b + l * DD);
    }

    gather_act_kernel<<<NACT_PAD, 128>>>();
    gemm_f16<false, false><<<dim3(NACT_PAD / 128, VV / 128), 256, dg::SMEM_BYTES>>>(
        pxah, pwh + W_H_OFF, hb, out, VV, DD, NACT);
}